// round 10
// baseline (speedup 1.0000x reference)
#include <cuda_runtime.h>
#include <cuda_bf16.h>
#include <cstdint>
#include <cstddef>

#define NN 4096
#define TD 768
#define ID 512
#define HH 256
#define NHD 4
#define HD 64
#define EE 131072
#define NC 3

// ---------------- scratch (static device globals; no allocation) -------------
__device__ float g_h[NN * HH];      // fp32 transformed features (GCN1 h)
__device__ float g_g1[NN * HH];     // GCN1 init (self-loop term)
__device__ float g_y[NN * 4];       // GCN2 h @ cls_w (padded to 4)
__device__ float g_dinv[NN];
__device__ float g_vsum[HH];
__device__ float g_bconst[3];
__device__ float g_bg[HH];          // bo @ G1
__device__ int   g_cnt[NN];         // zero at module load; re-zeroed by k_scan
__device__ int   g_start[NN + 1];
__device__ int   g_cursor[NN];
__device__ int   g_sorted[EE];
// bf16 activation chain (hi/lo pairs)
__device__ __nv_bfloat16 g_ch[NN * HH],  g_cl[NN * HH];
__device__ __nv_bfloat16 g_qb[NN * HH];
__device__ __nv_bfloat16 g_kb[NN * HH];
__device__ __nv_bfloat16 g_vb[NN * HH];
__device__ __nv_bfloat16 g_obh[NN * HH], g_obl[NN * HH];
__device__ __nv_bfloat16 g_g1h[NN * HH], g_g1l[NN * HH];
// transposed+split weights [n][K]
#define WOFF_TEXT  0
#define WOFF_IMAGE 196608
#define WOFF_WQ    327680
#define WOFF_WK    393216
#define WOFF_WV    458752
#define WOFF_G1    524288   /* holds WG = Wo@G1, composed */
#define WOFF_G2    589824
#define WTOT       655360
__device__ __nv_bfloat16 g_wth[WTOT], g_wtl[WTOT];

// =================== helpers =================================================
__device__ __forceinline__ uint32_t smem_u32(const void* p) {
    uint32_t a;
    asm("{ .reg .u64 t; cvta.to.shared.u64 t, %1; cvt.u32.u64 %0, t; }"
        : "=r"(a) : "l"(p));
    return a;
}
__device__ __forceinline__ uint32_t swz128(uint32_t o) { return o ^ ((o >> 3) & 0x70); }
__device__ __forceinline__ uint32_t swz64(uint32_t o)  { return o ^ ((o >> 3) & 0x30); }
__device__ __forceinline__ uint32_t packbf2(float x0, float x1) {
    uint32_t r;  // lo = x0, hi = x1
    asm("cvt.rn.satfinite.bf16x2.f32 %0, %1, %2;" : "=r"(r) : "f"(x1), "f"(x0));
    return r;
}
__device__ __forceinline__ void split_pair_store(void* oh, void* ol, size_t idx,
                                                 float x, float y) {
    uint32_t hp = packbf2(x, y);
    float hx = __uint_as_float(hp << 16);
    float hy = __uint_as_float(hp & 0xFFFF0000u);
    uint32_t lp = packbf2(x - hx, y - hy);
    ((uint32_t*)oh)[idx >> 1] = hp;
    ((uint32_t*)ol)[idx >> 1] = lp;
}
__device__ __forceinline__ void mma16816(float* c,
    uint32_t a0, uint32_t a1, uint32_t a2, uint32_t a3, uint32_t b0, uint32_t b1) {
    asm volatile("mma.sync.aligned.m16n8k16.row.col.f32.bf16.bf16.f32 "
        "{%0,%1,%2,%3}, {%4,%5,%6,%7}, {%8,%9}, {%0,%1,%2,%3};"
        : "+f"(c[0]), "+f"(c[1]), "+f"(c[2]), "+f"(c[3])
        : "r"(a0), "r"(a1), "r"(a2), "r"(a3), "r"(b0), "r"(b1));
}
__device__ __forceinline__ void ldsm4(uint32_t* r, uint32_t a) {
    asm volatile("ldmatrix.sync.aligned.m8n8.x4.shared.b16 {%0,%1,%2,%3}, [%4];"
        : "=r"(r[0]), "=r"(r[1]), "=r"(r[2]), "=r"(r[3]) : "r"(a));
}
__device__ __forceinline__ void ldsm4t(uint32_t* r, uint32_t a) {
    asm volatile("ldmatrix.sync.aligned.m8n8.x4.trans.shared.b16 {%0,%1,%2,%3}, [%4];"
        : "=r"(r[0]), "=r"(r[1]), "=r"(r[2]), "=r"(r[3]) : "r"(a));
}
__device__ __forceinline__ void cp16(uint32_t dst, const void* src) {
    asm volatile("cp.async.cg.shared.global [%0], [%1], 16;" :: "r"(dst), "l"(src) : "memory");
}
__device__ __forceinline__ void cp_commit() {
    asm volatile("cp.async.commit_group;" ::: "memory");
}
__device__ __forceinline__ void cp_wait0() {
    asm volatile("cp.async.wait_group 0;" ::: "memory");
}
__device__ __forceinline__ void redf(float* p, float v) {
    asm volatile("red.global.add.f32 [%0], %1;" :: "l"(p), "f"(v) : "memory");
}

// ====== single-launch prep: weights + hist + WG compose + bG + zeroing =======
// grid (24, 8, 8), block (32,32).
// z 0..4,7: transpose+split weight planes.
// z==5: edge dst histogram (cnt starts zero: static init / re-zeroed by scan).
// z==6: bx<8 -> WG = Wo@G1 composed tile; bx==8 -> bG = bo@G1;
//        bx==9 -> zero y + vsum.
__global__ void k_wprep_all(
    const float* w0, const float* w1, const float* w2, const float* w3,
    const float* w4, const float* wo, const float* g1w, const float* w7,
    const float* bo, const int* __restrict__ edst)
{
    const int z = blockIdx.z;
    const int tx = threadIdx.x, ty = threadIdx.y;
    if (z == 5) {
        int flat = (blockIdx.y * 24 + blockIdx.x) * 1024 + ty * 32 + tx;
        if (flat < EE) atomicAdd(&g_cnt[edst[flat]], 1);
        return;
    }
    if (z == 6) {
        if (blockIdx.x < 8) {
            // WG^T[n][k] = sum_j Wo[k][j] * G1[j][n]
            int k0 = blockIdx.x * 32, n0 = blockIdx.y * 32;
            __shared__ float sW[32][33], sG[32][33];
            float acc = 0.f;
            for (int j0 = 0; j0 < HH; j0 += 32) {
                sW[ty][tx] = wo[(size_t)(k0 + ty) * HH + j0 + tx];
                sG[ty][tx] = g1w[(size_t)(j0 + ty) * HH + n0 + tx];
                __syncthreads();
#pragma unroll
                for (int jj = 0; jj < 32; jj++)
                    acc = fmaf(sW[tx][jj], sG[jj][ty], acc);
                __syncthreads();
            }
            __nv_bfloat16 h = __float2bfloat16(acc);
            __nv_bfloat16 l = __float2bfloat16(acc - __bfloat162float(h));
            size_t idx = (size_t)WOFF_G1 + (size_t)(n0 + ty) * HH + k0 + tx;
            g_wth[idx] = h;
            g_wtl[idx] = l;
        } else if (blockIdx.x == 8) {
            if (blockIdx.y == 0) {
                int t = ty * 32 + tx;
                if (t < HH) {
                    float s = 0.f;
                    for (int j = 0; j < HH; j++)
                        s = fmaf(bo[j], g1w[(size_t)j * HH + t], s);
                    g_bg[t] = s;
                }
            }
        } else if (blockIdx.x == 9) {
            int flat = blockIdx.y * 1024 + ty * 32 + tx;
            for (int i = flat; i < NN * 4 + HH; i += 8192) {
                if (i < NN * 4) g_y[i] = 0.f;
                else g_vsum[i - NN * 4] = 0.f;
            }
        }
        return;
    }
    const float* W; int K, off;
    switch (z) {
        case 0: W = w0; K = TD; off = WOFF_TEXT; break;
        case 1: W = w1; K = ID; off = WOFF_IMAGE; break;
        case 2: W = w2; K = HH; off = WOFF_WQ; break;
        case 3: W = w3; K = HH; off = WOFF_WK; break;
        case 4: W = w4; K = HH; off = WOFF_WV; break;
        default: W = w7; K = HH; off = WOFF_G2; break;
    }
    int k0 = blockIdx.x * 32;
    if (k0 >= K) return;
    int n0 = blockIdx.y * 32;
    __shared__ float t[32][33];
    t[ty][tx] = W[(size_t)(k0 + ty) * HH + n0 + tx];
    __syncthreads();
    float v = t[tx][ty];
    __nv_bfloat16 h = __float2bfloat16(v);
    __nv_bfloat16 l = __float2bfloat16(v - __bfloat162float(h));
    size_t idx = (size_t)off + (size_t)(n0 + ty) * K + k0 + tx;
    g_wth[idx] = h;
    g_wtl[idx] = l;
}

// 1 CTA, 1024 threads: prefix-scan cnt -> start/cursor, dinv; zero cnt for next
// replay; bconst = gcn2_b @ cls_w.
__global__ void k_scan(const float* __restrict__ b2, const float* __restrict__ cw)
{
    __shared__ int wsum[32];
    const int t = threadIdx.x, lane = t & 31, wid = t >> 5;
    if (t < 3) {
        float s = 0.f;
        for (int j = 0; j < HH; j++) s = fmaf(b2[j], cw[j * 3 + t], s);
        g_bconst[t] = s;
    }
    const int base = t * 4;
    int c0 = g_cnt[base], c1 = g_cnt[base + 1], c2 = g_cnt[base + 2], c3 = g_cnt[base + 3];
    int s = c0 + c1 + c2 + c3;
    int v = s;
#pragma unroll
    for (int off = 1; off < 32; off <<= 1) {
        int u = __shfl_up_sync(0xffffffffu, v, off);
        if (lane >= off) v += u;
    }
    if (lane == 31) wsum[wid] = v;
    __syncthreads();
    if (wid == 0) {
        int x = wsum[lane];
#pragma unroll
        for (int off = 1; off < 32; off <<= 1) {
            int u = __shfl_up_sync(0xffffffffu, x, off);
            if (lane >= off) x += u;
        }
        wsum[lane] = x;
    }
    __syncthreads();
    int excl = v - s + (wid > 0 ? wsum[wid - 1] : 0);
    int e0 = excl, e1 = e0 + c0, e2 = e1 + c1, e3 = e2 + c2;
    g_start[base] = e0;  g_cursor[base] = e0;
    g_start[base + 1] = e1; g_cursor[base + 1] = e1;
    g_start[base + 2] = e2; g_cursor[base + 2] = e2;
    g_start[base + 3] = e3; g_cursor[base + 3] = e3;
    g_dinv[base]     = rsqrtf((float)(c0 + 1));
    g_dinv[base + 1] = rsqrtf((float)(c1 + 1));
    g_dinv[base + 2] = rsqrtf((float)(c2 + 1));
    g_dinv[base + 3] = rsqrtf((float)(c3 + 1));
    // re-zero cnt so the next graph replay starts from the static-init state
    g_cnt[base] = 0; g_cnt[base + 1] = 0; g_cnt[base + 2] = 0; g_cnt[base + 3] = 0;
    if (t == 1023) g_start[NN] = e3 + c3;
}

// ====== GCN layer-1 aggregation: warp per dst, gather ========================
__global__ void __launch_bounds__(256) k_agg1(
    const float* __restrict__ h, const float* __restrict__ init,
    __nv_bfloat16* __restrict__ oh, __nv_bfloat16* __restrict__ ol)
{
    const int dstn = (blockIdx.x * 256 + threadIdx.x) >> 5;
    const int lane = threadIdx.x & 31;
    if (dstn >= NN) return;
    const int beg = g_start[dstn], end = g_start[dstn + 1];
    const float dd = g_dinv[dstn];

    float acc[8];
    {
        const float4* ir = (const float4*)(init + (size_t)dstn * HH) + lane * 2;
        float4 a = ir[0], b = ir[1];
        acc[0] = a.x; acc[1] = a.y; acc[2] = a.z; acc[3] = a.w;
        acc[4] = b.x; acc[5] = b.y; acc[6] = b.z; acc[7] = b.w;
    }
    for (int e = beg; e < end; e += 32) {
        int n = end - e; if (n > 32) n = 32;
        int sidx = 0; float dv = 0.f;
        if (lane < n) {
            sidx = __ldg(&g_sorted[e + lane]);
            dv = __ldg(&g_dinv[sidx]);
        }
#pragma unroll 4
        for (int j = 0; j < n; j++) {
            int s = __shfl_sync(0xffffffffu, sidx, j);
            float cf = __shfl_sync(0xffffffffu, dv, j) * dd;
            const float4* hr = (const float4*)(h + ((size_t)s << 8)) + (lane << 1);
            float4 a = __ldg(hr), b = __ldg(hr + 1);
            acc[0] = fmaf(cf, a.x, acc[0]); acc[1] = fmaf(cf, a.y, acc[1]);
            acc[2] = fmaf(cf, a.z, acc[2]); acc[3] = fmaf(cf, a.w, acc[3]);
            acc[4] = fmaf(cf, b.x, acc[4]); acc[5] = fmaf(cf, b.y, acc[5]);
            acc[6] = fmaf(cf, b.z, acc[6]); acc[7] = fmaf(cf, b.w, acc[7]);
        }
    }
#pragma unroll
    for (int p = 0; p < 4; p++) {
        float x = fmaxf(acc[2 * p], 0.f), y = fmaxf(acc[2 * p + 1], 0.f);
        split_pair_store(oh, ol, (size_t)dstn * HH + lane * 8 + 2 * p, x, y);
    }
}

// ====== GCN layer-2 aggregation on y[4] (classifier space) ===================
__global__ void __launch_bounds__(256) k_agg2y(
    const float* __restrict__ y, const float* __restrict__ cls_b,
    float* __restrict__ out)
{
    const int d = (blockIdx.x * 256 + threadIdx.x) >> 5;
    const int lane = threadIdx.x & 31;
    if (d >= NN) return;
    const int beg = g_start[d], end = g_start[d + 1];
    float a0 = 0.f, a1 = 0.f, a2 = 0.f;
    for (int e = beg + lane; e < end; e += 32) {
        int s = __ldg(&g_sorted[e]);
        float dv = __ldg(&g_dinv[s]);
        float4 yv = *(const float4*)(y + s * 4);
        a0 = fmaf(dv, yv.x, a0);
        a1 = fmaf(dv, yv.y, a1);
        a2 = fmaf(dv, yv.z, a2);
    }
#pragma unroll
    for (int off = 16; off > 0; off >>= 1) {
        a0 += __shfl_xor_sync(0xffffffffu, a0, off);
        a1 += __shfl_xor_sync(0xffffffffu, a1, off);
        a2 += __shfl_xor_sync(0xffffffffu, a2, off);
    }
    if (lane == 0) {
        float dd = g_dinv[d];
        float4 yd = *(const float4*)(y + d * 4);
        out[d * 3 + 0] = fmaf(dd, fmaf(dd, yd.x, a0), g_bconst[0] + cls_b[0]);
        out[d * 3 + 1] = fmaf(dd, fmaf(dd, yd.y, a1), g_bconst[1] + cls_b[1]);
        out[d * 3 + 2] = fmaf(dd, fmaf(dd, yd.z, a2), g_bconst[2] + cls_b[2]);
    }
}

// =============== HMMA GEMM cores =============================================
#define GST 24576
#define GS_AL 8192
#define GS_W  16384
#define GS_WL 20480
#define GEMM_SMEM 49152

__device__ __forceinline__ void gemm_core_bf16(
    uint32_t sb, int tid, int m0, int n0,
    const void* A0v, const void* A1v,
    const __nv_bfloat16* WTh, const __nv_bfloat16* WTl,
    int K, float acc[8][4])
{
    const int w = tid >> 5, lane = tid & 31;
    const int rowa = w * 16 + (lane & 7) + ((lane >> 3) & 1) * 8;
    const int acb  = ((lane >> 4) & 1) * 16;
    const int nrow = lane & 7;
    const int bcb  = ((lane >> 3) & 3) * 16;
    const int nch = K >> 5;

    auto load_w = [&](int kc, int st) {
        int k0 = kc << 5;
        uint32_t base = sb + st * GST + GS_W;
#pragma unroll
        for (int j = 0; j < 2; j++) {
            int flat = tid + j * 256;
            int part = flat >> 8, r = (flat >> 2) & 63, c = flat & 3;
            const char* src = (const char*)(part ? WTl : WTh) +
                              (((size_t)(n0 + r) * K + k0) << 1) + c * 16;
            cp16(base + part * 4096 + swz64((uint32_t)(r * 64 + c * 16)), src);
        }
    };
    auto load_a = [&](int kc, int st) {
        int k0 = kc << 5;
        uint32_t base = sb + st * GST;
#pragma unroll
        for (int j = 0; j < 4; j++) {
            int flat = tid + j * 256;
            int part = flat >> 9, r = (flat >> 2) & 127, c = flat & 3;
            const char* src = (const char*)(part ? A1v : A0v) +
                              (((size_t)(m0 + r) * K + k0) << 1) + c * 16;
            cp16(base + part * GS_AL + swz64((uint32_t)(r * 64 + c * 16)), src);
        }
    };
    auto compute = [&](int st) {
        uint32_t base = sb + st * GST;
        uint32_t ah[2][4], al[2][4];
#pragma unroll
        for (int kk2 = 0; kk2 < 2; kk2++) {
            uint32_t ao = swz64((uint32_t)(rowa * 64 + kk2 * 32 + acb));
            ldsm4(ah[kk2], base + ao);
            ldsm4(al[kk2], base + GS_AL + ao);
        }
#pragma unroll
        for (int nb = 0; nb < 8; nb++) {
            uint32_t bo = swz64((uint32_t)((nb * 8 + nrow) * 64 + bcb));
            uint32_t bh[4], bl[4];
            ldsm4(bh, base + GS_W + bo);
            ldsm4(bl, base + GS_WL + bo);
            mma16816(acc[nb], ah[0][0], ah[0][1], ah[0][2], ah[0][3], bh[0], bh[1]);
            mma16816(acc[nb], ah[1][0], ah[1][1], ah[1][2], ah[1][3], bh[2], bh[3]);
            mma16816(acc[nb], ah[0][0], ah[0][1], ah[0][2], ah[0][3], bl[0], bl[1]);
            mma16816(acc[nb], ah[1][0], ah[1][1], ah[1][2], ah[1][3], bl[2], bl[3]);
            mma16816(acc[nb], al[0][0], al[0][1], al[0][2], al[0][3], bh[0], bh[1]);
            mma16816(acc[nb], al[1][0], al[1][1], al[1][2], al[1][3], bh[2], bh[3]);
        }
    };

    load_a(0, 0); load_w(0, 0); cp_commit(); cp_wait0();
    __syncthreads();
    for (int kc = 0; kc < nch; kc++) {
        if (kc + 1 < nch) {
            load_a(kc + 1, (kc + 1) & 1);
            load_w(kc + 1, (kc + 1) & 1);
            cp_commit();
        }
        compute(kc & 1);
        if (kc + 1 < nch) { cp_wait0(); __syncthreads(); }
    }
}

__device__ __forceinline__ void gemm_core_f32(
    char* smc, uint32_t sb, int tid, int m0, int n0,
    const float* A, const __nv_bfloat16* WTh, const __nv_bfloat16* WTl,
    int K, float acc[8][4])
{
    const int w = tid >> 5, lane = tid & 31;
    const int rowa = w * 16 + (lane & 7) + ((lane >> 3) & 1) * 8;
    const int acb  = ((lane >> 4) & 1) * 16;
    const int nrow = lane & 7;
    const int bcb  = ((lane >> 3) & 3) * 16;
    const int nch = K >> 5;
    float4 ar[4];

    auto load_w = [&](int kc, int st) {
        int k0 = kc << 5;
        uint32_t base = sb + st * GST + GS_W;
#pragma unroll
        for (int j = 0; j < 2; j++) {
            int flat = tid + j * 256;
            int part = flat >> 8, r = (flat >> 2) & 63, c = flat & 3;
            const char* src = (const char*)(part ? WTl : WTh) +
                              (((size_t)(n0 + r) * K + k0) << 1) + c * 16;
            cp16(base + part * 4096 + swz64((uint32_t)(r * 64 + c * 16)), src);
        }
    };
    auto ldg_a = [&](int kc) {
        int k0 = kc << 5;
#pragma unroll
        for (int j = 0; j < 4; j++) {
            int flat = tid + j * 256;
            int r = flat >> 3, c = flat & 7;
            ar[j] = *(const float4*)(A + (size_t)(m0 + r) * K + k0 + c * 4);
        }
    };
    auto sts_a = [&](int st) {
        uint32_t off0 = st * GST;
#pragma unroll
        for (int j = 0; j < 4; j++) {
            int flat = tid + j * 256;
            int r = flat >> 3, c = flat & 7;
            uint32_t off = swz64((uint32_t)(r * 64 + c * 8));
            uint32_t h0 = packbf2(ar[j].x, ar[j].y);
            uint32_t h1 = packbf2(ar[j].z, ar[j].w);
            float hx = __uint_as_float(h0 << 16), hy = __uint_as_float(h0 & 0xFFFF0000u);
            float hz = __uint_as_float(h1 << 16), hw = __uint_as_float(h1 & 0xFFFF0000u);
            uint32_t l0 = packbf2(ar[j].x - hx, ar[j].y - hy);
            uint32_t l1 = packbf2(ar[j].z - hz, ar[j].w - hw);
            *(uint2*)(smc + off0 + off) = make_uint2(h0, h1);
            *(uint2*)(smc + off0 + GS_AL + off) = make_uint2(l0, l1);
        }
    };
    auto compute = [&](int st) {
        uint32_t base = sb + st * GST;
        uint32_t ah[2][4], al[2][4];
#pragma unroll
        for (int kk2 = 0; kk2 < 2; kk2++) {
            uint32_t ao = swz64((uint32_t)(rowa * 64 + kk2 * 32 + acb));
            ldsm4(ah[kk2], base + ao);
            ldsm4(al[kk2], base + GS_AL + ao);
        }
#pragma unroll
        for (int nb = 0; nb < 8; nb++) {
            uint32_t bo = swz64((uint32_t)((nb * 8 + nrow) * 64 + bcb));
            uint32_t bh[4], bl[4];
            ldsm4(bh, base + GS_W + bo);
            ldsm4(bl, base + GS_WL + bo);
            mma16816(acc[nb], ah[0][0], ah[0][1], ah[0][2], ah[0][3], bh[0], bh[1]);
            mma16816(acc[nb], ah[1][0], ah[1][1], ah[1][2], ah[1][3], bh[2], bh[3]);
            mma16816(acc[nb], ah[0][0], ah[0][1], ah[0][2], ah[0][3], bl[0], bl[1]);
            mma16816(acc[nb], ah[1][0], ah[1][1], ah[1][2], ah[1][3], bl[2], bl[3]);
            mma16816(acc[nb], al[0][0], al[0][1], al[0][2], al[0][3], bh[0], bh[1]);
            mma16816(acc[nb], al[1][0], al[1][1], al[1][2], al[1][3], bh[2], bh[3]);
        }
    };

    ldg_a(0); load_w(0, 0); cp_commit(); sts_a(0); cp_wait0();
    __syncthreads();
    for (int kc = 0; kc < nch; kc++) {
        if (kc + 1 < nch) {
            ldg_a(kc + 1);
            load_w(kc + 1, (kc + 1) & 1);
            cp_commit();
        }
        compute(kc & 1);
        if (kc + 1 < nch) {
            sts_a((kc + 1) & 1);
            cp_wait0();
            __syncthreads();
        }
    }
}

// fused text+image projection + edge-scatter plane (blockIdx.y == 4)
__global__ void __launch_bounds__(256, 1) gemm_fuse2(
    const float* __restrict__ text, const float* __restrict__ image,
    const __nv_bfloat16* __restrict__ Wth, const __nv_bfloat16* __restrict__ Wtl,
    const __nv_bfloat16* __restrict__ Wih, const __nv_bfloat16* __restrict__ Wil,
    const float* __restrict__ tb, const float* __restrict__ ib,
    __nv_bfloat16* __restrict__ ch, __nv_bfloat16* __restrict__ cl,
    const int* __restrict__ esrc, const int* __restrict__ edst)
{
    if (blockIdx.y == 4) {
        // counting-sort scatter: 32 CTAs x 256 threads x 16 edges
        int base = (blockIdx.x * 256 + threadIdx.x) * 16;
        int4 d4[4], s4[4];
#pragma unroll
        for (int i = 0; i < 4; i++) {
            d4[i] = *(const int4*)(edst + base + i * 4);
            s4[i] = *(const int4*)(esrc + base + i * 4);
        }
#pragma unroll
        for (int i = 0; i < 4; i++) {
            const int dd[4] = {d4[i].x, d4[i].y, d4[i].z, d4[i].w};
            const int ss[4] = {s4[i].x, s4[i].y, s4[i].z, s4[i].w};
#pragma unroll
            for (int j = 0; j < 4; j++) {
                int pos = atomicAdd(&g_cursor[dd[j]], 1);
                g_sorted[pos] = ss[j];
            }
        }
        return;
    }
    extern __shared__ char sm[];
    const uint32_t sb = smem_u32(sm);
    const int tid = threadIdx.x, w = tid >> 5, lane = tid & 31;
    const int m0 = blockIdx.x * 128, n0 = blockIdx.y * 64;

    float acc[8][4] = {};
    gemm_core_f32(sm, sb, tid, m0, n0, text, Wth, Wtl, TD, acc);
    float rf[8][4];
#pragma unroll
    for (int nb = 0; nb < 8; nb++) {
        const int cg = n0 + (lane & 3) * 2 + nb * 8;
        float b0 = tb[cg], b1 = tb[cg + 1];
        rf[nb][0] = fmaxf(acc[nb][0] + b0, 0.f);
        rf[nb][1] = fmaxf(acc[nb][1] + b1, 0.f);
        rf[nb][2] = fmaxf(acc[nb][2] + b0, 0.f);
        rf[nb][3] = fmaxf(acc[nb][3] + b1, 0.f);
        acc[nb][0] = acc[nb][1] = acc[nb][2] = acc[nb][3] = 0.f;
    }
    __syncthreads();
    gemm_core_f32(sm, sb, tid, m0, n0, image, Wih, Wil, ID, acc);

    const int r0 = m0 + w * 16 + (lane >> 2);
#pragma unroll
    for (int nb = 0; nb < 8; nb++) {
        const int cg = n0 + (lane & 3) * 2 + nb * 8;
        float b0 = ib[cg], b1 = ib[cg + 1];
        const size_t i0 = (size_t)r0 * HH + cg;
        const size_t i1 = (size_t)(r0 + 8) * HH + cg;
        split_pair_store(ch, cl, i0,
                         rf[nb][0] + fmaxf(acc[nb][0] + b0, 0.f),
                         rf[nb][1] + fmaxf(acc[nb][1] + b1, 0.f));
        split_pair_store(ch, cl, i1,
                         rf[nb][2] + fmaxf(acc[nb][2] + b0, 0.f),
                         rf[nb][3] + fmaxf(acc[nb][3] + b1, 0.f));
    }
}

// general GEMM kernel (bf16-A), epilogues:
// EPI 6: h = acc + bias (fp32 out0); out1 = dinv^2*h + bias2 (aux=dinv)
// EPI 7: y-partials: red out0 += acc@cls_w (bias = cls_w)
template<int EPI>
__global__ void __launch_bounds__(256, 1) gemm_tc(
    const void* A0v, const void* A1v,
    const __nv_bfloat16* __restrict__ WTh, const __nv_bfloat16* __restrict__ WTl,
    const float* __restrict__ bias, const float* __restrict__ bias2,
    const float* __restrict__ aux,
    void* out0v, void* out1v, int K)
{
    extern __shared__ char sm[];
    const uint32_t sb = smem_u32(sm);
    const int tid = threadIdx.x, w = tid >> 5, lane = tid & 31;
    const int m0 = blockIdx.x * 128, n0 = blockIdx.y * 64;
    float acc[8][4] = {};
    gemm_core_bf16(sb, tid, m0, n0, A0v, A1v, WTh, WTl, K, acc);

    const int r0 = m0 + w * 16 + (lane >> 2);
    if (EPI == 7) {
        const float* cw = bias;
        float p0[3] = {0.f, 0.f, 0.f}, p1[3] = {0.f, 0.f, 0.f};
#pragma unroll
        for (int nb = 0; nb < 8; nb++) {
            const int cg = n0 + (lane & 3) * 2 + nb * 8;
#pragma unroll
            for (int c = 0; c < 3; c++) {
                float w0 = __ldg(cw + cg * 3 + c), w1 = __ldg(cw + (cg + 1) * 3 + c);
                p0[c] = fmaf(acc[nb][0], w0, fmaf(acc[nb][1], w1, p0[c]));
                p1[c] = fmaf(acc[nb][2], w0, fmaf(acc[nb][3], w1, p1[c]));
            }
        }
#pragma unroll
        for (int c = 0; c < 3; c++) {
            p0[c] += __shfl_xor_sync(0xffffffffu, p0[c], 1);
            p0[c] += __shfl_xor_sync(0xffffffffu, p0[c], 2);
            p1[c] += __shfl_xor_sync(0xffffffffu, p1[c], 1);
            p1[c] += __shfl_xor_sync(0xffffffffu, p1[c], 2);
        }
        if ((lane & 3) == 0) {
            float* y = (float*)out0v;
#pragma unroll
            for (int c = 0; c < 3; c++) {
                redf(y + r0 * 4 + c, p0[c]);
                redf(y + (r0 + 8) * 4 + c, p1[c]);
            }
        }
        return;
    }
#pragma unroll
    for (int nb = 0; nb < 8; nb++) {
        const int cg = n0 + (lane & 3) * 2 + nb * 8;
        float b0 = bias[cg], b1 = bias[cg + 1];
        float v00 = acc[nb][0] + b0, v01 = acc[nb][1] + b1;
        float v10 = acc[nb][2] + b0, v11 = acc[nb][3] + b1;
        const size_t i0 = (size_t)r0 * HH + cg;
        const size_t i1 = (size_t)(r0 + 8) * HH + cg;
        *(float2*)((float*)out0v + i0) = make_float2(v00, v01);
        *(float2*)((float*)out0v + i1) = make_float2(v10, v11);
        float bb0 = bias2[cg], bb1 = bias2[cg + 1];
        float dv0 = aux[r0], dv1 = aux[r0 + 8];
        float c20 = dv0 * dv0, c21 = dv1 * dv1;
        *(float2*)((float*)out1v + i0) = make_float2(fmaf(c20, v00, bb0), fmaf(c20, v01, bb1));
        *(float2*)((float*)out1v + i1) = make_float2(fmaf(c21, v10, bb0), fmaf(c21, v11, bb1));
    }
}

// fused QKV GEMM: grid (32, 12); sel = blockIdx.y>>2; V CTAs also red vsum
__global__ void __launch_bounds__(256, 1) gemm_qkv(
    const __nv_bfloat16* __restrict__ A0, const __nv_bfloat16* __restrict__ A1,
    const __nv_bfloat16* __restrict__ WTbase, const __nv_bfloat16* __restrict__ WLbase,
    const float* __restrict__ bq, const float* __restrict__ bk,
    const float* __restrict__ bv,
    __nv_bfloat16* __restrict__ oq, __nv_bfloat16* __restrict__ ok,
    __nv_bfloat16* __restrict__ ov, float* __restrict__ vsum)
{
    extern __shared__ char sm[];
    const uint32_t sb = smem_u32(sm);
    const int tid = threadIdx.x, w = tid >> 5, lane = tid & 31;
    const int sel = blockIdx.y >> 2;
    const int m0 = blockIdx.x * 128, n0 = (blockIdx.y & 3) * 64;
    const __nv_bfloat16* WTh = WTbase + (size_t)sel * HH * HH;
    const __nv_bfloat16* WTl = WLbase + (size_t)sel * HH * HH;
    const float* bias = sel == 0 ? bq : (sel == 1 ? bk : bv);
    __nv_bfloat16* out = sel == 0 ? oq : (sel == 1 ? ok : ov);

    float acc[8][4] = {};
    gemm_core_bf16(sb, tid, m0, n0, A0, A1, WTh, WTl, HH, acc);

    const int r0 = m0 + w * 16 + (lane >> 2);
#pragma unroll
    for (int nb = 0; nb < 8; nb++) {
        const int cg = n0 + (lane & 3) * 2 + nb * 8;
        float b0 = bias[cg], b1 = bias[cg + 1];
        float v00 = acc[nb][0] + b0, v01 = acc[nb][1] + b1;
        float v10 = acc[nb][2] + b0, v11 = acc[nb][3] + b1;
        const size_t i0 = (size_t)r0 * HH + cg;
        const size_t i1 = (size_t)(r0 + 8) * HH + cg;
        ((uint32_t*)out)[i0 >> 1] = packbf2(v00, v01);
        ((uint32_t*)out)[i1 >> 1] = packbf2(v10, v11);
        if (sel == 2) {
            float s0 = v00 + v10, s1 = v01 + v11;
#pragma unroll
            for (int off = 4; off < 32; off <<= 1) {
                s0 += __shfl_xor_sync(0xffffffffu, s0, off);
                s1 += __shfl_xor_sync(0xffffffffu, s1, off);
            }
            if (lane < 4) {
                redf(vsum + cg, s0);
                redf(vsum + cg + 1, s1);
            }
        }
    }
}

// ============== HMMA flash attention: 128 q-rows x 1 head per CTA ============
#define SM_BUFSTRIDE 32768
#define SM_VOFF 16384
#define SM_Q 65536
#define SM_ATT_TOTAL 81920

__device__ __forceinline__ void load_kv_tile(
    uint32_t sb, int buf, int kt, int head,
    const __nv_bfloat16* kb, const __nv_bfloat16* vb, int tid)
{
    const char* kc = (const char*)kb;
    const char* vc = (const char*)vb;
#pragma unroll
    for (int j = 0; j < 8; j++) {
        int flat = tid + j * 256;
        int arr = flat >> 10;
        int row = (flat >> 3) & 127;
        int c = flat & 7;
        const char* src = (arr ? vc : kc) +
            (((size_t)(kt + row) * HH + head * HD) << 1) + c * 16;
        uint32_t dst = sb + buf * SM_BUFSTRIDE + arr * SM_VOFF +
                       swz128((uint32_t)(row * 128 + c * 16));
        cp16(dst, src);
    }
}

__global__ void __launch_bounds__(256, 1) attn_mma(
    const __nv_bfloat16* __restrict__ qb, const __nv_bfloat16* __restrict__ kb,
    const __nv_bfloat16* __restrict__ vb, const float* __restrict__ vsum,
    __nv_bfloat16* __restrict__ oh, __nv_bfloat16* __restrict__ ol)
{
    extern __shared__ char sm[];
    const uint32_t sb = smem_u32(sm);
    const int tid = threadIdx.x, w = tid >> 5, lane = tid & 31;
    const int q0 = blockIdx.x * 128, head = blockIdx.y;

    {
        const char* qc = (const char*)qb;
#pragma unroll
        for (int j = 0; j < 4; j++) {
            int flat = tid + j * 256;
            int row = flat >> 3, c = flat & 7;
            const char* src = qc + (((size_t)(q0 + row) * HH + head * HD) << 1) + c * 16;
            cp16(sb + SM_Q + swz128((uint32_t)(row * 128 + c * 16)), src);
        }
        load_kv_tile(sb, 0, 0, head, kb, vb, tid);
        cp_commit();
        cp_wait0();
        __syncthreads();
    }

    uint32_t qa[4][4];
    {
        const int rowa = w * 16 + (lane & 7) + ((lane >> 3) & 1) * 8;
        const int cb = ((lane >> 4) & 1) * 16;
#pragma unroll
        for (int kk = 0; kk < 4; kk++)
            ldsm4(qa[kk], sb + SM_Q + swz128((uint32_t)(rowa * 128 + kk * 32 + cb)));
    }

    float oacc[8][4] = {};
    float sumd0 = 0.f, sumd1 = 0.f;

    for (int t = 0; t < 32; t++) {
        const uint32_t kbase = sb + (t & 1) * SM_BUFSTRIDE;
        const uint32_t vbase = kbase + SM_VOFF;
        if (t + 1 < 32) {
            load_kv_tile(sb, (t + 1) & 1, (t + 1) * 128, head, kb, vb, tid);
            cp_commit();
        }
#pragma unroll 2
        for (int kk = 0; kk < 8; kk++) {
            float s[2][4] = {{0.f,0.f,0.f,0.f},{0.f,0.f,0.f,0.f}};
#pragma unroll
            for (int half = 0; half < 2; half++) {
                const int keyl = kk * 16 + half * 8 + (lane & 7);
#pragma unroll
                for (int kk2 = 0; kk2 < 2; kk2++) {
                    uint32_t b[4];
                    ldsm4(b, kbase + swz128((uint32_t)(keyl * 128 + kk2 * 64 +
                                                       ((lane >> 3) & 3) * 16)));
                    mma16816(s[half], qa[2*kk2][0], qa[2*kk2][1], qa[2*kk2][2],
                             qa[2*kk2][3], b[0], b[1]);
                    mma16816(s[half], qa[2*kk2+1][0], qa[2*kk2+1][1], qa[2*kk2+1][2],
                             qa[2*kk2+1][3], b[2], b[3]);
                }
            }
#pragma unroll
            for (int half = 0; half < 2; half++) {
#pragma unroll
                for (int j = 0; j < 4; j++) {
                    float x = s[half][j] * 0.125f;
                    float h = fmaf(x, 4.166666667e-2f, 0.166666667f);
                    h = fmaf(h, x, 0.5f);
                    h = fmaf(h, x, 1.0f);
                    float dlt = x * h;
                    s[half][j] = dlt;
                    if (j < 2) sumd0 += dlt; else sumd1 += dlt;
                }
            }
            uint32_t A0 = packbf2(s[0][0], s[0][1]);
            uint32_t A1 = packbf2(s[0][2], s[0][3]);
            uint32_t A2 = packbf2(s[1][0], s[1][1]);
            uint32_t A3 = packbf2(s[1][2], s[1][3]);
            const int keyl2 = kk * 16 + (lane & 7) + ((lane >> 3) & 1) * 8;
            const int cb2 = ((lane >> 4) & 1) * 16;
#pragma unroll
            for (int nb2 = 0; nb2 < 4; nb2++) {
                uint32_t b[4];
                ldsm4t(b, vbase + swz128((uint32_t)(keyl2 * 128 + nb2 * 32 + cb2)));
                mma16816(oacc[2*nb2],     A0, A1, A2, A3, b[0], b[1]);
                mma16816(oacc[2*nb2 + 1], A0, A1, A2, A3, b[2], b[3]);
            }
        }
        if (t + 1 < 32) { cp_wait0(); __syncthreads(); }
    }

    sumd0 += __shfl_xor_sync(0xffffffffu, sumd0, 1);
    sumd0 += __shfl_xor_sync(0xffffffffu, sumd0, 2);
    sumd1 += __shfl_xor_sync(0xffffffffu, sumd1, 1);
    sumd1 += __shfl_xor_sync(0xffffffffu, sumd1, 2);
    const float inv0 = 1.0f / (4096.0f + sumd0);
    const float inv1 = 1.0f / (4096.0f + sumd1);
    const int r0 = q0 + w * 16 + (lane >> 2);
    const int cbase = head * HD + (lane & 3) * 2;
#pragma unroll
    for (int nb = 0; nb < 8; nb++) {
        int d = cbase + nb * 8;
        float sv0 = vsum[d], sv1 = vsum[d + 1];
        split_pair_store(oh, ol, (size_t)r0 * HH + d,
                         (sv0 + oacc[nb][0]) * inv0, (sv1 + oacc[nb][1]) * inv0);
        split_pair_store(oh, ol, (size_t)(r0 + 8) * HH + d,
                         (sv0 + oacc[nb][2]) * inv1, (sv1 + oacc[nb][3]) * inv1);
    }
}

// ---------------- launch -----------------------------------------------------
extern "C" void kernel_launch(void* const* d_in, const int* in_sizes, int n_in,
                              void* d_out, int out_size)
{
    const float* text    = (const float*)d_in[0];
    const float* image   = (const float*)d_in[1];
    const int*   ei      = (const int*)d_in[2];
    const float* text_w  = (const float*)d_in[3];
    const float* text_b  = (const float*)d_in[4];
    const float* image_w = (const float*)d_in[5];
    const float* image_b = (const float*)d_in[6];
    const float* wq = (const float*)d_in[7];  const float* bq = (const float*)d_in[8];
    const float* wk = (const float*)d_in[9];  const float* bk = (const float*)d_in[10];
    const float* wv = (const float*)d_in[11]; const float* bv = (const float*)d_in[12];
    const float* wo = (const float*)d_in[13]; const float* bo = (const float*)d_in[14];
    const float* gcn1_w = (const float*)d_in[15]; const float* gcn1_b = (const float*)d_in[16];
    const float* gcn2_w = (const float*)d_in[17]; const float* gcn2_b = (const float*)d_in[18];
    const float* cls_w  = (const float*)d_in[19]; const float* cls_b  = (const float*)d_in[20];
    float* out = (float*)d_out;

    float *hb, *g1, *yb, *dinv, *vsum, *bg;
    __nv_bfloat16 *ch, *cl, *qbb, *kbb, *vbb, *obh, *obl, *g1h, *g1l, *wth, *wtl;
    cudaGetSymbolAddress((void**)&hb, g_h);
    cudaGetSymbolAddress((void**)&g1, g_g1);
    cudaGetSymbolAddress((void**)&yb, g_y);
    cudaGetSymbolAddress((void**)&dinv, g_dinv);
    cudaGetSymbolAddress((void**)&vsum, g_vsum);
    cudaGetSymbolAddress((void**)&bg, g_bg);
    cudaGetSymbolAddress((void**)&ch, g_ch);
    cudaGetSymbolAddress((void**)&cl, g_cl);
    cudaGetSymbolAddress((void**)&qbb, g_qb);
    cudaGetSymbolAddress((void**)&kbb, g_kb);
    cudaGetSymbolAddress((void**)&vbb, g_vb);
    cudaGetSymbolAddress((void**)&obh, g_obh);
    cudaGetSymbolAddress((void**)&obl, g_obl);
    cudaGetSymbolAddress((void**)&g1h, g_g1h);
    cudaGetSymbolAddress((void**)&g1l, g_g1l);
    cudaGetSymbolAddress((void**)&wth, g_wth);
    cudaGetSymbolAddress((void**)&wtl, g_wtl);

    // 1: weight prep + hist + WG=Wo@G1 + bG + zero(vsum, y)
    k_wprep_all<<<dim3(24, 8, 8), dim3(32, 32)>>>(
        text_w, image_w, wq, wk, wv, wo, gcn1_w, gcn2_w, bo, ei + EE);

    // 2: scan (start/cursor/dinv, re-zero cnt, bconst)
    k_scan<<<1, 1024>>>(gcn2_b, cls_w);

    // 3: fused text+image projection + scatter plane
    {
        static bool done = false;
        if (!done) {
            cudaFuncSetAttribute(gemm_fuse2,
                                 cudaFuncAttributeMaxDynamicSharedMemorySize, GEMM_SMEM);
            done = true;
        }
        gemm_fuse2<<<dim3(32, 5), 256, GEMM_SMEM>>>(
            text, image, wth + WOFF_TEXT, wtl + WOFF_TEXT,
            wth + WOFF_IMAGE, wtl + WOFF_IMAGE, text_b, image_b, ch, cl,
            ei, ei + EE);
    }

    // 4: fused QKV (+vsum reds)
    {
        static bool done = false;
        if (!done) {
            cudaFuncSetAttribute(gemm_qkv,
                                 cudaFuncAttributeMaxDynamicSharedMemorySize, GEMM_SMEM);
            done = true;
        }
        gemm_qkv<<<dim3(32, 12), 256, GEMM_SMEM>>>(
            ch, cl, wth + WOFF_WQ, wtl + WOFF_WQ, bq, bk, bv, qbb, kbb, vbb, vsum);
    }

    // 5: attention
    cudaFuncSetAttribute(attn_mma, cudaFuncAttributeMaxDynamicSharedMemorySize,
                         SM_ATT_TOTAL);
    attn_mma<<<dim3(NN / 128, NHD), 256, SM_ATT_TOTAL>>>(qbb, kbb, vbb, vsum, obh, obl);

    // 6: GCN1 GEMM with composed weights (h = ob@WG + bG; init = dinv^2*h + b1)
    {
        static bool done = false;
        if (!done) {
            cudaFuncSetAttribute(gemm_tc<6>,
                                 cudaFuncAttributeMaxDynamicSharedMemorySize, GEMM_SMEM);
            done = true;
        }
        gemm_tc<6><<<dim3(32, 4), 256, GEMM_SMEM>>>(
            obh, obl, wth + WOFF_G1, wtl + WOFF_G1, bg, gcn1_b, dinv, hb, g1, HH);
    }

    // 7: GCN1 aggregation (gather) + relu + split
    k_agg1<<<NN * 32 / 256, 256>>>(hb, g1, g1h, g1l);

    // 8: GCN2 GEMM in classifier space (red into y)
    {
        static bool done = false;
        if (!done) {
            cudaFuncSetAttribute(gemm_tc<7>,
                                 cudaFuncAttributeMaxDynamicSharedMemorySize, GEMM_SMEM);
            done = true;
        }
        gemm_tc<7><<<dim3(32, 4), 256, GEMM_SMEM>>>(
            g1h, g1l, wth + WOFF_G2, wtl + WOFF_G2, cls_w, nullptr, nullptr,
            yb, nullptr, HH);
    }

    // 9: GCN2 aggregation on y + bias
    k_agg2y<<<NN * 32 / 256, 256>>>(yb, cls_b, out);
}

// round 11
// speedup vs baseline: 1.0292x; 1.0292x over previous
#include <cuda_runtime.h>
#include <cuda_bf16.h>
#include <cstdint>
#include <cstddef>

#define NN 4096
#define TD 768
#define ID 512
#define HH 256
#define NHD 4
#define HD 64
#define EE 131072
#define NC 3

// ---------------- scratch (static device globals; no allocation) -------------
__device__ float g_h[NN * HH];      // fp32 transformed features (GCN1 h)
__device__ float g_g1[NN * HH];     // GCN1 init (self-loop term)
__device__ float g_y[NN * 4];       // GCN2 h @ cls_w (padded to 4)
__device__ float g_dinv[NN];
__device__ float g_vsum[HH];
__device__ float g_bconst[3];
__device__ float g_bg[HH];          // bo @ G1
__device__ int   g_cnt[NN];         // zero at module load; re-zeroed by k_scan
__device__ int   g_start[NN + 1];
__device__ int   g_cursor[NN];
__device__ int   g_sorted[EE];
// bf16 activation chain (hi/lo pairs)
__device__ __nv_bfloat16 g_ch[NN * HH],  g_cl[NN * HH];
__device__ __nv_bfloat16 g_qb[NN * HH];
__device__ __nv_bfloat16 g_kb[NN * HH];
__device__ __nv_bfloat16 g_vb[NN * HH];
__device__ __nv_bfloat16 g_obh[NN * HH], g_obl[NN * HH];
__device__ __nv_bfloat16 g_g1h[NN * HH], g_g1l[NN * HH];
// transposed+split weights [n][K]
#define WOFF_TEXT  0
#define WOFF_IMAGE 196608
#define WOFF_WQ    327680
#define WOFF_WK    393216
#define WOFF_WV    458752
#define WOFF_G1    524288   /* holds WG = Wo@G1, composed */
#define WOFF_G2    589824
#define WTOT       655360
__device__ __nv_bfloat16 g_wth[WTOT], g_wtl[WTOT];

// =================== helpers =================================================
__device__ __forceinline__ uint32_t smem_u32(const void* p) {
    uint32_t a;
    asm("{ .reg .u64 t; cvta.to.shared.u64 t, %1; cvt.u32.u64 %0, t; }"
        : "=r"(a) : "l"(p));
    return a;
}
__device__ __forceinline__ uint32_t swz128(uint32_t o) { return o ^ ((o >> 3) & 0x70); }
__device__ __forceinline__ uint32_t swz64(uint32_t o)  { return o ^ ((o >> 3) & 0x30); }
__device__ __forceinline__ uint32_t packbf2(float x0, float x1) {
    uint32_t r;  // lo = x0, hi = x1
    asm("cvt.rn.satfinite.bf16x2.f32 %0, %1, %2;" : "=r"(r) : "f"(x1), "f"(x0));
    return r;
}
__device__ __forceinline__ void split_pair_store(void* oh, void* ol, size_t idx,
                                                 float x, float y) {
    uint32_t hp = packbf2(x, y);
    float hx = __uint_as_float(hp << 16);
    float hy = __uint_as_float(hp & 0xFFFF0000u);
    uint32_t lp = packbf2(x - hx, y - hy);
    ((uint32_t*)oh)[idx >> 1] = hp;
    ((uint32_t*)ol)[idx >> 1] = lp;
}
__device__ __forceinline__ void mma16816(float* c,
    uint32_t a0, uint32_t a1, uint32_t a2, uint32_t a3, uint32_t b0, uint32_t b1) {
    asm volatile("mma.sync.aligned.m16n8k16.row.col.f32.bf16.bf16.f32 "
        "{%0,%1,%2,%3}, {%4,%5,%6,%7}, {%8,%9}, {%0,%1,%2,%3};"
        : "+f"(c[0]), "+f"(c[1]), "+f"(c[2]), "+f"(c[3])
        : "r"(a0), "r"(a1), "r"(a2), "r"(a3), "r"(b0), "r"(b1));
}
__device__ __forceinline__ void ldsm4(uint32_t* r, uint32_t a) {
    asm volatile("ldmatrix.sync.aligned.m8n8.x4.shared.b16 {%0,%1,%2,%3}, [%4];"
        : "=r"(r[0]), "=r"(r[1]), "=r"(r[2]), "=r"(r[3]) : "r"(a));
}
__device__ __forceinline__ void ldsm4t(uint32_t* r, uint32_t a) {
    asm volatile("ldmatrix.sync.aligned.m8n8.x4.trans.shared.b16 {%0,%1,%2,%3}, [%4];"
        : "=r"(r[0]), "=r"(r[1]), "=r"(r[2]), "=r"(r[3]) : "r"(a));
}
__device__ __forceinline__ void cp16(uint32_t dst, const void* src) {
    asm volatile("cp.async.cg.shared.global [%0], [%1], 16;" :: "r"(dst), "l"(src) : "memory");
}
__device__ __forceinline__ void cp_commit() {
    asm volatile("cp.async.commit_group;" ::: "memory");
}
__device__ __forceinline__ void cp_wait0() {
    asm volatile("cp.async.wait_group 0;" ::: "memory");
}
__device__ __forceinline__ void redf(float* p, float v) {
    asm volatile("red.global.add.f32 [%0], %1;" :: "l"(p), "f"(v) : "memory");
}

// ====== single-launch prep: weights + hist + WG compose + bG + zeroing =======
__global__ void k_wprep_all(
    const float* w0, const float* w1, const float* w2, const float* w3,
    const float* w4, const float* wo, const float* g1w, const float* w7,
    const float* bo, const int* __restrict__ edst)
{
    const int z = blockIdx.z;
    const int tx = threadIdx.x, ty = threadIdx.y;
    if (z == 5) {
        int flat = (blockIdx.y * 24 + blockIdx.x) * 1024 + ty * 32 + tx;
        if (flat < EE) atomicAdd(&g_cnt[edst[flat]], 1);
        return;
    }
    if (z == 6) {
        if (blockIdx.x < 8) {
            // WG^T[n][k] = sum_j Wo[k][j] * G1[j][n]
            int k0 = blockIdx.x * 32, n0 = blockIdx.y * 32;
            __shared__ float sW[32][33], sG[32][33];
            float acc = 0.f;
            for (int j0 = 0; j0 < HH; j0 += 32) {
                sW[ty][tx] = wo[(size_t)(k0 + ty) * HH + j0 + tx];
                sG[ty][tx] = g1w[(size_t)(j0 + ty) * HH + n0 + tx];
                __syncthreads();
#pragma unroll
                for (int jj = 0; jj < 32; jj++)
                    acc = fmaf(sW[tx][jj], sG[jj][ty], acc);
                __syncthreads();
            }
            __nv_bfloat16 h = __float2bfloat16(acc);
            __nv_bfloat16 l = __float2bfloat16(acc - __bfloat162float(h));
            size_t idx = (size_t)WOFF_G1 + (size_t)(n0 + ty) * HH + k0 + tx;
            g_wth[idx] = h;
            g_wtl[idx] = l;
        } else if (blockIdx.x == 8) {
            if (blockIdx.y == 0) {
                int t = ty * 32 + tx;
                if (t < HH) {
                    float s = 0.f;
                    for (int j = 0; j < HH; j++)
                        s = fmaf(bo[j], g1w[(size_t)j * HH + t], s);
                    g_bg[t] = s;
                }
            }
        } else if (blockIdx.x == 9) {
            int flat = blockIdx.y * 1024 + ty * 32 + tx;
            for (int i = flat; i < NN * 4 + HH; i += 8192) {
                if (i < NN * 4) g_y[i] = 0.f;
                else g_vsum[i - NN * 4] = 0.f;
            }
        }
        return;
    }
    const float* W; int K, off;
    switch (z) {
        case 0: W = w0; K = TD; off = WOFF_TEXT; break;
        case 1: W = w1; K = ID; off = WOFF_IMAGE; break;
        case 2: W = w2; K = HH; off = WOFF_WQ; break;
        case 3: W = w3; K = HH; off = WOFF_WK; break;
        case 4: W = w4; K = HH; off = WOFF_WV; break;
        default: W = w7; K = HH; off = WOFF_G2; break;
    }
    int k0 = blockIdx.x * 32;
    if (k0 >= K) return;
    int n0 = blockIdx.y * 32;
    __shared__ float t[32][33];
    t[ty][tx] = W[(size_t)(k0 + ty) * HH + n0 + tx];
    __syncthreads();
    float v = t[tx][ty];
    __nv_bfloat16 h = __float2bfloat16(v);
    __nv_bfloat16 l = __float2bfloat16(v - __bfloat162float(h));
    size_t idx = (size_t)off + (size_t)(n0 + ty) * K + k0 + tx;
    g_wth[idx] = h;
    g_wtl[idx] = l;
}

// 1 CTA, 1024 threads: prefix-scan cnt -> start/cursor, dinv; re-zero cnt;
// bconst = gcn2_b @ cls_w.
__global__ void k_scan(const float* __restrict__ b2, const float* __restrict__ cw)
{
    __shared__ int wsum[32];
    const int t = threadIdx.x, lane = t & 31, wid = t >> 5;
    if (t < 3) {
        float s = 0.f;
        for (int j = 0; j < HH; j++) s = fmaf(b2[j], cw[j * 3 + t], s);
        g_bconst[t] = s;
    }
    const int base = t * 4;
    int c0 = g_cnt[base], c1 = g_cnt[base + 1], c2 = g_cnt[base + 2], c3 = g_cnt[base + 3];
    int s = c0 + c1 + c2 + c3;
    int v = s;
#pragma unroll
    for (int off = 1; off < 32; off <<= 1) {
        int u = __shfl_up_sync(0xffffffffu, v, off);
        if (lane >= off) v += u;
    }
    if (lane == 31) wsum[wid] = v;
    __syncthreads();
    if (wid == 0) {
        int x = wsum[lane];
#pragma unroll
        for (int off = 1; off < 32; off <<= 1) {
            int u = __shfl_up_sync(0xffffffffu, x, off);
            if (lane >= off) x += u;
        }
        wsum[lane] = x;
    }
    __syncthreads();
    int excl = v - s + (wid > 0 ? wsum[wid - 1] : 0);
    int e0 = excl, e1 = e0 + c0, e2 = e1 + c1, e3 = e2 + c2;
    g_start[base] = e0;  g_cursor[base] = e0;
    g_start[base + 1] = e1; g_cursor[base + 1] = e1;
    g_start[base + 2] = e2; g_cursor[base + 2] = e2;
    g_start[base + 3] = e3; g_cursor[base + 3] = e3;
    g_dinv[base]     = rsqrtf((float)(c0 + 1));
    g_dinv[base + 1] = rsqrtf((float)(c1 + 1));
    g_dinv[base + 2] = rsqrtf((float)(c2 + 1));
    g_dinv[base + 3] = rsqrtf((float)(c3 + 1));
    g_cnt[base] = 0; g_cnt[base + 1] = 0; g_cnt[base + 2] = 0; g_cnt[base + 3] = 0;
    if (t == 1023) g_start[NN] = e3 + c3;
}

// ====== GCN layer-1 aggregation: warp per dst, gather ========================
__global__ void __launch_bounds__(256) k_agg1(
    const float* __restrict__ h, const float* __restrict__ init,
    __nv_bfloat16* __restrict__ oh, __nv_bfloat16* __restrict__ ol)
{
    const int dstn = (blockIdx.x * 256 + threadIdx.x) >> 5;
    const int lane = threadIdx.x & 31;
    if (dstn >= NN) return;
    const int beg = g_start[dstn], end = g_start[dstn + 1];
    const float dd = g_dinv[dstn];

    float acc[8];
    {
        const float4* ir = (const float4*)(init + (size_t)dstn * HH) + lane * 2;
        float4 a = ir[0], b = ir[1];
        acc[0] = a.x; acc[1] = a.y; acc[2] = a.z; acc[3] = a.w;
        acc[4] = b.x; acc[5] = b.y; acc[6] = b.z; acc[7] = b.w;
    }
    for (int e = beg; e < end; e += 32) {
        int n = end - e; if (n > 32) n = 32;
        int sidx = 0; float dv = 0.f;
        if (lane < n) {
            sidx = __ldg(&g_sorted[e + lane]);
            dv = __ldg(&g_dinv[sidx]);
        }
#pragma unroll 4
        for (int j = 0; j < n; j++) {
            int s = __shfl_sync(0xffffffffu, sidx, j);
            float cf = __shfl_sync(0xffffffffu, dv, j) * dd;
            const float4* hr = (const float4*)(h + ((size_t)s << 8)) + (lane << 1);
            float4 a = __ldg(hr), b = __ldg(hr + 1);
            acc[0] = fmaf(cf, a.x, acc[0]); acc[1] = fmaf(cf, a.y, acc[1]);
            acc[2] = fmaf(cf, a.z, acc[2]); acc[3] = fmaf(cf, a.w, acc[3]);
            acc[4] = fmaf(cf, b.x, acc[4]); acc[5] = fmaf(cf, b.y, acc[5]);
            acc[6] = fmaf(cf, b.z, acc[6]); acc[7] = fmaf(cf, b.w, acc[7]);
        }
    }
#pragma unroll
    for (int p = 0; p < 4; p++) {
        float x = fmaxf(acc[2 * p], 0.f), y = fmaxf(acc[2 * p + 1], 0.f);
        split_pair_store(oh, ol, (size_t)dstn * HH + lane * 8 + 2 * p, x, y);
    }
}

// ====== GCN layer-2 aggregation on y[4] (classifier space) ===================
__global__ void __launch_bounds__(256) k_agg2y(
    const float* __restrict__ y, const float* __restrict__ cls_b,
    float* __restrict__ out)
{
    const int d = (blockIdx.x * 256 + threadIdx.x) >> 5;
    const int lane = threadIdx.x & 31;
    if (d >= NN) return;
    const int beg = g_start[d], end = g_start[d + 1];
    float a0 = 0.f, a1 = 0.f, a2 = 0.f;
    for (int e = beg + lane; e < end; e += 32) {
        int s = __ldg(&g_sorted[e]);
        float dv = __ldg(&g_dinv[s]);
        float4 yv = *(const float4*)(y + s * 4);
        a0 = fmaf(dv, yv.x, a0);
        a1 = fmaf(dv, yv.y, a1);
        a2 = fmaf(dv, yv.z, a2);
    }
#pragma unroll
    for (int off = 16; off > 0; off >>= 1) {
        a0 += __shfl_xor_sync(0xffffffffu, a0, off);
        a1 += __shfl_xor_sync(0xffffffffu, a1, off);
        a2 += __shfl_xor_sync(0xffffffffu, a2, off);
    }
    if (lane == 0) {
        float dd = g_dinv[d];
        float4 yd = *(const float4*)(y + d * 4);
        out[d * 3 + 0] = fmaf(dd, fmaf(dd, yd.x, a0), g_bconst[0] + cls_b[0]);
        out[d * 3 + 1] = fmaf(dd, fmaf(dd, yd.y, a1), g_bconst[1] + cls_b[1]);
        out[d * 3 + 2] = fmaf(dd, fmaf(dd, yd.z, a2), g_bconst[2] + cls_b[2]);
    }
}

// =============== HMMA GEMM cores =============================================
#define GST 24576
#define GS_AL 8192
#define GS_W  16384
#define GS_WL 20480
#define GEMM_SMEM 49152

// npass: 3 = full hi/lo (AhWh + AhWl + AlWh), 1 = AhWh only (skips lo loads)
__device__ __forceinline__ void gemm_core_bf16(
    uint32_t sb, int tid, int m0, int n0,
    const void* A0v, const void* A1v,
    const __nv_bfloat16* WTh, const __nv_bfloat16* WTl,
    int K, float acc[8][4], int npass)
{
    const int w = tid >> 5, lane = tid & 31;
    const int rowa = w * 16 + (lane & 7) + ((lane >> 3) & 1) * 8;
    const int acb  = ((lane >> 4) & 1) * 16;
    const int nrow = lane & 7;
    const int bcb  = ((lane >> 3) & 3) * 16;
    const int nch = K >> 5;
    const int ja = (npass == 1) ? 2 : 4;   // A-load iterations (hi only vs hi+lo)
    const int jw = (npass == 1) ? 1 : 2;   // W-load iterations

    auto load_w = [&](int kc, int st) {
        int k0 = kc << 5;
        uint32_t base = sb + st * GST + GS_W;
        for (int j = 0; j < jw; j++) {
            int flat = tid + j * 256;
            int part = flat >> 8, r = (flat >> 2) & 63, c = flat & 3;
            const char* src = (const char*)(part ? WTl : WTh) +
                              (((size_t)(n0 + r) * K + k0) << 1) + c * 16;
            cp16(base + part * 4096 + swz64((uint32_t)(r * 64 + c * 16)), src);
        }
    };
    auto load_a = [&](int kc, int st) {
        int k0 = kc << 5;
        uint32_t base = sb + st * GST;
        for (int j = 0; j < ja; j++) {
            int flat = tid + j * 256;
            int part = flat >> 9, r = (flat >> 2) & 127, c = flat & 3;
            const char* src = (const char*)(part ? A1v : A0v) +
                              (((size_t)(m0 + r) * K + k0) << 1) + c * 16;
            cp16(base + part * GS_AL + swz64((uint32_t)(r * 64 + c * 16)), src);
        }
    };
    auto compute = [&](int st) {
        uint32_t base = sb + st * GST;
        uint32_t ah[2][4], al[2][4];
#pragma unroll
        for (int kk2 = 0; kk2 < 2; kk2++) {
            uint32_t ao = swz64((uint32_t)(rowa * 64 + kk2 * 32 + acb));
            ldsm4(ah[kk2], base + ao);
            if (npass == 3) ldsm4(al[kk2], base + GS_AL + ao);
        }
#pragma unroll
        for (int nb = 0; nb < 8; nb++) {
            uint32_t bo = swz64((uint32_t)((nb * 8 + nrow) * 64 + bcb));
            uint32_t bh[4];
            ldsm4(bh, base + GS_W + bo);
            mma16816(acc[nb], ah[0][0], ah[0][1], ah[0][2], ah[0][3], bh[0], bh[1]);
            mma16816(acc[nb], ah[1][0], ah[1][1], ah[1][2], ah[1][3], bh[2], bh[3]);
            if (npass == 3) {
                uint32_t bl[4];
                ldsm4(bl, base + GS_WL + bo);
                mma16816(acc[nb], ah[0][0], ah[0][1], ah[0][2], ah[0][3], bl[0], bl[1]);
                mma16816(acc[nb], ah[1][0], ah[1][1], ah[1][2], ah[1][3], bl[2], bl[3]);
                mma16816(acc[nb], al[0][0], al[0][1], al[0][2], al[0][3], bh[0], bh[1]);
                mma16816(acc[nb], al[1][0], al[1][1], al[1][2], al[1][3], bh[2], bh[3]);
            }
        }
    };

    load_a(0, 0); load_w(0, 0); cp_commit(); cp_wait0();
    __syncthreads();
    for (int kc = 0; kc < nch; kc++) {
        if (kc + 1 < nch) {
            load_a(kc + 1, (kc + 1) & 1);
            load_w(kc + 1, (kc + 1) & 1);
            cp_commit();
        }
        compute(kc & 1);
        if (kc + 1 < nch) { cp_wait0(); __syncthreads(); }
    }
}

__device__ __forceinline__ void gemm_core_f32(
    char* smc, uint32_t sb, int tid, int m0, int n0,
    const float* A, const __nv_bfloat16* WTh, const __nv_bfloat16* WTl,
    int K, float acc[8][4])
{
    const int w = tid >> 5, lane = tid & 31;
    const int rowa = w * 16 + (lane & 7) + ((lane >> 3) & 1) * 8;
    const int acb  = ((lane >> 4) & 1) * 16;
    const int nrow = lane & 7;
    const int bcb  = ((lane >> 3) & 3) * 16;
    const int nch = K >> 5;
    float4 ar[4];

    auto load_w = [&](int kc, int st) {
        int k0 = kc << 5;
        uint32_t base = sb + st * GST + GS_W;
#pragma unroll
        for (int j = 0; j < 2; j++) {
            int flat = tid + j * 256;
            int part = flat >> 8, r = (flat >> 2) & 63, c = flat & 3;
            const char* src = (const char*)(part ? WTl : WTh) +
                              (((size_t)(n0 + r) * K + k0) << 1) + c * 16;
            cp16(base + part * 4096 + swz64((uint32_t)(r * 64 + c * 16)), src);
        }
    };
    auto ldg_a = [&](int kc) {
        int k0 = kc << 5;
#pragma unroll
        for (int j = 0; j < 4; j++) {
            int flat = tid + j * 256;
            int r = flat >> 3, c = flat & 7;
            ar[j] = *(const float4*)(A + (size_t)(m0 + r) * K + k0 + c * 4);
        }
    };
    auto sts_a = [&](int st) {
        uint32_t off0 = st * GST;
#pragma unroll
        for (int j = 0; j < 4; j++) {
            int flat = tid + j * 256;
            int r = flat >> 3, c = flat & 7;
            uint32_t off = swz64((uint32_t)(r * 64 + c * 8));
            uint32_t h0 = packbf2(ar[j].x, ar[j].y);
            uint32_t h1 = packbf2(ar[j].z, ar[j].w);
            float hx = __uint_as_float(h0 << 16), hy = __uint_as_float(h0 & 0xFFFF0000u);
            float hz = __uint_as_float(h1 << 16), hw = __uint_as_float(h1 & 0xFFFF0000u);
            uint32_t l0 = packbf2(ar[j].x - hx, ar[j].y - hy);
            uint32_t l1 = packbf2(ar[j].z - hz, ar[j].w - hw);
            *(uint2*)(smc + off0 + off) = make_uint2(h0, h1);
            *(uint2*)(smc + off0 + GS_AL + off) = make_uint2(l0, l1);
        }
    };
    auto compute = [&](int st) {
        uint32_t base = sb + st * GST;
        uint32_t ah[2][4], al[2][4];
#pragma unroll
        for (int kk2 = 0; kk2 < 2; kk2++) {
            uint32_t ao = swz64((uint32_t)(rowa * 64 + kk2 * 32 + acb));
            ldsm4(ah[kk2], base + ao);
            ldsm4(al[kk2], base + GS_AL + ao);
        }
#pragma unroll
        for (int nb = 0; nb < 8; nb++) {
            uint32_t bo = swz64((uint32_t)((nb * 8 + nrow) * 64 + bcb));
            uint32_t bh[4], bl[4];
            ldsm4(bh, base + GS_W + bo);
            ldsm4(bl, base + GS_WL + bo);
            mma16816(acc[nb], ah[0][0], ah[0][1], ah[0][2], ah[0][3], bh[0], bh[1]);
            mma16816(acc[nb], ah[1][0], ah[1][1], ah[1][2], ah[1][3], bh[2], bh[3]);
            mma16816(acc[nb], ah[0][0], ah[0][1], ah[0][2], ah[0][3], bl[0], bl[1]);
            mma16816(acc[nb], ah[1][0], ah[1][1], ah[1][2], ah[1][3], bl[2], bl[3]);
            mma16816(acc[nb], al[0][0], al[0][1], al[0][2], al[0][3], bh[0], bh[1]);
            mma16816(acc[nb], al[1][0], al[1][1], al[1][2], al[1][3], bh[2], bh[3]);
        }
    };

    ldg_a(0); load_w(0, 0); cp_commit(); sts_a(0); cp_wait0();
    __syncthreads();
    for (int kc = 0; kc < nch; kc++) {
        if (kc + 1 < nch) {
            ldg_a(kc + 1);
            load_w(kc + 1, (kc + 1) & 1);
            cp_commit();
        }
        compute(kc & 1);
        if (kc + 1 < nch) {
            sts_a((kc + 1) & 1);
            cp_wait0();
            __syncthreads();
        }
    }
}

// fused text+image projection + edge-scatter plane (blockIdx.y == 4)
__global__ void __launch_bounds__(256, 2) gemm_fuse2(
    const float* __restrict__ text, const float* __restrict__ image,
    const __nv_bfloat16* __restrict__ Wth, const __nv_bfloat16* __restrict__ Wtl,
    const __nv_bfloat16* __restrict__ Wih, const __nv_bfloat16* __restrict__ Wil,
    const float* __restrict__ tb, const float* __restrict__ ib,
    __nv_bfloat16* __restrict__ ch, __nv_bfloat16* __restrict__ cl,
    const int* __restrict__ esrc, const int* __restrict__ edst)
{
    if (blockIdx.y == 4) {
        int base = (blockIdx.x * 256 + threadIdx.x) * 16;
        int4 d4[4], s4[4];
#pragma unroll
        for (int i = 0; i < 4; i++) {
            d4[i] = *(const int4*)(edst + base + i * 4);
            s4[i] = *(const int4*)(esrc + base + i * 4);
        }
#pragma unroll
        for (int i = 0; i < 4; i++) {
            const int dd[4] = {d4[i].x, d4[i].y, d4[i].z, d4[i].w};
            const int ss[4] = {s4[i].x, s4[i].y, s4[i].z, s4[i].w};
#pragma unroll
            for (int j = 0; j < 4; j++) {
                int pos = atomicAdd(&g_cursor[dd[j]], 1);
                g_sorted[pos] = ss[j];
            }
        }
        return;
    }
    extern __shared__ char sm[];
    const uint32_t sb = smem_u32(sm);
    const int tid = threadIdx.x, w = tid >> 5, lane = tid & 31;
    const int m0 = blockIdx.x * 128, n0 = blockIdx.y * 64;

    float acc[8][4] = {};
    gemm_core_f32(sm, sb, tid, m0, n0, text, Wth, Wtl, TD, acc);
    float rf[8][4];
#pragma unroll
    for (int nb = 0; nb < 8; nb++) {
        const int cg = n0 + (lane & 3) * 2 + nb * 8;
        float b0 = tb[cg], b1 = tb[cg + 1];
        rf[nb][0] = fmaxf(acc[nb][0] + b0, 0.f);
        rf[nb][1] = fmaxf(acc[nb][1] + b1, 0.f);
        rf[nb][2] = fmaxf(acc[nb][2] + b0, 0.f);
        rf[nb][3] = fmaxf(acc[nb][3] + b1, 0.f);
        acc[nb][0] = acc[nb][1] = acc[nb][2] = acc[nb][3] = 0.f;
    }
    __syncthreads();
    gemm_core_f32(sm, sb, tid, m0, n0, image, Wih, Wil, ID, acc);

    const int r0 = m0 + w * 16 + (lane >> 2);
#pragma unroll
    for (int nb = 0; nb < 8; nb++) {
        const int cg = n0 + (lane & 3) * 2 + nb * 8;
        float b0 = ib[cg], b1 = ib[cg + 1];
        const size_t i0 = (size_t)r0 * HH + cg;
        const size_t i1 = (size_t)(r0 + 8) * HH + cg;
        split_pair_store(ch, cl, i0,
                         rf[nb][0] + fmaxf(acc[nb][0] + b0, 0.f),
                         rf[nb][1] + fmaxf(acc[nb][1] + b1, 0.f));
        split_pair_store(ch, cl, i1,
                         rf[nb][2] + fmaxf(acc[nb][2] + b0, 0.f),
                         rf[nb][3] + fmaxf(acc[nb][3] + b1, 0.f));
    }
}

// general GEMM kernel (bf16-A), epilogues:
// EPI 6: h = acc + bias (fp32 out0); out1 = dinv^2*h + bias2 (aux=dinv)
// EPI 7: y-partials: red out0 += acc@cls_w (bias = cls_w)
template<int EPI>
__global__ void __launch_bounds__(256, 2) gemm_tc(
    const void* A0v, const void* A1v,
    const __nv_bfloat16* __restrict__ WTh, const __nv_bfloat16* __restrict__ WTl,
    const float* __restrict__ bias, const float* __restrict__ bias2,
    const float* __restrict__ aux,
    void* out0v, void* out1v, int K)
{
    extern __shared__ char sm[];
    const uint32_t sb = smem_u32(sm);
    const int tid = threadIdx.x, w = tid >> 5, lane = tid & 31;
    const int m0 = blockIdx.x * 128, n0 = blockIdx.y * 64;
    float acc[8][4] = {};
    gemm_core_bf16(sb, tid, m0, n0, A0v, A1v, WTh, WTl, K, acc, 3);

    const int r0 = m0 + w * 16 + (lane >> 2);
    if (EPI == 7) {
        const float* cw = bias;
        float p0[3] = {0.f, 0.f, 0.f}, p1[3] = {0.f, 0.f, 0.f};
#pragma unroll
        for (int nb = 0; nb < 8; nb++) {
            const int cg = n0 + (lane & 3) * 2 + nb * 8;
#pragma unroll
            for (int c = 0; c < 3; c++) {
                float w0 = __ldg(cw + cg * 3 + c), w1 = __ldg(cw + (cg + 1) * 3 + c);
                p0[c] = fmaf(acc[nb][0], w0, fmaf(acc[nb][1], w1, p0[c]));
                p1[c] = fmaf(acc[nb][2], w0, fmaf(acc[nb][3], w1, p1[c]));
            }
        }
#pragma unroll
        for (int c = 0; c < 3; c++) {
            p0[c] += __shfl_xor_sync(0xffffffffu, p0[c], 1);
            p0[c] += __shfl_xor_sync(0xffffffffu, p0[c], 2);
            p1[c] += __shfl_xor_sync(0xffffffffu, p1[c], 1);
            p1[c] += __shfl_xor_sync(0xffffffffu, p1[c], 2);
        }
        if ((lane & 3) == 0) {
            float* y = (float*)out0v;
#pragma unroll
            for (int c = 0; c < 3; c++) {
                redf(y + r0 * 4 + c, p0[c]);
                redf(y + (r0 + 8) * 4 + c, p1[c]);
            }
        }
        return;
    }
#pragma unroll
    for (int nb = 0; nb < 8; nb++) {
        const int cg = n0 + (lane & 3) * 2 + nb * 8;
        float b0 = bias[cg], b1 = bias[cg + 1];
        float v00 = acc[nb][0] + b0, v01 = acc[nb][1] + b1;
        float v10 = acc[nb][2] + b0, v11 = acc[nb][3] + b1;
        const size_t i0 = (size_t)r0 * HH + cg;
        const size_t i1 = (size_t)(r0 + 8) * HH + cg;
        *(float2*)((float*)out0v + i0) = make_float2(v00, v01);
        *(float2*)((float*)out0v + i1) = make_float2(v10, v11);
        float bb0 = bias2[cg], bb1 = bias2[cg + 1];
        float dv0 = aux[r0], dv1 = aux[r0 + 8];
        float c20 = dv0 * dv0, c21 = dv1 * dv1;
        *(float2*)((float*)out1v + i0) = make_float2(fmaf(c20, v00, bb0), fmaf(c20, v01, bb1));
        *(float2*)((float*)out1v + i1) = make_float2(fmaf(c21, v10, bb0), fmaf(c21, v11, bb1));
    }
}

// fused QKV GEMM: grid (32, 12); sel = blockIdx.y>>2.
// Q,K: 1-pass bf16 (errors wash out in softmax); V: 3-pass (+vsum reds).
__global__ void __launch_bounds__(256, 2) gemm_qkv(
    const __nv_bfloat16* __restrict__ A0, const __nv_bfloat16* __restrict__ A1,
    const __nv_bfloat16* __restrict__ WTbase, const __nv_bfloat16* __restrict__ WLbase,
    const float* __restrict__ bq, const float* __restrict__ bk,
    const float* __restrict__ bv,
    __nv_bfloat16* __restrict__ oq, __nv_bfloat16* __restrict__ ok,
    __nv_bfloat16* __restrict__ ov, float* __restrict__ vsum)
{
    extern __shared__ char sm[];
    const uint32_t sb = smem_u32(sm);
    const int tid = threadIdx.x, w = tid >> 5, lane = tid & 31;
    const int sel = blockIdx.y >> 2;
    const int m0 = blockIdx.x * 128, n0 = (blockIdx.y & 3) * 64;
    const __nv_bfloat16* WTh = WTbase + (size_t)sel * HH * HH;
    const __nv_bfloat16* WTl = WLbase + (size_t)sel * HH * HH;
    const float* bias = sel == 0 ? bq : (sel == 1 ? bk : bv);
    __nv_bfloat16* out = sel == 0 ? oq : (sel == 1 ? ok : ov);
    const int npass = (sel == 2) ? 3 : 1;

    float acc[8][4] = {};
    gemm_core_bf16(sb, tid, m0, n0, A0, A1, WTh, WTl, HH, acc, npass);

    const int r0 = m0 + w * 16 + (lane >> 2);
#pragma unroll
    for (int nb = 0; nb < 8; nb++) {
        const int cg = n0 + (lane & 3) * 2 + nb * 8;
        float b0 = bias[cg], b1 = bias[cg + 1];
        float v00 = acc[nb][0] + b0, v01 = acc[nb][1] + b1;
        float v10 = acc[nb][2] + b0, v11 = acc[nb][3] + b1;
        const size_t i0 = (size_t)r0 * HH + cg;
        const size_t i1 = (size_t)(r0 + 8) * HH + cg;
        ((uint32_t*)out)[i0 >> 1] = packbf2(v00, v01);
        ((uint32_t*)out)[i1 >> 1] = packbf2(v10, v11);
        if (sel == 2) {
            float s0 = v00 + v10, s1 = v01 + v11;
#pragma unroll
            for (int off = 4; off < 32; off <<= 1) {
                s0 += __shfl_xor_sync(0xffffffffu, s0, off);
                s1 += __shfl_xor_sync(0xffffffffu, s1, off);
            }
            if (lane < 4) {
                redf(vsum + cg, s0);
                redf(vsum + cg + 1, s1);
            }
        }
    }
}

// ============== HMMA flash attention: 128 q-rows x 1 head per CTA ============
#define SM_BUFSTRIDE 32768
#define SM_VOFF 16384
#define SM_Q 65536
#define SM_ATT_TOTAL 81920

__device__ __forceinline__ void load_kv_tile(
    uint32_t sb, int buf, int kt, int head,
    const __nv_bfloat16* kb, const __nv_bfloat16* vb, int tid)
{
    const char* kc = (const char*)kb;
    const char* vc = (const char*)vb;
#pragma unroll
    for (int j = 0; j < 8; j++) {
        int flat = tid + j * 256;
        int arr = flat >> 10;
        int row = (flat >> 3) & 127;
        int c = flat & 7;
        const char* src = (arr ? vc : kc) +
            (((size_t)(kt + row) * HH + head * HD) << 1) + c * 16;
        uint32_t dst = sb + buf * SM_BUFSTRIDE + arr * SM_VOFF +
                       swz128((uint32_t)(row * 128 + c * 16));
        cp16(dst, src);
    }
}

__global__ void __launch_bounds__(256, 1) attn_mma(
    const __nv_bfloat16* __restrict__ qb, const __nv_bfloat16* __restrict__ kb,
    const __nv_bfloat16* __restrict__ vb, const float* __restrict__ vsum,
    __nv_bfloat16* __restrict__ oh, __nv_bfloat16* __restrict__ ol)
{
    extern __shared__ char sm[];
    const uint32_t sb = smem_u32(sm);
    const int tid = threadIdx.x, w = tid >> 5, lane = tid & 31;
    const int q0 = blockIdx.x * 128, head = blockIdx.y;

    {
        const char* qc = (const char*)qb;
#pragma unroll
        for (int j = 0; j < 4; j++) {
            int flat = tid + j * 256;
            int row = flat >> 3, c = flat & 7;
            const char* src = qc + (((size_t)(q0 + row) * HH + head * HD) << 1) + c * 16;
            cp16(sb + SM_Q + swz128((uint32_t)(row * 128 + c * 16)), src);
        }
        load_kv_tile(sb, 0, 0, head, kb, vb, tid);
        cp_commit();
        cp_wait0();
        __syncthreads();
    }

    uint32_t qa[4][4];
    {
        const int rowa = w * 16 + (lane & 7) + ((lane >> 3) & 1) * 8;
        const int cb = ((lane >> 4) & 1) * 16;
#pragma unroll
        for (int kk = 0; kk < 4; kk++)
            ldsm4(qa[kk], sb + SM_Q + swz128((uint32_t)(rowa * 128 + kk * 32 + cb)));
    }

    float oacc[8][4] = {};
    float sumd0 = 0.f, sumd1 = 0.f;

    for (int t = 0; t < 32; t++) {
        const uint32_t kbase = sb + (t & 1) * SM_BUFSTRIDE;
        const uint32_t vbase = kbase + SM_VOFF;
        if (t + 1 < 32) {
            load_kv_tile(sb, (t + 1) & 1, (t + 1) * 128, head, kb, vb, tid);
            cp_commit();
        }
#pragma unroll 2
        for (int kk = 0; kk < 8; kk++) {
            float s[2][4] = {{0.f,0.f,0.f,0.f},{0.f,0.f,0.f,0.f}};
#pragma unroll
            for (int half = 0; half < 2; half++) {
                const int keyl = kk * 16 + half * 8 + (lane & 7);
#pragma unroll
                for (int kk2 = 0; kk2 < 2; kk2++) {
                    uint32_t b[4];
                    ldsm4(b, kbase + swz128((uint32_t)(keyl * 128 + kk2 * 64 +
                                                       ((lane >> 3) & 3) * 16)));
                    mma16816(s[half], qa[2*kk2][0], qa[2*kk2][1], qa[2*kk2][2],
                             qa[2*kk2][3], b[0], b[1]);
                    mma16816(s[half], qa[2*kk2+1][0], qa[2*kk2+1][1], qa[2*kk2+1][2],
                             qa[2*kk2+1][3], b[2], b[3]);
                }
            }
#pragma unroll
            for (int half = 0; half < 2; half++) {
#pragma unroll
                for (int j = 0; j < 4; j++) {
                    float x = s[half][j] * 0.125f;
                    float h = fmaf(x, 4.166666667e-2f, 0.166666667f);
                    h = fmaf(h, x, 0.5f);
                    h = fmaf(h, x, 1.0f);
                    float dlt = x * h;
                    s[half][j] = dlt;
                    if (j < 2) sumd0 += dlt; else sumd1 += dlt;
                }
            }
            uint32_t A0 = packbf2(s[0][0], s[0][1]);
            uint32_t A1 = packbf2(s[0][2], s[0][3]);
            uint32_t A2 = packbf2(s[1][0], s[1][1]);
            uint32_t A3 = packbf2(s[1][2], s[1][3]);
            const int keyl2 = kk * 16 + (lane & 7) + ((lane >> 3) & 1) * 8;
            const int cb2 = ((lane >> 4) & 1) * 16;
#pragma unroll
            for (int nb2 = 0; nb2 < 4; nb2++) {
                uint32_t b[4];
                ldsm4t(b, vbase + swz128((uint32_t)(keyl2 * 128 + nb2 * 32 + cb2)));
                mma16816(oacc[2*nb2],     A0, A1, A2, A3, b[0], b[1]);
                mma16816(oacc[2*nb2 + 1], A0, A1, A2, A3, b[2], b[3]);
            }
        }
        if (t + 1 < 32) { cp_wait0(); __syncthreads(); }
    }

    sumd0 += __shfl_xor_sync(0xffffffffu, sumd0, 1);
    sumd0 += __shfl_xor_sync(0xffffffffu, sumd0, 2);
    sumd1 += __shfl_xor_sync(0xffffffffu, sumd1, 1);
    sumd1 += __shfl_xor_sync(0xffffffffu, sumd1, 2);
    const float inv0 = 1.0f / (4096.0f + sumd0);
    const float inv1 = 1.0f / (4096.0f + sumd1);
    const int r0 = q0 + w * 16 + (lane >> 2);
    const int cbase = head * HD + (lane & 3) * 2;
#pragma unroll
    for (int nb = 0; nb < 8; nb++) {
        int d = cbase + nb * 8;
        float sv0 = vsum[d], sv1 = vsum[d + 1];
        split_pair_store(oh, ol, (size_t)r0 * HH + d,
                         (sv0 + oacc[nb][0]) * inv0, (sv1 + oacc[nb][1]) * inv0);
        split_pair_store(oh, ol, (size_t)(r0 + 8) * HH + d,
                         (sv0 + oacc[nb][2]) * inv1, (sv1 + oacc[nb][3]) * inv1);
    }
}

// ---------------- launch -----------------------------------------------------
extern "C" void kernel_launch(void* const* d_in, const int* in_sizes, int n_in,
                              void* d_out, int out_size)
{
    const float* text    = (const float*)d_in[0];
    const float* image   = (const float*)d_in[1];
    const int*   ei      = (const int*)d_in[2];
    const float* text_w  = (const float*)d_in[3];
    const float* text_b  = (const float*)d_in[4];
    const float* image_w = (const float*)d_in[5];
    const float* image_b = (const float*)d_in[6];
    const float* wq = (const float*)d_in[7];  const float* bq = (const float*)d_in[8];
    const float* wk = (const float*)d_in[9];  const float* bk = (const float*)d_in[10];
    const float* wv = (const float*)d_in[11]; const float* bv = (const float*)d_in[12];
    const float* wo = (const float*)d_in[13]; const float* bo = (const float*)d_in[14];
    const float* gcn1_w = (const float*)d_in[15]; const float* gcn1_b = (const float*)d_in[16];
    const float* gcn2_w = (const float*)d_in[17]; const float* gcn2_b = (const float*)d_in[18];
    const float* cls_w  = (const float*)d_in[19]; const float* cls_b  = (const float*)d_in[20];
    float* out = (float*)d_out;

    float *hb, *g1, *yb, *dinv, *vsum, *bg;
    __nv_bfloat16 *ch, *cl, *qbb, *kbb, *vbb, *obh, *obl, *g1h, *g1l, *wth, *wtl;
    cudaGetSymbolAddress((void**)&hb, g_h);
    cudaGetSymbolAddress((void**)&g1, g_g1);
    cudaGetSymbolAddress((void**)&yb, g_y);
    cudaGetSymbolAddress((void**)&dinv, g_dinv);
    cudaGetSymbolAddress((void**)&vsum, g_vsum);
    cudaGetSymbolAddress((void**)&bg, g_bg);
    cudaGetSymbolAddress((void**)&ch, g_ch);
    cudaGetSymbolAddress((void**)&cl, g_cl);
    cudaGetSymbolAddress((void**)&qbb, g_qb);
    cudaGetSymbolAddress((void**)&kbb, g_kb);
    cudaGetSymbolAddress((void**)&vbb, g_vb);
    cudaGetSymbolAddress((void**)&obh, g_obh);
    cudaGetSymbolAddress((void**)&obl, g_obl);
    cudaGetSymbolAddress((void**)&g1h, g_g1h);
    cudaGetSymbolAddress((void**)&g1l, g_g1l);
    cudaGetSymbolAddress((void**)&wth, g_wth);
    cudaGetSymbolAddress((void**)&wtl, g_wtl);

    // 1: weight prep + hist + WG=Wo@G1 + bG + zero(vsum, y)
    k_wprep_all<<<dim3(24, 8, 8), dim3(32, 32)>>>(
        text_w, image_w, wq, wk, wv, wo, gcn1_w, gcn2_w, bo, ei + EE);

    // 2: scan (start/cursor/dinv, re-zero cnt, bconst)
    k_scan<<<1, 1024>>>(gcn2_b, cls_w);

    // 3: fused text+image projection + scatter plane
    {
        static bool done = false;
        if (!done) {
            cudaFuncSetAttribute(gemm_fuse2,
                                 cudaFuncAttributeMaxDynamicSharedMemorySize, GEMM_SMEM);
            done = true;
        }
        gemm_fuse2<<<dim3(32, 5), 256, GEMM_SMEM>>>(
            text, image, wth + WOFF_TEXT, wtl + WOFF_TEXT,
            wth + WOFF_IMAGE, wtl + WOFF_IMAGE, text_b, image_b, ch, cl,
            ei, ei + EE);
    }

    // 4: fused QKV (Q,K 1-pass; V 3-pass +vsum reds)
    {
        static bool done = false;
        if (!done) {
            cudaFuncSetAttribute(gemm_qkv,
                                 cudaFuncAttributeMaxDynamicSharedMemorySize, GEMM_SMEM);
            done = true;
        }
        gemm_qkv<<<dim3(32, 12), 256, GEMM_SMEM>>>(
            ch, cl, wth + WOFF_WQ, wtl + WOFF_WQ, bq, bk, bv, qbb, kbb, vbb, vsum);
    }

    // 5: attention
    cudaFuncSetAttribute(attn_mma, cudaFuncAttributeMaxDynamicSharedMemorySize,
                         SM_ATT_TOTAL);
    attn_mma<<<dim3(NN / 128, NHD), 256, SM_ATT_TOTAL>>>(qbb, kbb, vbb, vsum, obh, obl);

    // 6: GCN1 GEMM with composed weights (h = ob@WG + bG; init = dinv^2*h + b1)
    {
        static bool done = false;
        if (!done) {
            cudaFuncSetAttribute(gemm_tc<6>,
                                 cudaFuncAttributeMaxDynamicSharedMemorySize, GEMM_SMEM);
            done = true;
        }
        gemm_tc<6><<<dim3(32, 4), 256, GEMM_SMEM>>>(
            obh, obl, wth + WOFF_G1, wtl + WOFF_G1, bg, gcn1_b, dinv, hb, g1, HH);
    }

    // 7: GCN1 aggregation (gather) + relu + split
    k_agg1<<<NN * 32 / 256, 256>>>(hb, g1, g1h, g1l);

    // 8: GCN2 GEMM in classifier space (red into y)
    {
        static bool done = false;
        if (!done) {
            cudaFuncSetAttribute(gemm_tc<7>,
                                 cudaFuncAttributeMaxDynamicSharedMemorySize, GEMM_SMEM);
            done = true;
        }
        gemm_tc<7><<<dim3(32, 4), 256, GEMM_SMEM>>>(
            g1h, g1l, wth + WOFF_G2, wtl + WOFF_G2, cls_w, nullptr, nullptr,
            yb, nullptr, HH);
    }

    // 9: GCN2 aggregation on y + bias
    k_agg2y<<<NN * 32 / 256, 256>>>(yb, cls_b, out);
}

// round 12
// speedup vs baseline: 1.1322x; 1.1001x over previous
#include <cuda_runtime.h>
#include <cuda_bf16.h>
#include <cstdint>
#include <cstddef>

#define NN 4096
#define TD 768
#define ID 512
#define HH 256
#define NHD 4
#define HD 64
#define EE 131072
#define NC 3

// ---------------- scratch (static device globals; no allocation) -------------
__device__ float g_h[NN * HH];      // fp32 transformed features (GCN1 h)
__device__ float g_g1[NN * HH];     // GCN1 init (self-loop term)
__device__ float g_y[NN * 4];       // GCN2 h @ cls_w (padded to 4)
__device__ float g_dinv[NN];
__device__ float g_vsum[HH];
__device__ float g_bconst[3];
__device__ float g_bg[HH];          // bo @ G1
__device__ int   g_cnt[NN];         // zero at module load; re-zeroed by k_scan
__device__ int   g_start[NN + 1];
__device__ int   g_cursor[NN];
__device__ int   g_sorted[EE];
// bf16 activations (hi only — per-row rounding error is incoherent, dilutes)
__device__ __nv_bfloat16 g_ch[NN * HH];
__device__ __nv_bfloat16 g_qb[NN * HH];
__device__ __nv_bfloat16 g_kb[NN * HH];
__device__ __nv_bfloat16 g_vb[NN * HH];
__device__ __nv_bfloat16 g_obh[NN * HH];
__device__ __nv_bfloat16 g_g1h[NN * HH];
// transposed+split weights [n][K] (hi + lo: W-lo carries the coherent error)
#define WOFF_TEXT  0
#define WOFF_IMAGE 196608
#define WOFF_WQ    327680
#define WOFF_WK    393216
#define WOFF_WV    458752
#define WOFF_G1    524288   /* holds WG = Wo@G1, composed */
#define WOFF_G2    589824
#define WTOT       655360
__device__ __nv_bfloat16 g_wth[WTOT], g_wtl[WTOT];

// =================== helpers =================================================
__device__ __forceinline__ uint32_t smem_u32(const void* p) {
    uint32_t a;
    asm("{ .reg .u64 t; cvta.to.shared.u64 t, %1; cvt.u32.u64 %0, t; }"
        : "=r"(a) : "l"(p));
    return a;
}
__device__ __forceinline__ uint32_t swz128(uint32_t o) { return o ^ ((o >> 3) & 0x70); }
__device__ __forceinline__ uint32_t swz64(uint32_t o)  { return o ^ ((o >> 3) & 0x30); }
__device__ __forceinline__ uint32_t packbf2(float x0, float x1) {
    uint32_t r;  // lo = x0, hi = x1
    asm("cvt.rn.satfinite.bf16x2.f32 %0, %1, %2;" : "=r"(r) : "f"(x1), "f"(x0));
    return r;
}
__device__ __forceinline__ void mma16816(float* c,
    uint32_t a0, uint32_t a1, uint32_t a2, uint32_t a3, uint32_t b0, uint32_t b1) {
    asm volatile("mma.sync.aligned.m16n8k16.row.col.f32.bf16.bf16.f32 "
        "{%0,%1,%2,%3}, {%4,%5,%6,%7}, {%8,%9}, {%0,%1,%2,%3};"
        : "+f"(c[0]), "+f"(c[1]), "+f"(c[2]), "+f"(c[3])
        : "r"(a0), "r"(a1), "r"(a2), "r"(a3), "r"(b0), "r"(b1));
}
__device__ __forceinline__ void ldsm4(uint32_t* r, uint32_t a) {
    asm volatile("ldmatrix.sync.aligned.m8n8.x4.shared.b16 {%0,%1,%2,%3}, [%4];"
        : "=r"(r[0]), "=r"(r[1]), "=r"(r[2]), "=r"(r[3]) : "r"(a));
}
__device__ __forceinline__ void ldsm4t(uint32_t* r, uint32_t a) {
    asm volatile("ldmatrix.sync.aligned.m8n8.x4.trans.shared.b16 {%0,%1,%2,%3}, [%4];"
        : "=r"(r[0]), "=r"(r[1]), "=r"(r[2]), "=r"(r[3]) : "r"(a));
}
__device__ __forceinline__ void cp16(uint32_t dst, const void* src) {
    asm volatile("cp.async.cg.shared.global [%0], [%1], 16;" :: "r"(dst), "l"(src) : "memory");
}
__device__ __forceinline__ void cp_commit() {
    asm volatile("cp.async.commit_group;" ::: "memory");
}
__device__ __forceinline__ void cp_wait0() {
    asm volatile("cp.async.wait_group 0;" ::: "memory");
}
__device__ __forceinline__ void redf(float* p, float v) {
    asm volatile("red.global.add.f32 [%0], %1;" :: "l"(p), "f"(v) : "memory");
}

// ====== single-launch prep: weights + hist + WG compose + bG + zeroing =======
__global__ void k_wprep_all(
    const float* w0, const float* w1, const float* w2, const float* w3,
    const float* w4, const float* wo, const float* g1w, const float* w7,
    const float* bo, const int* __restrict__ edst)
{
    const int z = blockIdx.z;
    const int tx = threadIdx.x, ty = threadIdx.y;
    if (z == 5) {
        int flat = (blockIdx.y * 24 + blockIdx.x) * 1024 + ty * 32 + tx;
        if (flat < EE) atomicAdd(&g_cnt[edst[flat]], 1);
        return;
    }
    if (z == 6) {
        if (blockIdx.x < 8) {
            // WG^T[n][k] = sum_j Wo[k][j] * G1[j][n]
            int k0 = blockIdx.x * 32, n0 = blockIdx.y * 32;
            __shared__ float sW[32][33], sG[32][33];
            float acc = 0.f;
            for (int j0 = 0; j0 < HH; j0 += 32) {
                sW[ty][tx] = wo[(size_t)(k0 + ty) * HH + j0 + tx];
                sG[ty][tx] = g1w[(size_t)(j0 + ty) * HH + n0 + tx];
                __syncthreads();
#pragma unroll
                for (int jj = 0; jj < 32; jj++)
                    acc = fmaf(sW[tx][jj], sG[jj][ty], acc);
                __syncthreads();
            }
            __nv_bfloat16 h = __float2bfloat16(acc);
            __nv_bfloat16 l = __float2bfloat16(acc - __bfloat162float(h));
            size_t idx = (size_t)WOFF_G1 + (size_t)(n0 + ty) * HH + k0 + tx;
            g_wth[idx] = h;
            g_wtl[idx] = l;
        } else if (blockIdx.x == 8) {
            if (blockIdx.y == 0) {
                int t = ty * 32 + tx;
                if (t < HH) {
                    float s = 0.f;
                    for (int j = 0; j < HH; j++)
                        s = fmaf(bo[j], g1w[(size_t)j * HH + t], s);
                    g_bg[t] = s;
                }
            }
        } else if (blockIdx.x == 9) {
            int flat = blockIdx.y * 1024 + ty * 32 + tx;
            for (int i = flat; i < NN * 4 + HH; i += 8192) {
                if (i < NN * 4) g_y[i] = 0.f;
                else g_vsum[i - NN * 4] = 0.f;
            }
        }
        return;
    }
    const float* W; int K, off;
    switch (z) {
        case 0: W = w0; K = TD; off = WOFF_TEXT; break;
        case 1: W = w1; K = ID; off = WOFF_IMAGE; break;
        case 2: W = w2; K = HH; off = WOFF_WQ; break;
        case 3: W = w3; K = HH; off = WOFF_WK; break;
        case 4: W = w4; K = HH; off = WOFF_WV; break;
        default: W = w7; K = HH; off = WOFF_G2; break;
    }
    int k0 = blockIdx.x * 32;
    if (k0 >= K) return;
    int n0 = blockIdx.y * 32;
    __shared__ float t[32][33];
    t[ty][tx] = W[(size_t)(k0 + ty) * HH + n0 + tx];
    __syncthreads();
    float v = t[tx][ty];
    __nv_bfloat16 h = __float2bfloat16(v);
    __nv_bfloat16 l = __float2bfloat16(v - __bfloat162float(h));
    size_t idx = (size_t)off + (size_t)(n0 + ty) * K + k0 + tx;
    g_wth[idx] = h;
    g_wtl[idx] = l;
}

// 1 CTA, 1024 threads: prefix-scan cnt -> start/cursor, dinv; re-zero cnt;
// bconst = gcn2_b @ cls_w.
__global__ void k_scan(const float* __restrict__ b2, const float* __restrict__ cw)
{
    __shared__ int wsum[32];
    const int t = threadIdx.x, lane = t & 31, wid = t >> 5;
    if (t < 3) {
        float s = 0.f;
        for (int j = 0; j < HH; j++) s = fmaf(b2[j], cw[j * 3 + t], s);
        g_bconst[t] = s;
    }
    const int base = t * 4;
    int c0 = g_cnt[base], c1 = g_cnt[base + 1], c2 = g_cnt[base + 2], c3 = g_cnt[base + 3];
    int s = c0 + c1 + c2 + c3;
    int v = s;
#pragma unroll
    for (int off = 1; off < 32; off <<= 1) {
        int u = __shfl_up_sync(0xffffffffu, v, off);
        if (lane >= off) v += u;
    }
    if (lane == 31) wsum[wid] = v;
    __syncthreads();
    if (wid == 0) {
        int x = wsum[lane];
#pragma unroll
        for (int off = 1; off < 32; off <<= 1) {
            int u = __shfl_up_sync(0xffffffffu, x, off);
            if (lane >= off) x += u;
        }
        wsum[lane] = x;
    }
    __syncthreads();
    int excl = v - s + (wid > 0 ? wsum[wid - 1] : 0);
    int e0 = excl, e1 = e0 + c0, e2 = e1 + c1, e3 = e2 + c2;
    g_start[base] = e0;  g_cursor[base] = e0;
    g_start[base + 1] = e1; g_cursor[base + 1] = e1;
    g_start[base + 2] = e2; g_cursor[base + 2] = e2;
    g_start[base + 3] = e3; g_cursor[base + 3] = e3;
    g_dinv[base]     = rsqrtf((float)(c0 + 1));
    g_dinv[base + 1] = rsqrtf((float)(c1 + 1));
    g_dinv[base + 2] = rsqrtf((float)(c2 + 1));
    g_dinv[base + 3] = rsqrtf((float)(c3 + 1));
    g_cnt[base] = 0; g_cnt[base + 1] = 0; g_cnt[base + 2] = 0; g_cnt[base + 3] = 0;
    if (t == 1023) g_start[NN] = e3 + c3;
}

// ====== GCN layer-1 aggregation: warp per dst, gather ========================
__global__ void __launch_bounds__(256) k_agg1(
    const float* __restrict__ h, const float* __restrict__ init,
    __nv_bfloat16* __restrict__ oh)
{
    const int dstn = (blockIdx.x * 256 + threadIdx.x) >> 5;
    const int lane = threadIdx.x & 31;
    if (dstn >= NN) return;
    const int beg = g_start[dstn], end = g_start[dstn + 1];
    const float dd = g_dinv[dstn];

    float acc[8];
    {
        const float4* ir = (const float4*)(init + (size_t)dstn * HH) + lane * 2;
        float4 a = ir[0], b = ir[1];
        acc[0] = a.x; acc[1] = a.y; acc[2] = a.z; acc[3] = a.w;
        acc[4] = b.x; acc[5] = b.y; acc[6] = b.z; acc[7] = b.w;
    }
    for (int e = beg; e < end; e += 32) {
        int n = end - e; if (n > 32) n = 32;
        int sidx = 0; float dv = 0.f;
        if (lane < n) {
            sidx = __ldg(&g_sorted[e + lane]);
            dv = __ldg(&g_dinv[sidx]);
        }
#pragma unroll 4
        for (int j = 0; j < n; j++) {
            int s = __shfl_sync(0xffffffffu, sidx, j);
            float cf = __shfl_sync(0xffffffffu, dv, j) * dd;
            const float4* hr = (const float4*)(h + ((size_t)s << 8)) + (lane << 1);
            float4 a = __ldg(hr), b = __ldg(hr + 1);
            acc[0] = fmaf(cf, a.x, acc[0]); acc[1] = fmaf(cf, a.y, acc[1]);
            acc[2] = fmaf(cf, a.z, acc[2]); acc[3] = fmaf(cf, a.w, acc[3]);
            acc[4] = fmaf(cf, b.x, acc[4]); acc[5] = fmaf(cf, b.y, acc[5]);
            acc[6] = fmaf(cf, b.z, acc[6]); acc[7] = fmaf(cf, b.w, acc[7]);
        }
    }
#pragma unroll
    for (int p = 0; p < 4; p++) {
        float x = fmaxf(acc[2 * p], 0.f), y = fmaxf(acc[2 * p + 1], 0.f);
        ((uint32_t*)oh)[((size_t)dstn * HH + lane * 8 + 2 * p) >> 1] = packbf2(x, y);
    }
}

// ====== GCN layer-2 aggregation on y[4] (classifier space) ===================
__global__ void __launch_bounds__(256) k_agg2y(
    const float* __restrict__ y, const float* __restrict__ cls_b,
    float* __restrict__ out)
{
    const int d = (blockIdx.x * 256 + threadIdx.x) >> 5;
    const int lane = threadIdx.x & 31;
    if (d >= NN) return;
    const int beg = g_start[d], end = g_start[d + 1];
    float a0 = 0.f, a1 = 0.f, a2 = 0.f;
    for (int e = beg + lane; e < end; e += 32) {
        int s = __ldg(&g_sorted[e]);
        float dv = __ldg(&g_dinv[s]);
        float4 yv = *(const float4*)(y + s * 4);
        a0 = fmaf(dv, yv.x, a0);
        a1 = fmaf(dv, yv.y, a1);
        a2 = fmaf(dv, yv.z, a2);
    }
#pragma unroll
    for (int off = 16; off > 0; off >>= 1) {
        a0 += __shfl_xor_sync(0xffffffffu, a0, off);
        a1 += __shfl_xor_sync(0xffffffffu, a1, off);
        a2 += __shfl_xor_sync(0xffffffffu, a2, off);
    }
    if (lane == 0) {
        float dd = g_dinv[d];
        float4 yd = *(const float4*)(y + d * 4);
        out[d * 3 + 0] = fmaf(dd, fmaf(dd, yd.x, a0), g_bconst[0] + cls_b[0]);
        out[d * 3 + 1] = fmaf(dd, fmaf(dd, yd.y, a1), g_bconst[1] + cls_b[1]);
        out[d * 3 + 2] = fmaf(dd, fmaf(dd, yd.z, a2), g_bconst[2] + cls_b[2]);
    }
}

// =============== HMMA GEMM cores =============================================
#define GST 24576
#define GS_AL 8192
#define GS_W  16384
#define GS_WL 20480
#define GEMM_SMEM 49152

// NPASS: 2 = AhWh + AhWl (coherent-accurate), 1 = AhWh only.
template<int NPASS>
__device__ __forceinline__ void gemm_core_bf16(
    uint32_t sb, int tid, int m0, int n0,
    const __nv_bfloat16* A0,
    const __nv_bfloat16* WTh, const __nv_bfloat16* WTl,
    int K, float acc[8][4])
{
    const int w = tid >> 5, lane = tid & 31;
    const int rowa = w * 16 + (lane & 7) + ((lane >> 3) & 1) * 8;
    const int acb  = ((lane >> 4) & 1) * 16;
    const int nrow = lane & 7;
    const int bcb  = ((lane >> 3) & 3) * 16;
    const int nch = K >> 5;

    auto load_w = [&](int kc, int st) {
        int k0 = kc << 5;
        uint32_t base = sb + st * GST + GS_W;
#pragma unroll
        for (int j = 0; j < NPASS; j++) {
            int flat = tid + j * 256;
            int part = flat >> 8, r = (flat >> 2) & 63, c = flat & 3;
            const char* src = (const char*)(part ? WTl : WTh) +
                              (((size_t)(n0 + r) * K + k0) << 1) + c * 16;
            cp16(base + part * 4096 + swz64((uint32_t)(r * 64 + c * 16)), src);
        }
    };
    auto load_a = [&](int kc, int st) {
        int k0 = kc << 5;
        uint32_t base = sb + st * GST;
#pragma unroll
        for (int j = 0; j < 2; j++) {
            int flat = tid + j * 256;
            int r = flat >> 2, c = flat & 3;
            const char* src = (const char*)A0 +
                              (((size_t)(m0 + r) * K + k0) << 1) + c * 16;
            cp16(base + swz64((uint32_t)(r * 64 + c * 16)), src);
        }
    };
    auto compute = [&](int st) {
        uint32_t base = sb + st * GST;
        uint32_t ah[2][4];
#pragma unroll
        for (int kk2 = 0; kk2 < 2; kk2++)
            ldsm4(ah[kk2], base + swz64((uint32_t)(rowa * 64 + kk2 * 32 + acb)));
#pragma unroll
        for (int nb = 0; nb < 8; nb++) {
            uint32_t bo = swz64((uint32_t)((nb * 8 + nrow) * 64 + bcb));
            uint32_t bh[4];
            ldsm4(bh, base + GS_W + bo);
            mma16816(acc[nb], ah[0][0], ah[0][1], ah[0][2], ah[0][3], bh[0], bh[1]);
            mma16816(acc[nb], ah[1][0], ah[1][1], ah[1][2], ah[1][3], bh[2], bh[3]);
            if (NPASS == 2) {
                uint32_t bl[4];
                ldsm4(bl, base + GS_WL + bo);
                mma16816(acc[nb], ah[0][0], ah[0][1], ah[0][2], ah[0][3], bl[0], bl[1]);
                mma16816(acc[nb], ah[1][0], ah[1][1], ah[1][2], ah[1][3], bl[2], bl[3]);
            }
        }
    };

    load_a(0, 0); load_w(0, 0); cp_commit(); cp_wait0();
    __syncthreads();
    for (int kc = 0; kc < nch; kc++) {
        if (kc + 1 < nch) {
            load_a(kc + 1, (kc + 1) & 1);
            load_w(kc + 1, (kc + 1) & 1);
            cp_commit();
        }
        compute(kc & 1);
        if (kc + 1 < nch) { cp_wait0(); __syncthreads(); }
    }
}

// fp32-A core: 2-pass (AhWh + AhWl); A-lo never materialized.
__device__ __forceinline__ void gemm_core_f32(
    char* smc, uint32_t sb, int tid, int m0, int n0,
    const float* A, const __nv_bfloat16* WTh, const __nv_bfloat16* WTl,
    int K, float acc[8][4])
{
    const int w = tid >> 5, lane = tid & 31;
    const int rowa = w * 16 + (lane & 7) + ((lane >> 3) & 1) * 8;
    const int acb  = ((lane >> 4) & 1) * 16;
    const int nrow = lane & 7;
    const int bcb  = ((lane >> 3) & 3) * 16;
    const int nch = K >> 5;
    float4 ar[4];

    auto load_w = [&](int kc, int st) {
        int k0 = kc << 5;
        uint32_t base = sb + st * GST + GS_W;
#pragma unroll
        for (int j = 0; j < 2; j++) {
            int flat = tid + j * 256;
            int part = flat >> 8, r = (flat >> 2) & 63, c = flat & 3;
            const char* src = (const char*)(part ? WTl : WTh) +
                              (((size_t)(n0 + r) * K + k0) << 1) + c * 16;
            cp16(base + part * 4096 + swz64((uint32_t)(r * 64 + c * 16)), src);
        }
    };
    auto ldg_a = [&](int kc) {
        int k0 = kc << 5;
#pragma unroll
        for (int j = 0; j < 4; j++) {
            int flat = tid + j * 256;
            int r = flat >> 3, c = flat & 7;
            ar[j] = *(const float4*)(A + (size_t)(m0 + r) * K + k0 + c * 4);
        }
    };
    auto sts_a = [&](int st) {
        uint32_t off0 = st * GST;
#pragma unroll
        for (int j = 0; j < 4; j++) {
            int flat = tid + j * 256;
            int r = flat >> 3, c = flat & 7;
            uint32_t off = swz64((uint32_t)(r * 64 + c * 8));
            uint32_t h0 = packbf2(ar[j].x, ar[j].y);
            uint32_t h1 = packbf2(ar[j].z, ar[j].w);
            *(uint2*)(smc + off0 + off) = make_uint2(h0, h1);
        }
    };
    auto compute = [&](int st) {
        uint32_t base = sb + st * GST;
        uint32_t ah[2][4];
#pragma unroll
        for (int kk2 = 0; kk2 < 2; kk2++)
            ldsm4(ah[kk2], base + swz64((uint32_t)(rowa * 64 + kk2 * 32 + acb)));
#pragma unroll
        for (int nb = 0; nb < 8; nb++) {
            uint32_t bo = swz64((uint32_t)((nb * 8 + nrow) * 64 + bcb));
            uint32_t bh[4], bl[4];
            ldsm4(bh, base + GS_W + bo);
            ldsm4(bl, base + GS_WL + bo);
            mma16816(acc[nb], ah[0][0], ah[0][1], ah[0][2], ah[0][3], bh[0], bh[1]);
            mma16816(acc[nb], ah[1][0], ah[1][1], ah[1][2], ah[1][3], bh[2], bh[3]);
            mma16816(acc[nb], ah[0][0], ah[0][1], ah[0][2], ah[0][3], bl[0], bl[1]);
            mma16816(acc[nb], ah[1][0], ah[1][1], ah[1][2], ah[1][3], bl[2], bl[3]);
        }
    };

    ldg_a(0); load_w(0, 0); cp_commit(); sts_a(0); cp_wait0();
    __syncthreads();
    for (int kc = 0; kc < nch; kc++) {
        if (kc + 1 < nch) {
            ldg_a(kc + 1);
            load_w(kc + 1, (kc + 1) & 1);
            cp_commit();
        }
        compute(kc & 1);
        if (kc + 1 < nch) {
            sts_a((kc + 1) & 1);
            cp_wait0();
            __syncthreads();
        }
    }
}

// fused text+image projection + edge-scatter plane (blockIdx.y == 4)
__global__ void __launch_bounds__(256, 2) gemm_fuse2(
    const float* __restrict__ text, const float* __restrict__ image,
    const __nv_bfloat16* __restrict__ Wth, const __nv_bfloat16* __restrict__ Wtl,
    const __nv_bfloat16* __restrict__ Wih, const __nv_bfloat16* __restrict__ Wil,
    const float* __restrict__ tb, const float* __restrict__ ib,
    __nv_bfloat16* __restrict__ ch,
    const int* __restrict__ esrc, const int* __restrict__ edst)
{
    if (blockIdx.y == 4) {
        int base = (blockIdx.x * 256 + threadIdx.x) * 16;
        int4 d4[4], s4[4];
#pragma unroll
        for (int i = 0; i < 4; i++) {
            d4[i] = *(const int4*)(edst + base + i * 4);
            s4[i] = *(const int4*)(esrc + base + i * 4);
        }
#pragma unroll
        for (int i = 0; i < 4; i++) {
            const int dd[4] = {d4[i].x, d4[i].y, d4[i].z, d4[i].w};
            const int ss[4] = {s4[i].x, s4[i].y, s4[i].z, s4[i].w};
#pragma unroll
            for (int j = 0; j < 4; j++) {
                int pos = atomicAdd(&g_cursor[dd[j]], 1);
                g_sorted[pos] = ss[j];
            }
        }
        return;
    }
    extern __shared__ char sm[];
    const uint32_t sb = smem_u32(sm);
    const int tid = threadIdx.x, w = tid >> 5, lane = tid & 31;
    const int m0 = blockIdx.x * 128, n0 = blockIdx.y * 64;

    float acc[8][4] = {};
    gemm_core_f32(sm, sb, tid, m0, n0, text, Wth, Wtl, TD, acc);
    float rf[8][4];
#pragma unroll
    for (int nb = 0; nb < 8; nb++) {
        const int cg = n0 + (lane & 3) * 2 + nb * 8;
        float b0 = tb[cg], b1 = tb[cg + 1];
        rf[nb][0] = fmaxf(acc[nb][0] + b0, 0.f);
        rf[nb][1] = fmaxf(acc[nb][1] + b1, 0.f);
        rf[nb][2] = fmaxf(acc[nb][2] + b0, 0.f);
        rf[nb][3] = fmaxf(acc[nb][3] + b1, 0.f);
        acc[nb][0] = acc[nb][1] = acc[nb][2] = acc[nb][3] = 0.f;
    }
    __syncthreads();
    gemm_core_f32(sm, sb, tid, m0, n0, image, Wih, Wil, ID, acc);

    const int r0 = m0 + w * 16 + (lane >> 2);
#pragma unroll
    for (int nb = 0; nb < 8; nb++) {
        const int cg = n0 + (lane & 3) * 2 + nb * 8;
        float b0 = ib[cg], b1 = ib[cg + 1];
        const size_t i0 = (size_t)r0 * HH + cg;
        const size_t i1 = (size_t)(r0 + 8) * HH + cg;
        ((uint32_t*)ch)[i0 >> 1] = packbf2(rf[nb][0] + fmaxf(acc[nb][0] + b0, 0.f),
                                           rf[nb][1] + fmaxf(acc[nb][1] + b1, 0.f));
        ((uint32_t*)ch)[i1 >> 1] = packbf2(rf[nb][2] + fmaxf(acc[nb][2] + b0, 0.f),
                                           rf[nb][3] + fmaxf(acc[nb][3] + b1, 0.f));
    }
}

// general GEMM kernel (bf16-A hi, 2-pass), epilogues:
// EPI 6: h = acc + bias (fp32 out0); out1 = dinv^2*h + bias2 (aux=dinv)
// EPI 7: y-partials: red out0 += acc@cls_w (bias = cls_w)
template<int EPI>
__global__ void __launch_bounds__(256, 2) gemm_tc(
    const __nv_bfloat16* __restrict__ A0,
    const __nv_bfloat16* __restrict__ WTh, const __nv_bfloat16* __restrict__ WTl,
    const float* __restrict__ bias, const float* __restrict__ bias2,
    const float* __restrict__ aux,
    void* out0v, void* out1v, int K)
{
    extern __shared__ char sm[];
    const uint32_t sb = smem_u32(sm);
    const int tid = threadIdx.x, w = tid >> 5, lane = tid & 31;
    const int m0 = blockIdx.x * 128, n0 = blockIdx.y * 64;
    float acc[8][4] = {};
    gemm_core_bf16<2>(sb, tid, m0, n0, A0, WTh, WTl, K, acc);

    const int r0 = m0 + w * 16 + (lane >> 2);
    if (EPI == 7) {
        const float* cw = bias;
        float p0[3] = {0.f, 0.f, 0.f}, p1[3] = {0.f, 0.f, 0.f};
#pragma unroll
        for (int nb = 0; nb < 8; nb++) {
            const int cg = n0 + (lane & 3) * 2 + nb * 8;
#pragma unroll
            for (int c = 0; c < 3; c++) {
                float w0 = __ldg(cw + cg * 3 + c), w1 = __ldg(cw + (cg + 1) * 3 + c);
                p0[c] = fmaf(acc[nb][0], w0, fmaf(acc[nb][1], w1, p0[c]));
                p1[c] = fmaf(acc[nb][2], w0, fmaf(acc[nb][3], w1, p1[c]));
            }
        }
#pragma unroll
        for (int c = 0; c < 3; c++) {
            p0[c] += __shfl_xor_sync(0xffffffffu, p0[c], 1);
            p0[c] += __shfl_xor_sync(0xffffffffu, p0[c], 2);
            p1[c] += __shfl_xor_sync(0xffffffffu, p1[c], 1);
            p1[c] += __shfl_xor_sync(0xffffffffu, p1[c], 2);
        }
        if ((lane & 3) == 0) {
            float* y = (float*)out0v;
#pragma unroll
            for (int c = 0; c < 3; c++) {
                redf(y + r0 * 4 + c, p0[c]);
                redf(y + (r0 + 8) * 4 + c, p1[c]);
            }
        }
        return;
    }
#pragma unroll
    for (int nb = 0; nb < 8; nb++) {
        const int cg = n0 + (lane & 3) * 2 + nb * 8;
        float b0 = bias[cg], b1 = bias[cg + 1];
        float v00 = acc[nb][0] + b0, v01 = acc[nb][1] + b1;
        float v10 = acc[nb][2] + b0, v11 = acc[nb][3] + b1;
        const size_t i0 = (size_t)r0 * HH + cg;
        const size_t i1 = (size_t)(r0 + 8) * HH + cg;
        *(float2*)((float*)out0v + i0) = make_float2(v00, v01);
        *(float2*)((float*)out0v + i1) = make_float2(v10, v11);
        float bb0 = bias2[cg], bb1 = bias2[cg + 1];
        float dv0 = aux[r0], dv1 = aux[r0 + 8];
        float c20 = dv0 * dv0, c21 = dv1 * dv1;
        *(float2*)((float*)out1v + i0) = make_float2(fmaf(c20, v00, bb0), fmaf(c20, v01, bb1));
        *(float2*)((float*)out1v + i1) = make_float2(fmaf(c21, v10, bb0), fmaf(c21, v11, bb1));
    }
}

// fused QKV GEMM: grid (32, 12); sel = blockIdx.y>>2.
// Q,K: 1-pass; V: 2-pass (W-lo only) + vsum reds.
__global__ void __launch_bounds__(256, 2) gemm_qkv(
    const __nv_bfloat16* __restrict__ A0,
    const __nv_bfloat16* __restrict__ WTbase, const __nv_bfloat16* __restrict__ WLbase,
    const float* __restrict__ bq, const float* __restrict__ bk,
    const float* __restrict__ bv,
    __nv_bfloat16* __restrict__ oq, __nv_bfloat16* __restrict__ ok,
    __nv_bfloat16* __restrict__ ov, float* __restrict__ vsum)
{
    extern __shared__ char sm[];
    const uint32_t sb = smem_u32(sm);
    const int tid = threadIdx.x, w = tid >> 5, lane = tid & 31;
    const int sel = blockIdx.y >> 2;
    const int m0 = blockIdx.x * 128, n0 = (blockIdx.y & 3) * 64;
    const __nv_bfloat16* WTh = WTbase + (size_t)sel * HH * HH;
    const __nv_bfloat16* WTl = WLbase + (size_t)sel * HH * HH;
    const float* bias = sel == 0 ? bq : (sel == 1 ? bk : bv);
    __nv_bfloat16* out = sel == 0 ? oq : (sel == 1 ? ok : ov);

    float acc[8][4] = {};
    if (sel == 2) gemm_core_bf16<2>(sb, tid, m0, n0, A0, WTh, WTl, HH, acc);
    else          gemm_core_bf16<1>(sb, tid, m0, n0, A0, WTh, WTl, HH, acc);

    const int r0 = m0 + w * 16 + (lane >> 2);
#pragma unroll
    for (int nb = 0; nb < 8; nb++) {
        const int cg = n0 + (lane & 3) * 2 + nb * 8;
        float b0 = bias[cg], b1 = bias[cg + 1];
        float v00 = acc[nb][0] + b0, v01 = acc[nb][1] + b1;
        float v10 = acc[nb][2] + b0, v11 = acc[nb][3] + b1;
        const size_t i0 = (size_t)r0 * HH + cg;
        const size_t i1 = (size_t)(r0 + 8) * HH + cg;
        ((uint32_t*)out)[i0 >> 1] = packbf2(v00, v01);
        ((uint32_t*)out)[i1 >> 1] = packbf2(v10, v11);
        if (sel == 2) {
            float s0 = v00 + v10, s1 = v01 + v11;
#pragma unroll
            for (int off = 4; off < 32; off <<= 1) {
                s0 += __shfl_xor_sync(0xffffffffu, s0, off);
                s1 += __shfl_xor_sync(0xffffffffu, s1, off);
            }
            if (lane < 4) {
                redf(vsum + cg, s0);
                redf(vsum + cg + 1, s1);
            }
        }
    }
}

// ============== HMMA flash attention: 128 q-rows x 1 head per CTA ============
#define SM_BUFSTRIDE 32768
#define SM_VOFF 16384
#define SM_Q 65536
#define SM_ATT_TOTAL 81920

__device__ __forceinline__ void load_kv_tile(
    uint32_t sb, int buf, int kt, int head,
    const __nv_bfloat16* kb, const __nv_bfloat16* vb, int tid)
{
    const char* kc = (const char*)kb;
    const char* vc = (const char*)vb;
#pragma unroll
    for (int j = 0; j < 8; j++) {
        int flat = tid + j * 256;
        int arr = flat >> 10;
        int row = (flat >> 3) & 127;
        int c = flat & 7;
        const char* src = (arr ? vc : kc) +
            (((size_t)(kt + row) * HH + head * HD) << 1) + c * 16;
        uint32_t dst = sb + buf * SM_BUFSTRIDE + arr * SM_VOFF +
                       swz128((uint32_t)(row * 128 + c * 16));
        cp16(dst, src);
    }
}

__global__ void __launch_bounds__(256, 1) attn_mma(
    const __nv_bfloat16* __restrict__ qb, const __nv_bfloat16* __restrict__ kb,
    const __nv_bfloat16* __restrict__ vb, const float* __restrict__ vsum,
    __nv_bfloat16* __restrict__ oh)
{
    extern __shared__ char sm[];
    const uint32_t sb = smem_u32(sm);
    const int tid = threadIdx.x, w = tid >> 5, lane = tid & 31;
    const int q0 = blockIdx.x * 128, head = blockIdx.y;

    {
        const char* qc = (const char*)qb;
#pragma unroll
        for (int j = 0; j < 4; j++) {
            int flat = tid + j * 256;
            int row = flat >> 3, c = flat & 7;
            const char* src = qc + (((size_t)(q0 + row) * HH + head * HD) << 1) + c * 16;
            cp16(sb + SM_Q + swz128((uint32_t)(row * 128 + c * 16)), src);
        }
        load_kv_tile(sb, 0, 0, head, kb, vb, tid);
        cp_commit();
        cp_wait0();
        __syncthreads();
    }

    uint32_t qa[4][4];
    {
        const int rowa = w * 16 + (lane & 7) + ((lane >> 3) & 1) * 8;
        const int cb = ((lane >> 4) & 1) * 16;
#pragma unroll
        for (int kk = 0; kk < 4; kk++)
            ldsm4(qa[kk], sb + SM_Q + swz128((uint32_t)(rowa * 128 + kk * 32 + cb)));
    }

    float oacc[8][4] = {};
    float sumd0 = 0.f, sumd1 = 0.f;

    for (int t = 0; t < 32; t++) {
        const uint32_t kbase = sb + (t & 1) * SM_BUFSTRIDE;
        const uint32_t vbase = kbase + SM_VOFF;
        if (t + 1 < 32) {
            load_kv_tile(sb, (t + 1) & 1, (t + 1) * 128, head, kb, vb, tid);
            cp_commit();
        }
#pragma unroll 2
        for (int kk = 0; kk < 8; kk++) {
            float s[2][4] = {{0.f,0.f,0.f,0.f},{0.f,0.f,0.f,0.f}};
#pragma unroll
            for (int half = 0; half < 2; half++) {
                const int keyl = kk * 16 + half * 8 + (lane & 7);
#pragma unroll
                for (int kk2 = 0; kk2 < 2; kk2++) {
                    uint32_t b[4];
                    ldsm4(b, kbase + swz128((uint32_t)(keyl * 128 + kk2 * 64 +
                                                       ((lane >> 3) & 3) * 16)));
                    mma16816(s[half], qa[2*kk2][0], qa[2*kk2][1], qa[2*kk2][2],
                             qa[2*kk2][3], b[0], b[1]);
                    mma16816(s[half], qa[2*kk2+1][0], qa[2*kk2+1][1], qa[2*kk2+1][2],
                             qa[2*kk2+1][3], b[2], b[3]);
                }
            }
#pragma unroll
            for (int half = 0; half < 2; half++) {
#pragma unroll
                for (int j = 0; j < 4; j++) {
                    float x = s[half][j] * 0.125f;
                    float h = fmaf(x, 4.166666667e-2f, 0.166666667f);
                    h = fmaf(h, x, 0.5f);
                    h = fmaf(h, x, 1.0f);
                    float dlt = x * h;
                    s[half][j] = dlt;
                    if (j < 2) sumd0 += dlt; else sumd1 += dlt;
                }
            }
            uint32_t A0 = packbf2(s[0][0], s[0][1]);
            uint32_t A1 = packbf2(s[0][2], s[0][3]);
            uint32_t A2 = packbf2(s[1][0], s[1][1]);
            uint32_t A3 = packbf2(s[1][2], s[1][3]);
            const int keyl2 = kk * 16 + (lane & 7) + ((lane >> 3) & 1) * 8;
            const int cb2 = ((lane >> 4) & 1) * 16;
#pragma unroll
            for (int nb2 = 0; nb2 < 4; nb2++) {
                uint32_t b[4];
                ldsm4t(b, vbase + swz128((uint32_t)(keyl2 * 128 + nb2 * 32 + cb2)));
                mma16816(oacc[2*nb2],     A0, A1, A2, A3, b[0], b[1]);
                mma16816(oacc[2*nb2 + 1], A0, A1, A2, A3, b[2], b[3]);
            }
        }
        if (t + 1 < 32) { cp_wait0(); __syncthreads(); }
    }

    sumd0 += __shfl_xor_sync(0xffffffffu, sumd0, 1);
    sumd0 += __shfl_xor_sync(0xffffffffu, sumd0, 2);
    sumd1 += __shfl_xor_sync(0xffffffffu, sumd1, 1);
    sumd1 += __shfl_xor_sync(0xffffffffu, sumd1, 2);
    const float inv0 = 1.0f / (4096.0f + sumd0);
    const float inv1 = 1.0f / (4096.0f + sumd1);
    const int r0 = q0 + w * 16 + (lane >> 2);
    const int cbase = head * HD + (lane & 3) * 2;
#pragma unroll
    for (int nb = 0; nb < 8; nb++) {
        int d = cbase + nb * 8;
        float sv0 = vsum[d], sv1 = vsum[d + 1];
        ((uint32_t*)oh)[((size_t)r0 * HH + d) >> 1] =
            packbf2((sv0 + oacc[nb][0]) * inv0, (sv1 + oacc[nb][1]) * inv0);
        ((uint32_t*)oh)[((size_t)(r0 + 8) * HH + d) >> 1] =
            packbf2((sv0 + oacc[nb][2]) * inv1, (sv1 + oacc[nb][3]) * inv1);
    }
}

// ---------------- launch -----------------------------------------------------
extern "C" void kernel_launch(void* const* d_in, const int* in_sizes, int n_in,
                              void* d_out, int out_size)
{
    const float* text    = (const float*)d_in[0];
    const float* image   = (const float*)d_in[1];
    const int*   ei      = (const int*)d_in[2];
    const float* text_w  = (const float*)d_in[3];
    const float* text_b  = (const float*)d_in[4];
    const float* image_w = (const float*)d_in[5];
    const float* image_b = (const float*)d_in[6];
    const float* wq = (const float*)d_in[7];  const float* bq = (const float*)d_in[8];
    const float* wk = (const float*)d_in[9];  const float* bk = (const float*)d_in[10];
    const float* wv = (const float*)d_in[11]; const float* bv = (const float*)d_in[12];
    const float* wo = (const float*)d_in[13]; const float* bo = (const float*)d_in[14];
    const float* gcn1_w = (const float*)d_in[15]; const float* gcn1_b = (const float*)d_in[16];
    const float* gcn2_w = (const float*)d_in[17]; const float* gcn2_b = (const float*)d_in[18];
    const float* cls_w  = (const float*)d_in[19]; const float* cls_b  = (const float*)d_in[20];
    float* out = (float*)d_out;

    float *hb, *g1, *yb, *dinv, *vsum, *bg;
    __nv_bfloat16 *ch, *qbb, *kbb, *vbb, *obh, *g1h, *wth, *wtl;
    cudaGetSymbolAddress((void**)&hb, g_h);
    cudaGetSymbolAddress((void**)&g1, g_g1);
    cudaGetSymbolAddress((void**)&yb, g_y);
    cudaGetSymbolAddress((void**)&dinv, g_dinv);
    cudaGetSymbolAddress((void**)&vsum, g_vsum);
    cudaGetSymbolAddress((void**)&bg, g_bg);
    cudaGetSymbolAddress((void**)&ch, g_ch);
    cudaGetSymbolAddress((void**)&qbb, g_qb);
    cudaGetSymbolAddress((void**)&kbb, g_kb);
    cudaGetSymbolAddress((void**)&vbb, g_vb);
    cudaGetSymbolAddress((void**)&obh, g_obh);
    cudaGetSymbolAddress((void**)&g1h, g_g1h);
    cudaGetSymbolAddress((void**)&wth, g_wth);
    cudaGetSymbolAddress((void**)&wtl, g_wtl);

    // 1: weight prep + hist + WG=Wo@G1 + bG + zero(vsum, y)
    k_wprep_all<<<dim3(24, 8, 8), dim3(32, 32)>>>(
        text_w, image_w, wq, wk, wv, wo, gcn1_w, gcn2_w, bo, ei + EE);

    // 2: scan (start/cursor/dinv, re-zero cnt, bconst)
    k_scan<<<1, 1024>>>(gcn2_b, cls_w);

    // 3: fused text+image projection + scatter plane
    {
        static bool done = false;
        if (!done) {
            cudaFuncSetAttribute(gemm_fuse2,
                                 cudaFuncAttributeMaxDynamicSharedMemorySize, GEMM_SMEM);
            done = true;
        }
        gemm_fuse2<<<dim3(32, 5), 256, GEMM_SMEM>>>(
            text, image, wth + WOFF_TEXT, wtl + WOFF_TEXT,
            wth + WOFF_IMAGE, wtl + WOFF_IMAGE, text_b, image_b, ch,
            ei, ei + EE);
    }

    // 4: fused QKV (Q,K 1-pass; V 2-pass + vsum reds)
    {
        static bool done = false;
        if (!done) {
            cudaFuncSetAttribute(gemm_qkv,
                                 cudaFuncAttributeMaxDynamicSharedMemorySize, GEMM_SMEM);
            done = true;
        }
        gemm_qkv<<<dim3(32, 12), 256, GEMM_SMEM>>>(
            ch, wth + WOFF_WQ, wtl + WOFF_WQ, bq, bk, bv, qbb, kbb, vbb, vsum);
    }

    // 5: attention
    cudaFuncSetAttribute(attn_mma, cudaFuncAttributeMaxDynamicSharedMemorySize,
                         SM_ATT_TOTAL);
    attn_mma<<<dim3(NN / 128, NHD), 256, SM_ATT_TOTAL>>>(qbb, kbb, vbb, vsum, obh);

    // 6: GCN1 GEMM with composed weights (h = ob@WG + bG; init = dinv^2*h + b1)
    {
        static bool done = false;
        if (!done) {
            cudaFuncSetAttribute(gemm_tc<6>,
                                 cudaFuncAttributeMaxDynamicSharedMemorySize, GEMM_SMEM);
            done = true;
        }
        gemm_tc<6><<<dim3(32, 4), 256, GEMM_SMEM>>>(
            obh, wth + WOFF_G1, wtl + WOFF_G1, bg, gcn1_b, dinv, hb, g1, HH);
    }

    // 7: GCN1 aggregation (gather) + relu -> bf16 hi
    k_agg1<<<NN * 32 / 256, 256>>>(hb, g1, g1h);

    // 8: GCN2 GEMM in classifier space (red into y)
    {
        static bool done = false;
        if (!done) {
            cudaFuncSetAttribute(gemm_tc<7>,
                                 cudaFuncAttributeMaxDynamicSharedMemorySize, GEMM_SMEM);
            done = true;
        }
        gemm_tc<7><<<dim3(32, 4), 256, GEMM_SMEM>>>(
            g1h, wth + WOFF_G2, wtl + WOFF_G2, cls_w, nullptr, nullptr,
            yb, nullptr, HH);
    }

    // 9: GCN2 aggregation on y + bias
    k_agg2y<<<NN * 32 / 256, 256>>>(yb, cls_b, out);
}

// round 13
// speedup vs baseline: 1.1432x; 1.0097x over previous
#include <cuda_runtime.h>
#include <cuda_bf16.h>
#include <cstdint>
#include <cstddef>

#define NN 4096
#define TD 768
#define ID 512
#define HH 256
#define NHD 4
#define HD 64
#define EE 131072
#define NC 3

// ---------------- scratch (static device globals; no allocation) -------------
__device__ float g_h[NN * HH];      // fp32 transformed features (GCN1 h)
__device__ float g_g1[NN * HH];     // GCN1 init (self-loop term)
__device__ float g_y[NN * 4];       // GCN2 h @ cls_w (padded to 4)
__device__ float g_dinv[NN];
__device__ float g_vsum[HH];
__device__ float g_bconst[3];
__device__ float g_bg[HH];          // bo @ G1
__device__ int   g_cnt[NN];         // zero at module load; re-zeroed by k_scan
__device__ int   g_start[NN + 1];
__device__ int   g_cursor[NN];
__device__ int   g_sorted[EE];
// bf16 activations (hi only)
__device__ __nv_bfloat16 g_ch[NN * HH];
__device__ __nv_bfloat16 g_qb[NN * HH];
__device__ __nv_bfloat16 g_kb[NN * HH];
__device__ __nv_bfloat16 g_vb[NN * HH];
__device__ __nv_bfloat16 g_obh[NN * HH];
__device__ __nv_bfloat16 g_g1h[NN * HH];
// transposed+split weights [n][K] (hi + lo)
#define WOFF_TEXT  0
#define WOFF_IMAGE 196608
#define WOFF_WQ    327680
#define WOFF_WK    393216
#define WOFF_WV    458752
#define WOFF_G1    524288   /* holds WG = Wo@G1, composed */
#define WOFF_G2    589824
#define WTOT       655360
__device__ __nv_bfloat16 g_wth[WTOT], g_wtl[WTOT];

// =================== helpers =================================================
__device__ __forceinline__ uint32_t smem_u32(const void* p) {
    uint32_t a;
    asm("{ .reg .u64 t; cvta.to.shared.u64 t, %1; cvt.u32.u64 %0, t; }"
        : "=r"(a) : "l"(p));
    return a;
}
__device__ __forceinline__ uint32_t swz128(uint32_t o) { return o ^ ((o >> 3) & 0x70); }
__device__ __forceinline__ uint32_t swz64(uint32_t o)  { return o ^ ((o >> 3) & 0x30); }
__device__ __forceinline__ uint32_t packbf2(float x0, float x1) {
    uint32_t r;  // lo = x0, hi = x1
    asm("cvt.rn.satfinite.bf16x2.f32 %0, %1, %2;" : "=r"(r) : "f"(x1), "f"(x0));
    return r;
}
__device__ __forceinline__ void mma16816(float* c,
    uint32_t a0, uint32_t a1, uint32_t a2, uint32_t a3, uint32_t b0, uint32_t b1) {
    asm volatile("mma.sync.aligned.m16n8k16.row.col.f32.bf16.bf16.f32 "
        "{%0,%1,%2,%3}, {%4,%5,%6,%7}, {%8,%9}, {%0,%1,%2,%3};"
        : "+f"(c[0]), "+f"(c[1]), "+f"(c[2]), "+f"(c[3])
        : "r"(a0), "r"(a1), "r"(a2), "r"(a3), "r"(b0), "r"(b1));
}
__device__ __forceinline__ void ldsm4(uint32_t* r, uint32_t a) {
    asm volatile("ldmatrix.sync.aligned.m8n8.x4.shared.b16 {%0,%1,%2,%3}, [%4];"
        : "=r"(r[0]), "=r"(r[1]), "=r"(r[2]), "=r"(r[3]) : "r"(a));
}
__device__ __forceinline__ void ldsm4t(uint32_t* r, uint32_t a) {
    asm volatile("ldmatrix.sync.aligned.m8n8.x4.trans.shared.b16 {%0,%1,%2,%3}, [%4];"
        : "=r"(r[0]), "=r"(r[1]), "=r"(r[2]), "=r"(r[3]) : "r"(a));
}
__device__ __forceinline__ void cp16(uint32_t dst, const void* src) {
    asm volatile("cp.async.cg.shared.global [%0], [%1], 16;" :: "r"(dst), "l"(src) : "memory");
}
__device__ __forceinline__ void cp_commit() {
    asm volatile("cp.async.commit_group;" ::: "memory");
}
__device__ __forceinline__ void cp_wait0() {
    asm volatile("cp.async.wait_group 0;" ::: "memory");
}
__device__ __forceinline__ void cp_wait1() {
    asm volatile("cp.async.wait_group 1;" ::: "memory");
}
__device__ __forceinline__ void redf(float* p, float v) {
    asm volatile("red.global.add.f32 [%0], %1;" :: "l"(p), "f"(v) : "memory");
}

// ====== single-launch prep: weights + hist + WG compose + bG + zeroing =======
__global__ void k_wprep_all(
    const float* w0, const float* w1, const float* w2, const float* w3,
    const float* w4, const float* wo, const float* g1w, const float* w7,
    const float* bo, const int* __restrict__ edst)
{
    const int z = blockIdx.z;
    const int tx = threadIdx.x, ty = threadIdx.y;
    if (z == 5) {
        int flat = (blockIdx.y * 24 + blockIdx.x) * 1024 + ty * 32 + tx;
        if (flat < EE) atomicAdd(&g_cnt[edst[flat]], 1);
        return;
    }
    if (z == 6) {
        if (blockIdx.x < 8) {
            int k0 = blockIdx.x * 32, n0 = blockIdx.y * 32;
            __shared__ float sW[32][33], sG[32][33];
            float acc = 0.f;
            for (int j0 = 0; j0 < HH; j0 += 32) {
                sW[ty][tx] = wo[(size_t)(k0 + ty) * HH + j0 + tx];
                sG[ty][tx] = g1w[(size_t)(j0 + ty) * HH + n0 + tx];
                __syncthreads();
#pragma unroll
                for (int jj = 0; jj < 32; jj++)
                    acc = fmaf(sW[tx][jj], sG[jj][ty], acc);
                __syncthreads();
            }
            __nv_bfloat16 h = __float2bfloat16(acc);
            __nv_bfloat16 l = __float2bfloat16(acc - __bfloat162float(h));
            size_t idx = (size_t)WOFF_G1 + (size_t)(n0 + ty) * HH + k0 + tx;
            g_wth[idx] = h;
            g_wtl[idx] = l;
        } else if (blockIdx.x == 8) {
            if (blockIdx.y == 0) {
                int t = ty * 32 + tx;
                if (t < HH) {
                    float s = 0.f;
                    for (int j = 0; j < HH; j++)
                        s = fmaf(bo[j], g1w[(size_t)j * HH + t], s);
                    g_bg[t] = s;
                }
            }
        } else if (blockIdx.x == 9) {
            int flat = blockIdx.y * 1024 + ty * 32 + tx;
            for (int i = flat; i < NN * 4 + HH; i += 8192) {
                if (i < NN * 4) g_y[i] = 0.f;
                else g_vsum[i - NN * 4] = 0.f;
            }
        }
        return;
    }
    const float* W; int K, off;
    switch (z) {
        case 0: W = w0; K = TD; off = WOFF_TEXT; break;
        case 1: W = w1; K = ID; off = WOFF_IMAGE; break;
        case 2: W = w2; K = HH; off = WOFF_WQ; break;
        case 3: W = w3; K = HH; off = WOFF_WK; break;
        case 4: W = w4; K = HH; off = WOFF_WV; break;
        default: W = w7; K = HH; off = WOFF_G2; break;
    }
    int k0 = blockIdx.x * 32;
    if (k0 >= K) return;
    int n0 = blockIdx.y * 32;
    __shared__ float t[32][33];
    t[ty][tx] = W[(size_t)(k0 + ty) * HH + n0 + tx];
    __syncthreads();
    float v = t[tx][ty];
    __nv_bfloat16 h = __float2bfloat16(v);
    __nv_bfloat16 l = __float2bfloat16(v - __bfloat162float(h));
    size_t idx = (size_t)off + (size_t)(n0 + ty) * K + k0 + tx;
    g_wth[idx] = h;
    g_wtl[idx] = l;
}

// 1 CTA, 1024 threads: prefix-scan cnt -> start/cursor, dinv; re-zero cnt;
// bconst = gcn2_b @ cls_w.
__global__ void k_scan(const float* __restrict__ b2, const float* __restrict__ cw)
{
    __shared__ int wsum[32];
    const int t = threadIdx.x, lane = t & 31, wid = t >> 5;
    if (t < 3) {
        float s = 0.f;
        for (int j = 0; j < HH; j++) s = fmaf(b2[j], cw[j * 3 + t], s);
        g_bconst[t] = s;
    }
    const int base = t * 4;
    int c0 = g_cnt[base], c1 = g_cnt[base + 1], c2 = g_cnt[base + 2], c3 = g_cnt[base + 3];
    int s = c0 + c1 + c2 + c3;
    int v = s;
#pragma unroll
    for (int off = 1; off < 32; off <<= 1) {
        int u = __shfl_up_sync(0xffffffffu, v, off);
        if (lane >= off) v += u;
    }
    if (lane == 31) wsum[wid] = v;
    __syncthreads();
    if (wid == 0) {
        int x = wsum[lane];
#pragma unroll
        for (int off = 1; off < 32; off <<= 1) {
            int u = __shfl_up_sync(0xffffffffu, x, off);
            if (lane >= off) x += u;
        }
        wsum[lane] = x;
    }
    __syncthreads();
    int excl = v - s + (wid > 0 ? wsum[wid - 1] : 0);
    int e0 = excl, e1 = e0 + c0, e2 = e1 + c1, e3 = e2 + c2;
    g_start[base] = e0;  g_cursor[base] = e0;
    g_start[base + 1] = e1; g_cursor[base + 1] = e1;
    g_start[base + 2] = e2; g_cursor[base + 2] = e2;
    g_start[base + 3] = e3; g_cursor[base + 3] = e3;
    g_dinv[base]     = rsqrtf((float)(c0 + 1));
    g_dinv[base + 1] = rsqrtf((float)(c1 + 1));
    g_dinv[base + 2] = rsqrtf((float)(c2 + 1));
    g_dinv[base + 3] = rsqrtf((float)(c3 + 1));
    g_cnt[base] = 0; g_cnt[base + 1] = 0; g_cnt[base + 2] = 0; g_cnt[base + 3] = 0;
    if (t == 1023) g_start[NN] = e3 + c3;
}

// ====== GCN layer-1 aggregation: warp per dst, gather ========================
__global__ void __launch_bounds__(256) k_agg1(
    const float* __restrict__ h, const float* __restrict__ init,
    __nv_bfloat16* __restrict__ oh)
{
    const int dstn = (blockIdx.x * 256 + threadIdx.x) >> 5;
    const int lane = threadIdx.x & 31;
    if (dstn >= NN) return;
    const int beg = g_start[dstn], end = g_start[dstn + 1];
    const float dd = g_dinv[dstn];

    float acc[8];
    {
        const float4* ir = (const float4*)(init + (size_t)dstn * HH) + lane * 2;
        float4 a = ir[0], b = ir[1];
        acc[0] = a.x; acc[1] = a.y; acc[2] = a.z; acc[3] = a.w;
        acc[4] = b.x; acc[5] = b.y; acc[6] = b.z; acc[7] = b.w;
    }
    for (int e = beg; e < end; e += 32) {
        int n = end - e; if (n > 32) n = 32;
        int sidx = 0; float dv = 0.f;
        if (lane < n) {
            sidx = __ldg(&g_sorted[e + lane]);
            dv = __ldg(&g_dinv[sidx]);
        }
#pragma unroll 4
        for (int j = 0; j < n; j++) {
            int s = __shfl_sync(0xffffffffu, sidx, j);
            float cf = __shfl_sync(0xffffffffu, dv, j) * dd;
            const float4* hr = (const float4*)(h + ((size_t)s << 8)) + (lane << 1);
            float4 a = __ldg(hr), b = __ldg(hr + 1);
            acc[0] = fmaf(cf, a.x, acc[0]); acc[1] = fmaf(cf, a.y, acc[1]);
            acc[2] = fmaf(cf, a.z, acc[2]); acc[3] = fmaf(cf, a.w, acc[3]);
            acc[4] = fmaf(cf, b.x, acc[4]); acc[5] = fmaf(cf, b.y, acc[5]);
            acc[6] = fmaf(cf, b.z, acc[6]); acc[7] = fmaf(cf, b.w, acc[7]);
        }
    }
#pragma unroll
    for (int p = 0; p < 4; p++) {
        float x = fmaxf(acc[2 * p], 0.f), y = fmaxf(acc[2 * p + 1], 0.f);
        ((uint32_t*)oh)[((size_t)dstn * HH + lane * 8 + 2 * p) >> 1] = packbf2(x, y);
    }
}

// ====== GCN layer-2 aggregation on y[4] (classifier space) ===================
__global__ void __launch_bounds__(256) k_agg2y(
    const float* __restrict__ y, const float* __restrict__ cls_b,
    float* __restrict__ out)
{
    const int d = (blockIdx.x * 256 + threadIdx.x) >> 5;
    const int lane = threadIdx.x & 31;
    if (d >= NN) return;
    const int beg = g_start[d], end = g_start[d + 1];
    float a0 = 0.f, a1 = 0.f, a2 = 0.f;
    for (int e = beg + lane; e < end; e += 32) {
        int s = __ldg(&g_sorted[e]);
        float dv = __ldg(&g_dinv[s]);
        float4 yv = *(const float4*)(y + s * 4);
        a0 = fmaf(dv, yv.x, a0);
        a1 = fmaf(dv, yv.y, a1);
        a2 = fmaf(dv, yv.z, a2);
    }
#pragma unroll
    for (int off = 16; off > 0; off >>= 1) {
        a0 += __shfl_xor_sync(0xffffffffu, a0, off);
        a1 += __shfl_xor_sync(0xffffffffu, a1, off);
        a2 += __shfl_xor_sync(0xffffffffu, a2, off);
    }
    if (lane == 0) {
        float dd = g_dinv[d];
        float4 yd = *(const float4*)(y + d * 4);
        out[d * 3 + 0] = fmaf(dd, fmaf(dd, yd.x, a0), g_bconst[0] + cls_b[0]);
        out[d * 3 + 1] = fmaf(dd, fmaf(dd, yd.y, a1), g_bconst[1] + cls_b[1]);
        out[d * 3 + 2] = fmaf(dd, fmaf(dd, yd.z, a2), g_bconst[2] + cls_b[2]);
    }
}

// =============== HMMA GEMM cores =============================================
#define GST 24576
#define GS_AL 8192
#define GS_W  16384
#define GS_WL 20480
#define GEMM_SMEM 49152     /* f32 core: 2 stages */
#define GEMM_SMEM3 73728    /* bf16 core: 3 stages */

// NPASS: 2 = AhWh + AhWl, 1 = AhWh only. 3-stage cp.async pipeline (wait 1).
template<int NPASS>
__device__ __forceinline__ void gemm_core_bf16(
    uint32_t sb, int tid, int m0, int n0,
    const __nv_bfloat16* A0,
    const __nv_bfloat16* WTh, const __nv_bfloat16* WTl,
    int K, float acc[8][4])
{
    const int w = tid >> 5, lane = tid & 31;
    const int rowa = w * 16 + (lane & 7) + ((lane >> 3) & 1) * 8;
    const int acb  = ((lane >> 4) & 1) * 16;
    const int nrow = lane & 7;
    const int bcb  = ((lane >> 3) & 3) * 16;
    const int nch = K >> 5;

    auto load_st = [&](int kc, int st) {
        int k0 = kc << 5;
        uint32_t base = sb + st * GST;
#pragma unroll
        for (int j = 0; j < 2; j++) {
            int flat = tid + j * 256;
            int r = flat >> 2, c = flat & 3;
            const char* src = (const char*)A0 +
                              (((size_t)(m0 + r) * K + k0) << 1) + c * 16;
            cp16(base + swz64((uint32_t)(r * 64 + c * 16)), src);
        }
#pragma unroll
        for (int j = 0; j < NPASS; j++) {
            int flat = tid + j * 256;
            int part = flat >> 8, r = (flat >> 2) & 63, c = flat & 3;
            const char* src = (const char*)(part ? WTl : WTh) +
                              (((size_t)(n0 + r) * K + k0) << 1) + c * 16;
            cp16(base + GS_W + part * 4096 + swz64((uint32_t)(r * 64 + c * 16)), src);
        }
        cp_commit();
    };
    auto compute = [&](int st) {
        uint32_t base = sb + st * GST;
        uint32_t ah[2][4];
#pragma unroll
        for (int kk2 = 0; kk2 < 2; kk2++)
            ldsm4(ah[kk2], base + swz64((uint32_t)(rowa * 64 + kk2 * 32 + acb)));
#pragma unroll
        for (int nb = 0; nb < 8; nb++) {
            uint32_t bo = swz64((uint32_t)((nb * 8 + nrow) * 64 + bcb));
            uint32_t bh[4];
            ldsm4(bh, base + GS_W + bo);
            mma16816(acc[nb], ah[0][0], ah[0][1], ah[0][2], ah[0][3], bh[0], bh[1]);
            mma16816(acc[nb], ah[1][0], ah[1][1], ah[1][2], ah[1][3], bh[2], bh[3]);
            if (NPASS == 2) {
                uint32_t bl[4];
                ldsm4(bl, base + GS_WL + bo);
                mma16816(acc[nb], ah[0][0], ah[0][1], ah[0][2], ah[0][3], bl[0], bl[1]);
                mma16816(acc[nb], ah[1][0], ah[1][1], ah[1][2], ah[1][3], bl[2], bl[3]);
            }
        }
    };

    // 3-stage pipeline
    load_st(0, 0);
    load_st(1, 1);
    cp_wait1();              // stage 0 ready
    __syncthreads();
    int st = 0;
    for (int kc = 0; kc < nch; kc++) {
        if (kc + 2 < nch) {
            int s2 = st + 2; if (s2 >= 3) s2 -= 3;
            load_st(kc + 2, s2);
        }
        compute(st);
        if (kc + 1 < nch) {
            cp_wait1();      // stage kc+1 ready (kc+2 may still be in flight)
            __syncthreads();
        }
        if (++st == 3) st = 0;
    }
}

// fp32-A core: 2-pass (AhWh + AhWl); 2-stage (register-staged A conversion).
__device__ __forceinline__ void gemm_core_f32(
    char* smc, uint32_t sb, int tid, int m0, int n0,
    const float* A, const __nv_bfloat16* WTh, const __nv_bfloat16* WTl,
    int K, float acc[8][4])
{
    const int w = tid >> 5, lane = tid & 31;
    const int rowa = w * 16 + (lane & 7) + ((lane >> 3) & 1) * 8;
    const int acb  = ((lane >> 4) & 1) * 16;
    const int nrow = lane & 7;
    const int bcb  = ((lane >> 3) & 3) * 16;
    const int nch = K >> 5;
    float4 ar[4];

    auto load_w = [&](int kc, int st) {
        int k0 = kc << 5;
        uint32_t base = sb + st * GST + GS_W;
#pragma unroll
        for (int j = 0; j < 2; j++) {
            int flat = tid + j * 256;
            int part = flat >> 8, r = (flat >> 2) & 63, c = flat & 3;
            const char* src = (const char*)(part ? WTl : WTh) +
                              (((size_t)(n0 + r) * K + k0) << 1) + c * 16;
            cp16(base + part * 4096 + swz64((uint32_t)(r * 64 + c * 16)), src);
        }
    };
    auto ldg_a = [&](int kc) {
        int k0 = kc << 5;
#pragma unroll
        for (int j = 0; j < 4; j++) {
            int flat = tid + j * 256;
            int r = flat >> 3, c = flat & 7;
            ar[j] = *(const float4*)(A + (size_t)(m0 + r) * K + k0 + c * 4);
        }
    };
    auto sts_a = [&](int st) {
        uint32_t off0 = st * GST;
#pragma unroll
        for (int j = 0; j < 4; j++) {
            int flat = tid + j * 256;
            int r = flat >> 3, c = flat & 7;
            uint32_t off = swz64((uint32_t)(r * 64 + c * 8));
            uint32_t h0 = packbf2(ar[j].x, ar[j].y);
            uint32_t h1 = packbf2(ar[j].z, ar[j].w);
            *(uint2*)(smc + off0 + off) = make_uint2(h0, h1);
        }
    };
    auto compute = [&](int st) {
        uint32_t base = sb + st * GST;
        uint32_t ah[2][4];
#pragma unroll
        for (int kk2 = 0; kk2 < 2; kk2++)
            ldsm4(ah[kk2], base + swz64((uint32_t)(rowa * 64 + kk2 * 32 + acb)));
#pragma unroll
        for (int nb = 0; nb < 8; nb++) {
            uint32_t bo = swz64((uint32_t)((nb * 8 + nrow) * 64 + bcb));
            uint32_t bh[4], bl[4];
            ldsm4(bh, base + GS_W + bo);
            ldsm4(bl, base + GS_WL + bo);
            mma16816(acc[nb], ah[0][0], ah[0][1], ah[0][2], ah[0][3], bh[0], bh[1]);
            mma16816(acc[nb], ah[1][0], ah[1][1], ah[1][2], ah[1][3], bh[2], bh[3]);
            mma16816(acc[nb], ah[0][0], ah[0][1], ah[0][2], ah[0][3], bl[0], bl[1]);
            mma16816(acc[nb], ah[1][0], ah[1][1], ah[1][2], ah[1][3], bl[2], bl[3]);
        }
    };

    ldg_a(0); load_w(0, 0); cp_commit(); sts_a(0); cp_wait0();
    __syncthreads();
    for (int kc = 0; kc < nch; kc++) {
        if (kc + 1 < nch) {
            ldg_a(kc + 1);
            load_w(kc + 1, (kc + 1) & 1);
            cp_commit();
        }
        compute(kc & 1);
        if (kc + 1 < nch) {
            sts_a((kc + 1) & 1);
            cp_wait0();
            __syncthreads();
        }
    }
}

// fused text+image projection + edge-scatter plane (blockIdx.y == 4)
__global__ void __launch_bounds__(256, 2) gemm_fuse2(
    const float* __restrict__ text, const float* __restrict__ image,
    const __nv_bfloat16* __restrict__ Wth, const __nv_bfloat16* __restrict__ Wtl,
    const __nv_bfloat16* __restrict__ Wih, const __nv_bfloat16* __restrict__ Wil,
    const float* __restrict__ tb, const float* __restrict__ ib,
    __nv_bfloat16* __restrict__ ch,
    const int* __restrict__ esrc, const int* __restrict__ edst)
{
    if (blockIdx.y == 4) {
        int base = (blockIdx.x * 256 + threadIdx.x) * 16;
        int4 d4[4], s4[4];
#pragma unroll
        for (int i = 0; i < 4; i++) {
            d4[i] = *(const int4*)(edst + base + i * 4);
            s4[i] = *(const int4*)(esrc + base + i * 4);
        }
#pragma unroll
        for (int i = 0; i < 4; i++) {
            const int dd[4] = {d4[i].x, d4[i].y, d4[i].z, d4[i].w};
            const int ss[4] = {s4[i].x, s4[i].y, s4[i].z, s4[i].w};
#pragma unroll
            for (int j = 0; j < 4; j++) {
                int pos = atomicAdd(&g_cursor[dd[j]], 1);
                g_sorted[pos] = ss[j];
            }
        }
        return;
    }
    extern __shared__ char sm[];
    const uint32_t sb = smem_u32(sm);
    const int tid = threadIdx.x, w = tid >> 5, lane = tid & 31;
    const int m0 = blockIdx.x * 128, n0 = blockIdx.y * 64;

    float acc[8][4] = {};
    gemm_core_f32(sm, sb, tid, m0, n0, text, Wth, Wtl, TD, acc);
    float rf[8][4];
#pragma unroll
    for (int nb = 0; nb < 8; nb++) {
        const int cg = n0 + (lane & 3) * 2 + nb * 8;
        float b0 = tb[cg], b1 = tb[cg + 1];
        rf[nb][0] = fmaxf(acc[nb][0] + b0, 0.f);
        rf[nb][1] = fmaxf(acc[nb][1] + b1, 0.f);
        rf[nb][2] = fmaxf(acc[nb][2] + b0, 0.f);
        rf[nb][3] = fmaxf(acc[nb][3] + b1, 0.f);
        acc[nb][0] = acc[nb][1] = acc[nb][2] = acc[nb][3] = 0.f;
    }
    __syncthreads();
    gemm_core_f32(sm, sb, tid, m0, n0, image, Wih, Wil, ID, acc);

    const int r0 = m0 + w * 16 + (lane >> 2);
#pragma unroll
    for (int nb = 0; nb < 8; nb++) {
        const int cg = n0 + (lane & 3) * 2 + nb * 8;
        float b0 = ib[cg], b1 = ib[cg + 1];
        const size_t i0 = (size_t)r0 * HH + cg;
        const size_t i1 = (size_t)(r0 + 8) * HH + cg;
        ((uint32_t*)ch)[i0 >> 1] = packbf2(rf[nb][0] + fmaxf(acc[nb][0] + b0, 0.f),
                                           rf[nb][1] + fmaxf(acc[nb][1] + b1, 0.f));
        ((uint32_t*)ch)[i1 >> 1] = packbf2(rf[nb][2] + fmaxf(acc[nb][2] + b0, 0.f),
                                           rf[nb][3] + fmaxf(acc[nb][3] + b1, 0.f));
    }
}

// general GEMM kernel (bf16-A hi, 2-pass), epilogues:
// EPI 6: h = acc + bias (fp32 out0); out1 = dinv^2*h + bias2 (aux=dinv)
// EPI 7: y-partials: red out0 += acc@cls_w (bias = cls_w)
template<int EPI>
__global__ void __launch_bounds__(256, 2) gemm_tc(
    const __nv_bfloat16* __restrict__ A0,
    const __nv_bfloat16* __restrict__ WTh, const __nv_bfloat16* __restrict__ WTl,
    const float* __restrict__ bias, const float* __restrict__ bias2,
    const float* __restrict__ aux,
    void* out0v, void* out1v, int K)
{
    extern __shared__ char sm[];
    const uint32_t sb = smem_u32(sm);
    const int tid = threadIdx.x, w = tid >> 5, lane = tid & 31;
    const int m0 = blockIdx.x * 128, n0 = blockIdx.y * 64;
    float acc[8][4] = {};
    gemm_core_bf16<2>(sb, tid, m0, n0, A0, WTh, WTl, K, acc);

    const int r0 = m0 + w * 16 + (lane >> 2);
    if (EPI == 7) {
        const float* cw = bias;
        float p0[3] = {0.f, 0.f, 0.f}, p1[3] = {0.f, 0.f, 0.f};
#pragma unroll
        for (int nb = 0; nb < 8; nb++) {
            const int cg = n0 + (lane & 3) * 2 + nb * 8;
#pragma unroll
            for (int c = 0; c < 3; c++) {
                float w0 = __ldg(cw + cg * 3 + c), w1 = __ldg(cw + (cg + 1) * 3 + c);
                p0[c] = fmaf(acc[nb][0], w0, fmaf(acc[nb][1], w1, p0[c]));
                p1[c] = fmaf(acc[nb][2], w0, fmaf(acc[nb][3], w1, p1[c]));
            }
        }
#pragma unroll
        for (int c = 0; c < 3; c++) {
            p0[c] += __shfl_xor_sync(0xffffffffu, p0[c], 1);
            p0[c] += __shfl_xor_sync(0xffffffffu, p0[c], 2);
            p1[c] += __shfl_xor_sync(0xffffffffu, p1[c], 1);
            p1[c] += __shfl_xor_sync(0xffffffffu, p1[c], 2);
        }
        if ((lane & 3) == 0) {
            float* y = (float*)out0v;
#pragma unroll
            for (int c = 0; c < 3; c++) {
                redf(y + r0 * 4 + c, p0[c]);
                redf(y + (r0 + 8) * 4 + c, p1[c]);
            }
        }
        return;
    }
#pragma unroll
    for (int nb = 0; nb < 8; nb++) {
        const int cg = n0 + (lane & 3) * 2 + nb * 8;
        float b0 = bias[cg], b1 = bias[cg + 1];
        float v00 = acc[nb][0] + b0, v01 = acc[nb][1] + b1;
        float v10 = acc[nb][2] + b0, v11 = acc[nb][3] + b1;
        const size_t i0 = (size_t)r0 * HH + cg;
        const size_t i1 = (size_t)(r0 + 8) * HH + cg;
        *(float2*)((float*)out0v + i0) = make_float2(v00, v01);
        *(float2*)((float*)out0v + i1) = make_float2(v10, v11);
        float bb0 = bias2[cg], bb1 = bias2[cg + 1];
        float dv0 = aux[r0], dv1 = aux[r0 + 8];
        float c20 = dv0 * dv0, c21 = dv1 * dv1;
        *(float2*)((float*)out1v + i0) = make_float2(fmaf(c20, v00, bb0), fmaf(c20, v01, bb1));
        *(float2*)((float*)out1v + i1) = make_float2(fmaf(c21, v10, bb0), fmaf(c21, v11, bb1));
    }
}

// fused QKV GEMM: grid (32, 12); sel = blockIdx.y>>2.
// Q,K: 1-pass; V: 2-pass + vsum reds.
__global__ void __launch_bounds__(256, 2) gemm_qkv(
    const __nv_bfloat16* __restrict__ A0,
    const __nv_bfloat16* __restrict__ WTbase, const __nv_bfloat16* __restrict__ WLbase,
    const float* __restrict__ bq, const float* __restrict__ bk,
    const float* __restrict__ bv,
    __nv_bfloat16* __restrict__ oq, __nv_bfloat16* __restrict__ ok,
    __nv_bfloat16* __restrict__ ov, float* __restrict__ vsum)
{
    extern __shared__ char sm[];
    const uint32_t sb = smem_u32(sm);
    const int tid = threadIdx.x, w = tid >> 5, lane = tid & 31;
    const int sel = blockIdx.y >> 2;
    const int m0 = blockIdx.x * 128, n0 = (blockIdx.y & 3) * 64;
    const __nv_bfloat16* WTh = WTbase + (size_t)sel * HH * HH;
    const __nv_bfloat16* WTl = WLbase + (size_t)sel * HH * HH;
    const float* bias = sel == 0 ? bq : (sel == 1 ? bk : bv);
    __nv_bfloat16* out = sel == 0 ? oq : (sel == 1 ? ok : ov);

    float acc[8][4] = {};
    if (sel == 2) gemm_core_bf16<2>(sb, tid, m0, n0, A0, WTh, WTl, HH, acc);
    else          gemm_core_bf16<1>(sb, tid, m0, n0, A0, WTh, WTl, HH, acc);

    const int r0 = m0 + w * 16 + (lane >> 2);
#pragma unroll
    for (int nb = 0; nb < 8; nb++) {
        const int cg = n0 + (lane & 3) * 2 + nb * 8;
        float b0 = bias[cg], b1 = bias[cg + 1];
        float v00 = acc[nb][0] + b0, v01 = acc[nb][1] + b1;
        float v10 = acc[nb][2] + b0, v11 = acc[nb][3] + b1;
        const size_t i0 = (size_t)r0 * HH + cg;
        const size_t i1 = (size_t)(r0 + 8) * HH + cg;
        ((uint32_t*)out)[i0 >> 1] = packbf2(v00, v01);
        ((uint32_t*)out)[i1 >> 1] = packbf2(v10, v11);
        if (sel == 2) {
            float s0 = v00 + v10, s1 = v01 + v11;
#pragma unroll
            for (int off = 4; off < 32; off <<= 1) {
                s0 += __shfl_xor_sync(0xffffffffu, s0, off);
                s1 += __shfl_xor_sync(0xffffffffu, s1, off);
            }
            if (lane < 4) {
                redf(vsum + cg, s0);
                redf(vsum + cg + 1, s1);
            }
        }
    }
}

// ============== HMMA flash attention: 128 q-rows x 1 head per CTA ============
// 3-stage K/V pipeline: 3 x 32KB KV buffers + 16KB Q = 112KB smem.
#define SM_BUFSTRIDE 32768
#define SM_VOFF 16384
#define SM_Q 98304
#define SM_ATT_TOTAL 114688

__device__ __forceinline__ void load_kv_tile(
    uint32_t sb, int buf, int kt, int head,
    const __nv_bfloat16* kb, const __nv_bfloat16* vb, int tid)
{
    const char* kc = (const char*)kb;
    const char* vc = (const char*)vb;
#pragma unroll
    for (int j = 0; j < 8; j++) {
        int flat = tid + j * 256;
        int arr = flat >> 10;
        int row = (flat >> 3) & 127;
        int c = flat & 7;
        const char* src = (arr ? vc : kc) +
            (((size_t)(kt + row) * HH + head * HD) << 1) + c * 16;
        uint32_t dst = sb + buf * SM_BUFSTRIDE + arr * SM_VOFF +
                       swz128((uint32_t)(row * 128 + c * 16));
        cp16(dst, src);
    }
}

__global__ void __launch_bounds__(256, 1) attn_mma(
    const __nv_bfloat16* __restrict__ qb, const __nv_bfloat16* __restrict__ kb,
    const __nv_bfloat16* __restrict__ vb, const float* __restrict__ vsum,
    __nv_bfloat16* __restrict__ oh)
{
    extern __shared__ char sm[];
    const uint32_t sb = smem_u32(sm);
    const int tid = threadIdx.x, w = tid >> 5, lane = tid & 31;
    const int q0 = blockIdx.x * 128, head = blockIdx.y;

    // prologue: group0 = Q + KV0, group1 = KV1
    {
        const char* qc = (const char*)qb;
#pragma unroll
        for (int j = 0; j < 4; j++) {
            int flat = tid + j * 256;
            int row = flat >> 3, c = flat & 7;
            const char* src = qc + (((size_t)(q0 + row) * HH + head * HD) << 1) + c * 16;
            cp16(sb + SM_Q + swz128((uint32_t)(row * 128 + c * 16)), src);
        }
        load_kv_tile(sb, 0, 0, head, kb, vb, tid);
        cp_commit();
        load_kv_tile(sb, 1, 128, head, kb, vb, tid);
        cp_commit();
        cp_wait1();           // group0 (Q + KV0) ready
        __syncthreads();
    }

    uint32_t qa[4][4];
    {
        const int rowa = w * 16 + (lane & 7) + ((lane >> 3) & 1) * 8;
        const int cb = ((lane >> 4) & 1) * 16;
#pragma unroll
        for (int kk = 0; kk < 4; kk++)
            ldsm4(qa[kk], sb + SM_Q + swz128((uint32_t)(rowa * 128 + kk * 32 + cb)));
    }

    float oacc[8][4] = {};
    float sumd0 = 0.f, sumd1 = 0.f;

    int buf = 0;
    for (int t = 0; t < 32; t++) {
        const uint32_t kbase = sb + buf * SM_BUFSTRIDE;
        const uint32_t vbase = kbase + SM_VOFF;
        if (t + 2 < 32) {
            int b2 = buf + 2; if (b2 >= 3) b2 -= 3;
            load_kv_tile(sb, b2, (t + 2) * 128, head, kb, vb, tid);
            cp_commit();
        }
#pragma unroll 2
        for (int kk = 0; kk < 8; kk++) {
            float s[2][4] = {{0.f,0.f,0.f,0.f},{0.f,0.f,0.f,0.f}};
#pragma unroll
            for (int half = 0; half < 2; half++) {
                const int keyl = kk * 16 + half * 8 + (lane & 7);
#pragma unroll
                for (int kk2 = 0; kk2 < 2; kk2++) {
                    uint32_t b[4];
                    ldsm4(b, kbase + swz128((uint32_t)(keyl * 128 + kk2 * 64 +
                                                       ((lane >> 3) & 3) * 16)));
                    mma16816(s[half], qa[2*kk2][0], qa[2*kk2][1], qa[2*kk2][2],
                             qa[2*kk2][3], b[0], b[1]);
                    mma16816(s[half], qa[2*kk2+1][0], qa[2*kk2+1][1], qa[2*kk2+1][2],
                             qa[2*kk2+1][3], b[2], b[3]);
                }
            }
#pragma unroll
            for (int half = 0; half < 2; half++) {
#pragma unroll
                for (int j = 0; j < 4; j++) {
                    float x = s[half][j] * 0.125f;
                    float h = fmaf(x, 4.166666667e-2f, 0.166666667f);
                    h = fmaf(h, x, 0.5f);
                    h = fmaf(h, x, 1.0f);
                    float dlt = x * h;
                    s[half][j] = dlt;
                    if (j < 2) sumd0 += dlt; else sumd1 += dlt;
                }
            }
            uint32_t A0 = packbf2(s[0][0], s[0][1]);
            uint32_t A1 = packbf2(s[0][2], s[0][3]);
            uint32_t A2 = packbf2(s[1][0], s[1][1]);
            uint32_t A3 = packbf2(s[1][2], s[1][3]);
            const int keyl2 = kk * 16 + (lane & 7) + ((lane >> 3) & 1) * 8;
            const int cb2 = ((lane >> 4) & 1) * 16;
#pragma unroll
            for (int nb2 = 0; nb2 < 4; nb2++) {
                uint32_t b[4];
                ldsm4t(b, vbase + swz128((uint32_t)(keyl2 * 128 + nb2 * 32 + cb2)));
                mma16816(oacc[2*nb2],     A0, A1, A2, A3, b[0], b[1]);
                mma16816(oacc[2*nb2 + 1], A0, A1, A2, A3, b[2], b[3]);
            }
        }
        if (t + 1 < 32) {
            cp_wait1();       // stage t+1 ready; t+2 may be in flight
            __syncthreads();
        }
        if (++buf == 3) buf = 0;
    }

    sumd0 += __shfl_xor_sync(0xffffffffu, sumd0, 1);
    sumd0 += __shfl_xor_sync(0xffffffffu, sumd0, 2);
    sumd1 += __shfl_xor_sync(0xffffffffu, sumd1, 1);
    sumd1 += __shfl_xor_sync(0xffffffffu, sumd1, 2);
    const float inv0 = 1.0f / (4096.0f + sumd0);
    const float inv1 = 1.0f / (4096.0f + sumd1);
    const int r0 = q0 + w * 16 + (lane >> 2);
    const int cbase = head * HD + (lane & 3) * 2;
#pragma unroll
    for (int nb = 0; nb < 8; nb++) {
        int d = cbase + nb * 8;
        float sv0 = vsum[d], sv1 = vsum[d + 1];
        ((uint32_t*)oh)[((size_t)r0 * HH + d) >> 1] =
            packbf2((sv0 + oacc[nb][0]) * inv0, (sv1 + oacc[nb][1]) * inv0);
        ((uint32_t*)oh)[((size_t)(r0 + 8) * HH + d) >> 1] =
            packbf2((sv0 + oacc[nb][2]) * inv1, (sv1 + oacc[nb][3]) * inv1);
    }
}

// ---------------- launch -----------------------------------------------------
extern "C" void kernel_launch(void* const* d_in, const int* in_sizes, int n_in,
                              void* d_out, int out_size)
{
    const float* text    = (const float*)d_in[0];
    const float* image   = (const float*)d_in[1];
    const int*   ei      = (const int*)d_in[2];
    const float* text_w  = (const float*)d_in[3];
    const float* text_b  = (const float*)d_in[4];
    const float* image_w = (const float*)d_in[5];
    const float* image_b = (const float*)d_in[6];
    const float* wq = (const float*)d_in[7];  const float* bq = (const float*)d_in[8];
    const float* wk = (const float*)d_in[9];  const float* bk = (const float*)d_in[10];
    const float* wv = (const float*)d_in[11]; const float* bv = (const float*)d_in[12];
    const float* wo = (const float*)d_in[13]; const float* bo = (const float*)d_in[14];
    const float* gcn1_w = (const float*)d_in[15]; const float* gcn1_b = (const float*)d_in[16];
    const float* gcn2_w = (const float*)d_in[17]; const float* gcn2_b = (const float*)d_in[18];
    const float* cls_w  = (const float*)d_in[19]; const float* cls_b  = (const float*)d_in[20];
    float* out = (float*)d_out;

    float *hb, *g1, *yb, *dinv, *vsum, *bg;
    __nv_bfloat16 *ch, *qbb, *kbb, *vbb, *obh, *g1h, *wth, *wtl;
    cudaGetSymbolAddress((void**)&hb, g_h);
    cudaGetSymbolAddress((void**)&g1, g_g1);
    cudaGetSymbolAddress((void**)&yb, g_y);
    cudaGetSymbolAddress((void**)&dinv, g_dinv);
    cudaGetSymbolAddress((void**)&vsum, g_vsum);
    cudaGetSymbolAddress((void**)&bg, g_bg);
    cudaGetSymbolAddress((void**)&ch, g_ch);
    cudaGetSymbolAddress((void**)&qbb, g_qb);
    cudaGetSymbolAddress((void**)&kbb, g_kb);
    cudaGetSymbolAddress((void**)&vbb, g_vb);
    cudaGetSymbolAddress((void**)&obh, g_obh);
    cudaGetSymbolAddress((void**)&g1h, g_g1h);
    cudaGetSymbolAddress((void**)&wth, g_wth);
    cudaGetSymbolAddress((void**)&wtl, g_wtl);

    // 1: weight prep + hist + WG=Wo@G1 + bG + zero(vsum, y)
    k_wprep_all<<<dim3(24, 8, 8), dim3(32, 32)>>>(
        text_w, image_w, wq, wk, wv, wo, gcn1_w, gcn2_w, bo, ei + EE);

    // 2: scan (start/cursor/dinv, re-zero cnt, bconst)
    k_scan<<<1, 1024>>>(gcn2_b, cls_w);

    // 3: fused text+image projection + scatter plane
    {
        static bool done = false;
        if (!done) {
            cudaFuncSetAttribute(gemm_fuse2,
                                 cudaFuncAttributeMaxDynamicSharedMemorySize, GEMM_SMEM);
            done = true;
        }
        gemm_fuse2<<<dim3(32, 5), 256, GEMM_SMEM>>>(
            text, image, wth + WOFF_TEXT, wtl + WOFF_TEXT,
            wth + WOFF_IMAGE, wtl + WOFF_IMAGE, text_b, image_b, ch,
            ei, ei + EE);
    }

    // 4: fused QKV (Q,K 1-pass; V 2-pass + vsum reds), 3-stage pipeline
    {
        static bool done = false;
        if (!done) {
            cudaFuncSetAttribute(gemm_qkv,
                                 cudaFuncAttributeMaxDynamicSharedMemorySize, GEMM_SMEM3);
            done = true;
        }
        gemm_qkv<<<dim3(32, 12), 256, GEMM_SMEM3>>>(
            ch, wth + WOFF_WQ, wtl + WOFF_WQ, bq, bk, bv, qbb, kbb, vbb, vsum);
    }

    // 5: attention (3-stage KV pipeline)
    cudaFuncSetAttribute(attn_mma, cudaFuncAttributeMaxDynamicSharedMemorySize,
                         SM_ATT_TOTAL);
    attn_mma<<<dim3(NN / 128, NHD), 256, SM_ATT_TOTAL>>>(qbb, kbb, vbb, vsum, obh);

    // 6: GCN1 GEMM with composed weights (h = ob@WG + bG; init = dinv^2*h + b1)
    {
        static bool done = false;
        if (!done) {
            cudaFuncSetAttribute(gemm_tc<6>,
                                 cudaFuncAttributeMaxDynamicSharedMemorySize, GEMM_SMEM3);
            done = true;
        }
        gemm_tc<6><<<dim3(32, 4), 256, GEMM_SMEM3>>>(
            obh, wth + WOFF_G1, wtl + WOFF_G1, bg, gcn1_b, dinv, hb, g1, HH);
    }

    // 7: GCN1 aggregation (gather) + relu -> bf16 hi
    k_agg1<<<NN * 32 / 256, 256>>>(hb, g1, g1h);

    // 8: GCN2 GEMM in classifier space (red into y)
    {
        static bool done = false;
        if (!done) {
            cudaFuncSetAttribute(gemm_tc<7>,
                                 cudaFuncAttributeMaxDynamicSharedMemorySize, GEMM_SMEM3);
            done = true;
        }
        gemm_tc<7><<<dim3(32, 4), 256, GEMM_SMEM3>>>(
            g1h, wth + WOFF_G2, wtl + WOFF_G2, cls_w, nullptr, nullptr,
            yb, nullptr, HH);
    }

    // 9: GCN2 aggregation on y + bias
    k_agg2y<<<NN * 32 / 256, 256>>>(yb, cls_b, out);
}

// round 14
// speedup vs baseline: 1.2011x; 1.0506x over previous
#include <cuda_runtime.h>
#include <cuda_bf16.h>
#include <cstdint>
#include <cstddef>

#define NN 4096
#define TD 768
#define ID 512
#define HH 256
#define NHD 4
#define HD 64
#define EE 131072
#define NC 3

// ---------------- scratch (static device globals; no allocation) -------------
__device__ float g_y[NN * 4];       // GCN2 h @ cls_w (padded to 4)
__device__ float g_dinv[NN];
__device__ float g_vsum[HH];
__device__ float g_bconst[3];
__device__ float g_bg[HH];          // bo @ G1
__device__ int   g_cnt[NN];         // zero at module load; re-zeroed by k_scan
__device__ int   g_start[NN + 1];
__device__ int   g_cursor[NN];
__device__ int   g_sorted[EE];
// bf16 activations (hi only)
__device__ __nv_bfloat16 g_ch[NN * HH];
__device__ __nv_bfloat16 g_qb[NN * HH];
__device__ __nv_bfloat16 g_kb[NN * HH];   // K for attention; then reused as GCN1 h
__device__ __nv_bfloat16 g_vb[NN * HH];
__device__ __nv_bfloat16 g_obh[NN * HH];
__device__ __nv_bfloat16 g_g1h[NN * HH];
// transposed+split weights [n][K] (hi + lo)
#define WOFF_TEXT  0
#define WOFF_IMAGE 196608
#define WOFF_WQ    327680
#define WOFF_WK    393216
#define WOFF_WV    458752
#define WOFF_G1    524288   /* holds WG = Wo@G1, composed */
#define WOFF_G2    589824
#define WTOT       655360
__device__ __nv_bfloat16 g_wth[WTOT], g_wtl[WTOT];

// =================== helpers =================================================
__device__ __forceinline__ uint32_t smem_u32(const void* p) {
    uint32_t a;
    asm("{ .reg .u64 t; cvta.to.shared.u64 t, %1; cvt.u32.u64 %0, t; }"
        : "=r"(a) : "l"(p));
    return a;
}
__device__ __forceinline__ uint32_t swz128(uint32_t o) { return o ^ ((o >> 3) & 0x70); }
__device__ __forceinline__ uint32_t swz64(uint32_t o)  { return o ^ ((o >> 3) & 0x30); }
__device__ __forceinline__ uint32_t packbf2(float x0, float x1) {
    uint32_t r;  // lo = x0, hi = x1
    asm("cvt.rn.satfinite.bf16x2.f32 %0, %1, %2;" : "=r"(r) : "f"(x1), "f"(x0));
    return r;
}
__device__ __forceinline__ void unpack2(uint32_t u, float& lo, float& hi) {
    lo = __uint_as_float(u << 16);
    hi = __uint_as_float(u & 0xFFFF0000u);
}
__device__ __forceinline__ void mma16816(float* c,
    uint32_t a0, uint32_t a1, uint32_t a2, uint32_t a3, uint32_t b0, uint32_t b1) {
    asm volatile("mma.sync.aligned.m16n8k16.row.col.f32.bf16.bf16.f32 "
        "{%0,%1,%2,%3}, {%4,%5,%6,%7}, {%8,%9}, {%0,%1,%2,%3};"
        : "+f"(c[0]), "+f"(c[1]), "+f"(c[2]), "+f"(c[3])
        : "r"(a0), "r"(a1), "r"(a2), "r"(a3), "r"(b0), "r"(b1));
}
__device__ __forceinline__ void ldsm4(uint32_t* r, uint32_t a) {
    asm volatile("ldmatrix.sync.aligned.m8n8.x4.shared.b16 {%0,%1,%2,%3}, [%4];"
        : "=r"(r[0]), "=r"(r[1]), "=r"(r[2]), "=r"(r[3]) : "r"(a));
}
__device__ __forceinline__ void ldsm4t(uint32_t* r, uint32_t a) {
    asm volatile("ldmatrix.sync.aligned.m8n8.x4.trans.shared.b16 {%0,%1,%2,%3}, [%4];"
        : "=r"(r[0]), "=r"(r[1]), "=r"(r[2]), "=r"(r[3]) : "r"(a));
}
__device__ __forceinline__ void cp16(uint32_t dst, const void* src) {
    asm volatile("cp.async.cg.shared.global [%0], [%1], 16;" :: "r"(dst), "l"(src) : "memory");
}
__device__ __forceinline__ void cp_commit() {
    asm volatile("cp.async.commit_group;" ::: "memory");
}
__device__ __forceinline__ void cp_wait0() {
    asm volatile("cp.async.wait_group 0;" ::: "memory");
}
__device__ __forceinline__ void cp_wait1() {
    asm volatile("cp.async.wait_group 1;" ::: "memory");
}
__device__ __forceinline__ void redf(float* p, float v) {
    asm volatile("red.global.add.f32 [%0], %1;" :: "l"(p), "f"(v) : "memory");
}

// ====== single-launch prep: weights + hist + WG compose + bG + zeroing =======
__global__ void k_wprep_all(
    const float* w0, const float* w1, const float* w2, const float* w3,
    const float* w4, const float* wo, const float* g1w, const float* w7,
    const float* bo, const int* __restrict__ edst)
{
    const int z = blockIdx.z;
    const int tx = threadIdx.x, ty = threadIdx.y;
    if (z == 5) {
        int flat = (blockIdx.y * 24 + blockIdx.x) * 1024 + ty * 32 + tx;
        if (flat < EE) atomicAdd(&g_cnt[edst[flat]], 1);
        return;
    }
    if (z == 6) {
        if (blockIdx.x < 8) {
            int k0 = blockIdx.x * 32, n0 = blockIdx.y * 32;
            __shared__ float sW[32][33], sG[32][33];
            float acc = 0.f;
            for (int j0 = 0; j0 < HH; j0 += 32) {
                sW[ty][tx] = wo[(size_t)(k0 + ty) * HH + j0 + tx];
                sG[ty][tx] = g1w[(size_t)(j0 + ty) * HH + n0 + tx];
                __syncthreads();
#pragma unroll
                for (int jj = 0; jj < 32; jj++)
                    acc = fmaf(sW[tx][jj], sG[jj][ty], acc);
                __syncthreads();
            }
            __nv_bfloat16 h = __float2bfloat16(acc);
            __nv_bfloat16 l = __float2bfloat16(acc - __bfloat162float(h));
            size_t idx = (size_t)WOFF_G1 + (size_t)(n0 + ty) * HH + k0 + tx;
            g_wth[idx] = h;
            g_wtl[idx] = l;
        } else if (blockIdx.x == 8) {
            if (blockIdx.y == 0) {
                int t = ty * 32 + tx;
                if (t < HH) {
                    float s = 0.f;
                    for (int j = 0; j < HH; j++)
                        s = fmaf(bo[j], g1w[(size_t)j * HH + t], s);
                    g_bg[t] = s;
                }
            }
        } else if (blockIdx.x == 9) {
            int flat = blockIdx.y * 1024 + ty * 32 + tx;
            for (int i = flat; i < NN * 4 + HH; i += 8192) {
                if (i < NN * 4) g_y[i] = 0.f;
                else g_vsum[i - NN * 4] = 0.f;
            }
        }
        return;
    }
    const float* W; int K, off;
    switch (z) {
        case 0: W = w0; K = TD; off = WOFF_TEXT; break;
        case 1: W = w1; K = ID; off = WOFF_IMAGE; break;
        case 2: W = w2; K = HH; off = WOFF_WQ; break;
        case 3: W = w3; K = HH; off = WOFF_WK; break;
        case 4: W = w4; K = HH; off = WOFF_WV; break;
        default: W = w7; K = HH; off = WOFF_G2; break;
    }
    int k0 = blockIdx.x * 32;
    if (k0 >= K) return;
    int n0 = blockIdx.y * 32;
    __shared__ float t[32][33];
    t[ty][tx] = W[(size_t)(k0 + ty) * HH + n0 + tx];
    __syncthreads();
    float v = t[tx][ty];
    __nv_bfloat16 h = __float2bfloat16(v);
    __nv_bfloat16 l = __float2bfloat16(v - __bfloat162float(h));
    size_t idx = (size_t)off + (size_t)(n0 + ty) * K + k0 + tx;
    g_wth[idx] = h;
    g_wtl[idx] = l;
}

// 1 CTA, 1024 threads: prefix-scan cnt -> start/cursor, dinv; re-zero cnt;
// bconst = gcn2_b @ cls_w.
__global__ void k_scan(const float* __restrict__ b2, const float* __restrict__ cw)
{
    __shared__ int wsum[32];
    const int t = threadIdx.x, lane = t & 31, wid = t >> 5;
    if (t < 3) {
        float s = 0.f;
        for (int j = 0; j < HH; j++) s = fmaf(b2[j], cw[j * 3 + t], s);
        g_bconst[t] = s;
    }
    const int base = t * 4;
    int c0 = g_cnt[base], c1 = g_cnt[base + 1], c2 = g_cnt[base + 2], c3 = g_cnt[base + 3];
    int s = c0 + c1 + c2 + c3;
    int v = s;
#pragma unroll
    for (int off = 1; off < 32; off <<= 1) {
        int u = __shfl_up_sync(0xffffffffu, v, off);
        if (lane >= off) v += u;
    }
    if (lane == 31) wsum[wid] = v;
    __syncthreads();
    if (wid == 0) {
        int x = wsum[lane];
#pragma unroll
        for (int off = 1; off < 32; off <<= 1) {
            int u = __shfl_up_sync(0xffffffffu, x, off);
            if (lane >= off) x += u;
        }
        wsum[lane] = x;
    }
    __syncthreads();
    int excl = v - s + (wid > 0 ? wsum[wid - 1] : 0);
    int e0 = excl, e1 = e0 + c0, e2 = e1 + c1, e3 = e2 + c2;
    g_start[base] = e0;  g_cursor[base] = e0;
    g_start[base + 1] = e1; g_cursor[base + 1] = e1;
    g_start[base + 2] = e2; g_cursor[base + 2] = e2;
    g_start[base + 3] = e3; g_cursor[base + 3] = e3;
    g_dinv[base]     = rsqrtf((float)(c0 + 1));
    g_dinv[base + 1] = rsqrtf((float)(c1 + 1));
    g_dinv[base + 2] = rsqrtf((float)(c2 + 1));
    g_dinv[base + 3] = rsqrtf((float)(c3 + 1));
    g_cnt[base] = 0; g_cnt[base + 1] = 0; g_cnt[base + 2] = 0; g_cnt[base + 3] = 0;
    if (t == 1023) g_start[NN] = e3 + c3;
}

// ====== GCN layer-1 aggregation: warp per dst, bf16 gather ==================
// out = relu(dinv[d]^2 * h[d] + b1 + sum coef*h[src]) -> bf16
__global__ void __launch_bounds__(256) k_agg1(
    const __nv_bfloat16* __restrict__ h, const float* __restrict__ b1,
    __nv_bfloat16* __restrict__ oh)
{
    const int dstn = (blockIdx.x * 256 + threadIdx.x) >> 5;
    const int lane = threadIdx.x & 31;
    if (dstn >= NN) return;
    const int beg = g_start[dstn], end = g_start[dstn + 1];
    const float dd = g_dinv[dstn];

    float acc[8];
    {
        uint4 u = __ldg((const uint4*)(h + (size_t)dstn * HH) + lane);
        const float c2 = dd * dd;
        const float* bb = b1 + lane * 8;
        float f0, f1;
        unpack2(u.x, f0, f1); acc[0] = fmaf(c2, f0, bb[0]); acc[1] = fmaf(c2, f1, bb[1]);
        unpack2(u.y, f0, f1); acc[2] = fmaf(c2, f0, bb[2]); acc[3] = fmaf(c2, f1, bb[3]);
        unpack2(u.z, f0, f1); acc[4] = fmaf(c2, f0, bb[4]); acc[5] = fmaf(c2, f1, bb[5]);
        unpack2(u.w, f0, f1); acc[6] = fmaf(c2, f0, bb[6]); acc[7] = fmaf(c2, f1, bb[7]);
    }
    for (int e = beg; e < end; e += 32) {
        int n = end - e; if (n > 32) n = 32;
        int sidx = 0; float dv = 0.f;
        if (lane < n) {
            sidx = __ldg(&g_sorted[e + lane]);
            dv = __ldg(&g_dinv[sidx]);
        }
#pragma unroll 4
        for (int j = 0; j < n; j++) {
            int s = __shfl_sync(0xffffffffu, sidx, j);
            float cf = __shfl_sync(0xffffffffu, dv, j) * dd;
            uint4 u = __ldg((const uint4*)(h + ((size_t)s << 8)) + lane);
            float f0, f1;
            unpack2(u.x, f0, f1); acc[0] = fmaf(cf, f0, acc[0]); acc[1] = fmaf(cf, f1, acc[1]);
            unpack2(u.y, f0, f1); acc[2] = fmaf(cf, f0, acc[2]); acc[3] = fmaf(cf, f1, acc[3]);
            unpack2(u.z, f0, f1); acc[4] = fmaf(cf, f0, acc[4]); acc[5] = fmaf(cf, f1, acc[5]);
            unpack2(u.w, f0, f1); acc[6] = fmaf(cf, f0, acc[6]); acc[7] = fmaf(cf, f1, acc[7]);
        }
    }
#pragma unroll
    for (int p = 0; p < 4; p++) {
        float x = fmaxf(acc[2 * p], 0.f), y = fmaxf(acc[2 * p + 1], 0.f);
        ((uint32_t*)oh)[((size_t)dstn * HH + lane * 8 + 2 * p) >> 1] = packbf2(x, y);
    }
}

// ====== GCN layer-2 aggregation on y[4] (classifier space) ===================
__global__ void __launch_bounds__(256) k_agg2y(
    const float* __restrict__ y, const float* __restrict__ cls_b,
    float* __restrict__ out)
{
    const int d = (blockIdx.x * 256 + threadIdx.x) >> 5;
    const int lane = threadIdx.x & 31;
    if (d >= NN) return;
    const int beg = g_start[d], end = g_start[d + 1];
    float a0 = 0.f, a1 = 0.f, a2 = 0.f;
    for (int e = beg + lane; e < end; e += 32) {
        int s = __ldg(&g_sorted[e]);
        float dv = __ldg(&g_dinv[s]);
        float4 yv = *(const float4*)(y + s * 4);
        a0 = fmaf(dv, yv.x, a0);
        a1 = fmaf(dv, yv.y, a1);
        a2 = fmaf(dv, yv.z, a2);
    }
#pragma unroll
    for (int off = 16; off > 0; off >>= 1) {
        a0 += __shfl_xor_sync(0xffffffffu, a0, off);
        a1 += __shfl_xor_sync(0xffffffffu, a1, off);
        a2 += __shfl_xor_sync(0xffffffffu, a2, off);
    }
    if (lane == 0) {
        float dd = g_dinv[d];
        float4 yd = *(const float4*)(y + d * 4);
        out[d * 3 + 0] = fmaf(dd, fmaf(dd, yd.x, a0), g_bconst[0] + cls_b[0]);
        out[d * 3 + 1] = fmaf(dd, fmaf(dd, yd.y, a1), g_bconst[1] + cls_b[1]);
        out[d * 3 + 2] = fmaf(dd, fmaf(dd, yd.z, a2), g_bconst[2] + cls_b[2]);
    }
}

// =============== HMMA GEMM cores =============================================
// 64-wide K chunks, 3-stage cp.async pipeline. Stage = A 16KB + W 16KB = 32KB.
#define GST64 32768
#define G64W  16384
#define GEMM_SMEM3 98304
// f32 core: 2-stage, 24KB/stage
#define GST 24576
#define GS_W  16384
#define GS_WL 20480
#define GEMM_SMEM 49152

// NPASS: 2 = AhWh + AhWl, 1 = AhWh only.
template<int NPASS>
__device__ __forceinline__ void gemm_core_bf16(
    uint32_t sb, int tid, int m0, int n0,
    const __nv_bfloat16* A0,
    const __nv_bfloat16* WTh, const __nv_bfloat16* WTl,
    int K, float acc[8][4])
{
    const int w = tid >> 5, lane = tid & 31;
    const int rowa = w * 16 + (lane & 7) + ((lane >> 3) & 1) * 8;
    const int acb  = ((lane >> 4) & 1) * 16;
    const int nrow = lane & 7;
    const int bcb  = ((lane >> 3) & 3) * 16;
    const int nch = K >> 6;

    auto load_st = [&](int kc, int st) {
        int k0 = kc << 6;
        uint32_t base = sb + st * GST64;
#pragma unroll
        for (int j = 0; j < 4; j++) {      // A: 128 rows x 128B
            int flat = tid + j * 256;
            int r = flat >> 3, c = flat & 7;
            const char* src = (const char*)A0 +
                              (((size_t)(m0 + r) * K + k0) << 1) + c * 16;
            cp16(base + swz128((uint32_t)(r * 128 + c * 16)), src);
        }
#pragma unroll
        for (int p = 0; p < NPASS; p++) {  // W: 64 rows x 128B per part
#pragma unroll
            for (int j = 0; j < 2; j++) {
                int flat = tid + j * 256;
                int r = flat >> 3, c = flat & 7;
                const char* src = (const char*)(p ? WTl : WTh) +
                                  (((size_t)(n0 + r) * K + k0) << 1) + c * 16;
                cp16(base + G64W + p * 8192 + swz128((uint32_t)(r * 128 + c * 16)), src);
            }
        }
        cp_commit();
    };
    auto compute = [&](int st) {
        uint32_t base = sb + st * GST64;
#pragma unroll
        for (int s = 0; s < 2; s++) {
            uint32_t ah[2][4];
#pragma unroll
            for (int kk2 = 0; kk2 < 2; kk2++)
                ldsm4(ah[kk2], base + swz128((uint32_t)(rowa * 128 + s * 64 +
                                                        kk2 * 32 + acb)));
#pragma unroll
            for (int nb = 0; nb < 8; nb++) {
                uint32_t bo = (uint32_t)((nb * 8 + nrow) * 128 + s * 64 + bcb);
                uint32_t bh[4];
                ldsm4(bh, base + G64W + swz128(bo));
                mma16816(acc[nb], ah[0][0], ah[0][1], ah[0][2], ah[0][3], bh[0], bh[1]);
                mma16816(acc[nb], ah[1][0], ah[1][1], ah[1][2], ah[1][3], bh[2], bh[3]);
                if (NPASS == 2) {
                    uint32_t bl[4];
                    ldsm4(bl, base + G64W + 8192 + swz128(bo));
                    mma16816(acc[nb], ah[0][0], ah[0][1], ah[0][2], ah[0][3], bl[0], bl[1]);
                    mma16816(acc[nb], ah[1][0], ah[1][1], ah[1][2], ah[1][3], bl[2], bl[3]);
                }
            }
        }
    };

    load_st(0, 0);
    load_st(1, 1);
    cp_wait1();
    __syncthreads();
    int st = 0;
    for (int kc = 0; kc < nch; kc++) {
        if (kc + 2 < nch) {
            int s2 = st + 2; if (s2 >= 3) s2 -= 3;
            load_st(kc + 2, s2);
        }
        compute(st);
        if (kc + 1 < nch) {
            if (kc + 2 < nch) cp_wait1(); else cp_wait0();
            __syncthreads();
        }
        if (++st == 3) st = 0;
    }
}

// fp32-A core: 2-pass (AhWh + AhWl); 2-stage; 32-wide chunks (unchanged).
__device__ __forceinline__ void gemm_core_f32(
    char* smc, uint32_t sb, int tid, int m0, int n0,
    const float* A, const __nv_bfloat16* WTh, const __nv_bfloat16* WTl,
    int K, float acc[8][4])
{
    const int w = tid >> 5, lane = tid & 31;
    const int rowa = w * 16 + (lane & 7) + ((lane >> 3) & 1) * 8;
    const int acb  = ((lane >> 4) & 1) * 16;
    const int nrow = lane & 7;
    const int bcb  = ((lane >> 3) & 3) * 16;
    const int nch = K >> 5;
    float4 ar[4];

    auto load_w = [&](int kc, int st) {
        int k0 = kc << 5;
        uint32_t base = sb + st * GST + GS_W;
#pragma unroll
        for (int j = 0; j < 2; j++) {
            int flat = tid + j * 256;
            int part = flat >> 8, r = (flat >> 2) & 63, c = flat & 3;
            const char* src = (const char*)(part ? WTl : WTh) +
                              (((size_t)(n0 + r) * K + k0) << 1) + c * 16;
            cp16(base + part * 4096 + swz64((uint32_t)(r * 64 + c * 16)), src);
        }
    };
    auto ldg_a = [&](int kc) {
        int k0 = kc << 5;
#pragma unroll
        for (int j = 0; j < 4; j++) {
            int flat = tid + j * 256;
            int r = flat >> 3, c = flat & 7;
            ar[j] = *(const float4*)(A + (size_t)(m0 + r) * K + k0 + c * 4);
        }
    };
    auto sts_a = [&](int st) {
        uint32_t off0 = st * GST;
#pragma unroll
        for (int j = 0; j < 4; j++) {
            int flat = tid + j * 256;
            int r = flat >> 3, c = flat & 7;
            uint32_t off = swz64((uint32_t)(r * 64 + c * 8));
            uint32_t h0 = packbf2(ar[j].x, ar[j].y);
            uint32_t h1 = packbf2(ar[j].z, ar[j].w);
            *(uint2*)(smc + off0 + off) = make_uint2(h0, h1);
        }
    };
    auto compute = [&](int st) {
        uint32_t base = sb + st * GST;
        uint32_t ah[2][4];
#pragma unroll
        for (int kk2 = 0; kk2 < 2; kk2++)
            ldsm4(ah[kk2], base + swz64((uint32_t)(rowa * 64 + kk2 * 32 + acb)));
#pragma unroll
        for (int nb = 0; nb < 8; nb++) {
            uint32_t bo = swz64((uint32_t)((nb * 8 + nrow) * 64 + bcb));
            uint32_t bh[4], bl[4];
            ldsm4(bh, base + GS_W + bo);
            ldsm4(bl, base + GS_WL + bo);
            mma16816(acc[nb], ah[0][0], ah[0][1], ah[0][2], ah[0][3], bh[0], bh[1]);
            mma16816(acc[nb], ah[1][0], ah[1][1], ah[1][2], ah[1][3], bh[2], bh[3]);
            mma16816(acc[nb], ah[0][0], ah[0][1], ah[0][2], ah[0][3], bl[0], bl[1]);
            mma16816(acc[nb], ah[1][0], ah[1][1], ah[1][2], ah[1][3], bl[2], bl[3]);
        }
    };

    ldg_a(0); load_w(0, 0); cp_commit(); sts_a(0); cp_wait0();
    __syncthreads();
    for (int kc = 0; kc < nch; kc++) {
        if (kc + 1 < nch) {
            ldg_a(kc + 1);
            load_w(kc + 1, (kc + 1) & 1);
            cp_commit();
        }
        compute(kc & 1);
        if (kc + 1 < nch) {
            sts_a((kc + 1) & 1);
            cp_wait0();
            __syncthreads();
        }
    }
}

// fused text+image projection + edge-scatter plane (blockIdx.y == 4)
__global__ void __launch_bounds__(256, 2) gemm_fuse2(
    const float* __restrict__ text, const float* __restrict__ image,
    const __nv_bfloat16* __restrict__ Wth, const __nv_bfloat16* __restrict__ Wtl,
    const __nv_bfloat16* __restrict__ Wih, const __nv_bfloat16* __restrict__ Wil,
    const float* __restrict__ tb, const float* __restrict__ ib,
    __nv_bfloat16* __restrict__ ch,
    const int* __restrict__ esrc, const int* __restrict__ edst)
{
    if (blockIdx.y == 4) {
        int base = (blockIdx.x * 256 + threadIdx.x) * 16;
        int4 d4[4], s4[4];
#pragma unroll
        for (int i = 0; i < 4; i++) {
            d4[i] = *(const int4*)(edst + base + i * 4);
            s4[i] = *(const int4*)(esrc + base + i * 4);
        }
#pragma unroll
        for (int i = 0; i < 4; i++) {
            const int dd[4] = {d4[i].x, d4[i].y, d4[i].z, d4[i].w};
            const int ss[4] = {s4[i].x, s4[i].y, s4[i].z, s4[i].w};
#pragma unroll
            for (int j = 0; j < 4; j++) {
                int pos = atomicAdd(&g_cursor[dd[j]], 1);
                g_sorted[pos] = ss[j];
            }
        }
        return;
    }
    extern __shared__ char sm[];
    const uint32_t sb = smem_u32(sm);
    const int tid = threadIdx.x, w = tid >> 5, lane = tid & 31;
    const int m0 = blockIdx.x * 128, n0 = blockIdx.y * 64;

    float acc[8][4] = {};
    gemm_core_f32(sm, sb, tid, m0, n0, text, Wth, Wtl, TD, acc);
    float rf[8][4];
#pragma unroll
    for (int nb = 0; nb < 8; nb++) {
        const int cg = n0 + (lane & 3) * 2 + nb * 8;
        float b0 = tb[cg], b1 = tb[cg + 1];
        rf[nb][0] = fmaxf(acc[nb][0] + b0, 0.f);
        rf[nb][1] = fmaxf(acc[nb][1] + b1, 0.f);
        rf[nb][2] = fmaxf(acc[nb][2] + b0, 0.f);
        rf[nb][3] = fmaxf(acc[nb][3] + b1, 0.f);
        acc[nb][0] = acc[nb][1] = acc[nb][2] = acc[nb][3] = 0.f;
    }
    __syncthreads();
    gemm_core_f32(sm, sb, tid, m0, n0, image, Wih, Wil, ID, acc);

    const int r0 = m0 + w * 16 + (lane >> 2);
#pragma unroll
    for (int nb = 0; nb < 8; nb++) {
        const int cg = n0 + (lane & 3) * 2 + nb * 8;
        float b0 = ib[cg], b1 = ib[cg + 1];
        const size_t i0 = (size_t)r0 * HH + cg;
        const size_t i1 = (size_t)(r0 + 8) * HH + cg;
        ((uint32_t*)ch)[i0 >> 1] = packbf2(rf[nb][0] + fmaxf(acc[nb][0] + b0, 0.f),
                                           rf[nb][1] + fmaxf(acc[nb][1] + b1, 0.f));
        ((uint32_t*)ch)[i1 >> 1] = packbf2(rf[nb][2] + fmaxf(acc[nb][2] + b0, 0.f),
                                           rf[nb][3] + fmaxf(acc[nb][3] + b1, 0.f));
    }
}

// general GEMM kernel (bf16-A hi, 2-pass), epilogues:
// EPI 2: bias -> bf16 out0 (GCN1 h)
// EPI 7: y-partials: red out0 += acc@cls_w (bias = cls_w)
template<int EPI>
__global__ void __launch_bounds__(256, 2) gemm_tc(
    const __nv_bfloat16* __restrict__ A0,
    const __nv_bfloat16* __restrict__ WTh, const __nv_bfloat16* __restrict__ WTl,
    const float* __restrict__ bias,
    void* out0v, int K)
{
    extern __shared__ char sm[];
    const uint32_t sb = smem_u32(sm);
    const int tid = threadIdx.x, w = tid >> 5, lane = tid & 31;
    const int m0 = blockIdx.x * 128, n0 = blockIdx.y * 64;
    float acc[8][4] = {};
    gemm_core_bf16<2>(sb, tid, m0, n0, A0, WTh, WTl, K, acc);

    const int r0 = m0 + w * 16 + (lane >> 2);
    if (EPI == 7) {
        const float* cw = bias;
        float p0[3] = {0.f, 0.f, 0.f}, p1[3] = {0.f, 0.f, 0.f};
#pragma unroll
        for (int nb = 0; nb < 8; nb++) {
            const int cg = n0 + (lane & 3) * 2 + nb * 8;
#pragma unroll
            for (int c = 0; c < 3; c++) {
                float w0 = __ldg(cw + cg * 3 + c), w1 = __ldg(cw + (cg + 1) * 3 + c);
                p0[c] = fmaf(acc[nb][0], w0, fmaf(acc[nb][1], w1, p0[c]));
                p1[c] = fmaf(acc[nb][2], w0, fmaf(acc[nb][3], w1, p1[c]));
            }
        }
#pragma unroll
        for (int c = 0; c < 3; c++) {
            p0[c] += __shfl_xor_sync(0xffffffffu, p0[c], 1);
            p0[c] += __shfl_xor_sync(0xffffffffu, p0[c], 2);
            p1[c] += __shfl_xor_sync(0xffffffffu, p1[c], 1);
            p1[c] += __shfl_xor_sync(0xffffffffu, p1[c], 2);
        }
        if ((lane & 3) == 0) {
            float* y = (float*)out0v;
#pragma unroll
            for (int c = 0; c < 3; c++) {
                redf(y + r0 * 4 + c, p0[c]);
                redf(y + (r0 + 8) * 4 + c, p1[c]);
            }
        }
        return;
    }
    // EPI 2
#pragma unroll
    for (int nb = 0; nb < 8; nb++) {
        const int cg = n0 + (lane & 3) * 2 + nb * 8;
        float b0 = bias[cg], b1 = bias[cg + 1];
        const size_t i0 = (size_t)r0 * HH + cg;
        const size_t i1 = (size_t)(r0 + 8) * HH + cg;
        ((uint32_t*)out0v)[i0 >> 1] = packbf2(acc[nb][0] + b0, acc[nb][1] + b1);
        ((uint32_t*)out0v)[i1 >> 1] = packbf2(acc[nb][2] + b0, acc[nb][3] + b1);
    }
}

// fused QKV GEMM: grid (32, 12); sel = blockIdx.y>>2.
// Q,K: 1-pass; V: 2-pass + vsum reds.
__global__ void __launch_bounds__(256, 2) gemm_qkv(
    const __nv_bfloat16* __restrict__ A0,
    const __nv_bfloat16* __restrict__ WTbase, const __nv_bfloat16* __restrict__ WLbase,
    const float* __restrict__ bq, const float* __restrict__ bk,
    const float* __restrict__ bv,
    __nv_bfloat16* __restrict__ oq, __nv_bfloat16* __restrict__ ok,
    __nv_bfloat16* __restrict__ ov, float* __restrict__ vsum)
{
    extern __shared__ char sm[];
    const uint32_t sb = smem_u32(sm);
    const int tid = threadIdx.x, w = tid >> 5, lane = tid & 31;
    const int sel = blockIdx.y >> 2;
    const int m0 = blockIdx.x * 128, n0 = (blockIdx.y & 3) * 64;
    const __nv_bfloat16* WTh = WTbase + (size_t)sel * HH * HH;
    const __nv_bfloat16* WTl = WLbase + (size_t)sel * HH * HH;
    const float* bias = sel == 0 ? bq : (sel == 1 ? bk : bv);
    __nv_bfloat16* out = sel == 0 ? oq : (sel == 1 ? ok : ov);

    float acc[8][4] = {};
    if (sel == 2) gemm_core_bf16<2>(sb, tid, m0, n0, A0, WTh, WTl, HH, acc);
    else          gemm_core_bf16<1>(sb, tid, m0, n0, A0, WTh, WTl, HH, acc);

    const int r0 = m0 + w * 16 + (lane >> 2);
#pragma unroll
    for (int nb = 0; nb < 8; nb++) {
        const int cg = n0 + (lane & 3) * 2 + nb * 8;
        float b0 = bias[cg], b1 = bias[cg + 1];
        float v00 = acc[nb][0] + b0, v01 = acc[nb][1] + b1;
        float v10 = acc[nb][2] + b0, v11 = acc[nb][3] + b1;
        const size_t i0 = (size_t)r0 * HH + cg;
        const size_t i1 = (size_t)(r0 + 8) * HH + cg;
        ((uint32_t*)out)[i0 >> 1] = packbf2(v00, v01);
        ((uint32_t*)out)[i1 >> 1] = packbf2(v10, v11);
        if (sel == 2) {
            float s0 = v00 + v10, s1 = v01 + v11;
#pragma unroll
            for (int off = 4; off < 32; off <<= 1) {
                s0 += __shfl_xor_sync(0xffffffffu, s0, off);
                s1 += __shfl_xor_sync(0xffffffffu, s1, off);
            }
            if (lane < 4) {
                redf(vsum + cg, s0);
                redf(vsum + cg + 1, s1);
            }
        }
    }
}

// ============== HMMA flash attention: 128 q-rows x 1 head per CTA ============
// 3-stage K/V pipeline: 3 x 32KB KV buffers + 16KB Q = 112KB smem.
#define SM_BUFSTRIDE 32768
#define SM_VOFF 16384
#define SM_Q 98304
#define SM_ATT_TOTAL 114688

__device__ __forceinline__ void load_kv_tile(
    uint32_t sb, int buf, int kt, int head,
    const __nv_bfloat16* kb, const __nv_bfloat16* vb, int tid)
{
    const char* kc = (const char*)kb;
    const char* vc = (const char*)vb;
#pragma unroll
    for (int j = 0; j < 8; j++) {
        int flat = tid + j * 256;
        int arr = flat >> 10;
        int row = (flat >> 3) & 127;
        int c = flat & 7;
        const char* src = (arr ? vc : kc) +
            (((size_t)(kt + row) * HH + head * HD) << 1) + c * 16;
        uint32_t dst = sb + buf * SM_BUFSTRIDE + arr * SM_VOFF +
                       swz128((uint32_t)(row * 128 + c * 16));
        cp16(dst, src);
    }
}

__global__ void __launch_bounds__(256, 1) attn_mma(
    const __nv_bfloat16* __restrict__ qb, const __nv_bfloat16* __restrict__ kb,
    const __nv_bfloat16* __restrict__ vb, const float* __restrict__ vsum,
    __nv_bfloat16* __restrict__ oh)
{
    extern __shared__ char sm[];
    const uint32_t sb = smem_u32(sm);
    const int tid = threadIdx.x, w = tid >> 5, lane = tid & 31;
    const int q0 = blockIdx.x * 128, head = blockIdx.y;

    {
        const char* qc = (const char*)qb;
#pragma unroll
        for (int j = 0; j < 4; j++) {
            int flat = tid + j * 256;
            int row = flat >> 3, c = flat & 7;
            const char* src = qc + (((size_t)(q0 + row) * HH + head * HD) << 1) + c * 16;
            cp16(sb + SM_Q + swz128((uint32_t)(row * 128 + c * 16)), src);
        }
        load_kv_tile(sb, 0, 0, head, kb, vb, tid);
        cp_commit();
        load_kv_tile(sb, 1, 128, head, kb, vb, tid);
        cp_commit();
        cp_wait1();
        __syncthreads();
    }

    uint32_t qa[4][4];
    {
        const int rowa = w * 16 + (lane & 7) + ((lane >> 3) & 1) * 8;
        const int cb = ((lane >> 4) & 1) * 16;
#pragma unroll
        for (int kk = 0; kk < 4; kk++)
            ldsm4(qa[kk], sb + SM_Q + swz128((uint32_t)(rowa * 128 + kk * 32 + cb)));
    }

    float oacc[8][4] = {};
    float sumd0 = 0.f, sumd1 = 0.f;

    int buf = 0;
    for (int t = 0; t < 32; t++) {
        const uint32_t kbase = sb + buf * SM_BUFSTRIDE;
        const uint32_t vbase = kbase + SM_VOFF;
        if (t + 2 < 32) {
            int b2 = buf + 2; if (b2 >= 3) b2 -= 3;
            load_kv_tile(sb, b2, (t + 2) * 128, head, kb, vb, tid);
            cp_commit();
        }
#pragma unroll 2
        for (int kk = 0; kk < 8; kk++) {
            float s[2][4] = {{0.f,0.f,0.f,0.f},{0.f,0.f,0.f,0.f}};
#pragma unroll
            for (int half = 0; half < 2; half++) {
                const int keyl = kk * 16 + half * 8 + (lane & 7);
#pragma unroll
                for (int kk2 = 0; kk2 < 2; kk2++) {
                    uint32_t b[4];
                    ldsm4(b, kbase + swz128((uint32_t)(keyl * 128 + kk2 * 64 +
                                                       ((lane >> 3) & 3) * 16)));
                    mma16816(s[half], qa[2*kk2][0], qa[2*kk2][1], qa[2*kk2][2],
                             qa[2*kk2][3], b[0], b[1]);
                    mma16816(s[half], qa[2*kk2+1][0], qa[2*kk2+1][1], qa[2*kk2+1][2],
                             qa[2*kk2+1][3], b[2], b[3]);
                }
            }
#pragma unroll
            for (int half = 0; half < 2; half++) {
#pragma unroll
                for (int j = 0; j < 4; j++) {
                    float x = s[half][j] * 0.125f;
                    float h = fmaf(x, 4.166666667e-2f, 0.166666667f);
                    h = fmaf(h, x, 0.5f);
                    h = fmaf(h, x, 1.0f);
                    float dlt = x * h;
                    s[half][j] = dlt;
                    if (j < 2) sumd0 += dlt; else sumd1 += dlt;
                }
            }
            uint32_t A0 = packbf2(s[0][0], s[0][1]);
            uint32_t A1 = packbf2(s[0][2], s[0][3]);
            uint32_t A2 = packbf2(s[1][0], s[1][1]);
            uint32_t A3 = packbf2(s[1][2], s[1][3]);
            const int keyl2 = kk * 16 + (lane & 7) + ((lane >> 3) & 1) * 8;
            const int cb2 = ((lane >> 4) & 1) * 16;
#pragma unroll
            for (int nb2 = 0; nb2 < 4; nb2++) {
                uint32_t b[4];
                ldsm4t(b, vbase + swz128((uint32_t)(keyl2 * 128 + nb2 * 32 + cb2)));
                mma16816(oacc[2*nb2],     A0, A1, A2, A3, b[0], b[1]);
                mma16816(oacc[2*nb2 + 1], A0, A1, A2, A3, b[2], b[3]);
            }
        }
        if (t + 1 < 32) {
            if (t + 2 < 32) cp_wait1(); else cp_wait0();
            __syncthreads();
        }
        if (++buf == 3) buf = 0;
    }

    sumd0 += __shfl_xor_sync(0xffffffffu, sumd0, 1);
    sumd0 += __shfl_xor_sync(0xffffffffu, sumd0, 2);
    sumd1 += __shfl_xor_sync(0xffffffffu, sumd1, 1);
    sumd1 += __shfl_xor_sync(0xffffffffu, sumd1, 2);
    const float inv0 = 1.0f / (4096.0f + sumd0);
    const float inv1 = 1.0f / (4096.0f + sumd1);
    const int r0 = q0 + w * 16 + (lane >> 2);
    const int cbase = head * HD + (lane & 3) * 2;
#pragma unroll
    for (int nb = 0; nb < 8; nb++) {
        int d = cbase + nb * 8;
        float sv0 = vsum[d], sv1 = vsum[d + 1];
        ((uint32_t*)oh)[((size_t)r0 * HH + d) >> 1] =
            packbf2((sv0 + oacc[nb][0]) * inv0, (sv1 + oacc[nb][1]) * inv0);
        ((uint32_t*)oh)[((size_t)(r0 + 8) * HH + d) >> 1] =
            packbf2((sv0 + oacc[nb][2]) * inv1, (sv1 + oacc[nb][3]) * inv1);
    }
}

// ---------------- launch -----------------------------------------------------
extern "C" void kernel_launch(void* const* d_in, const int* in_sizes, int n_in,
                              void* d_out, int out_size)
{
    const float* text    = (const float*)d_in[0];
    const float* image   = (const float*)d_in[1];
    const int*   ei      = (const int*)d_in[2];
    const float* text_w  = (const float*)d_in[3];
    const float* text_b  = (const float*)d_in[4];
    const float* image_w = (const float*)d_in[5];
    const float* image_b = (const float*)d_in[6];
    const float* wq = (const float*)d_in[7];  const float* bq = (const float*)d_in[8];
    const float* wk = (const float*)d_in[9];  const float* bk = (const float*)d_in[10];
    const float* wv = (const float*)d_in[11]; const float* bv = (const float*)d_in[12];
    const float* wo = (const float*)d_in[13]; const float* bo = (const float*)d_in[14];
    const float* gcn1_w = (const float*)d_in[15]; const float* gcn1_b = (const float*)d_in[16];
    const float* gcn2_w = (const float*)d_in[17]; const float* gcn2_b = (const float*)d_in[18];
    const float* cls_w  = (const float*)d_in[19]; const float* cls_b  = (const float*)d_in[20];
    float* out = (float*)d_out;

    float *yb, *dinv, *vsum, *bg;
    __nv_bfloat16 *ch, *qbb, *kbb, *vbb, *obh, *g1h, *wth, *wtl;
    cudaGetSymbolAddress((void**)&yb, g_y);
    cudaGetSymbolAddress((void**)&dinv, g_dinv);
    cudaGetSymbolAddress((void**)&vsum, g_vsum);
    cudaGetSymbolAddress((void**)&bg, g_bg);
    cudaGetSymbolAddress((void**)&ch, g_ch);
    cudaGetSymbolAddress((void**)&qbb, g_qb);
    cudaGetSymbolAddress((void**)&kbb, g_kb);
    cudaGetSymbolAddress((void**)&vbb, g_vb);
    cudaGetSymbolAddress((void**)&obh, g_obh);
    cudaGetSymbolAddress((void**)&g1h, g_g1h);
    cudaGetSymbolAddress((void**)&wth, g_wth);
    cudaGetSymbolAddress((void**)&wtl, g_wtl);

    // 1: weight prep + hist + WG=Wo@G1 + bG + zero(vsum, y)
    k_wprep_all<<<dim3(24, 8, 8), dim3(32, 32)>>>(
        text_w, image_w, wq, wk, wv, wo, gcn1_w, gcn2_w, bo, ei + EE);

    // 2: scan (start/cursor/dinv, re-zero cnt, bconst)
    k_scan<<<1, 1024>>>(gcn2_b, cls_w);

    // 3: fused text+image projection + scatter plane
    {
        static bool done = false;
        if (!done) {
            cudaFuncSetAttribute(gemm_fuse2,
                                 cudaFuncAttributeMaxDynamicSharedMemorySize, GEMM_SMEM);
            done = true;
        }
        gemm_fuse2<<<dim3(32, 5), 256, GEMM_SMEM>>>(
            text, image, wth + WOFF_TEXT, wtl + WOFF_TEXT,
            wth + WOFF_IMAGE, wtl + WOFF_IMAGE, text_b, image_b, ch,
            ei, ei + EE);
    }

    // 4: fused QKV (Q,K 1-pass; V 2-pass + vsum reds), 64-wide 3-stage
    {
        static bool done = false;
        if (!done) {
            cudaFuncSetAttribute(gemm_qkv,
                                 cudaFuncAttributeMaxDynamicSharedMemorySize, GEMM_SMEM3);
            done = true;
        }
        gemm_qkv<<<dim3(32, 12), 256, GEMM_SMEM3>>>(
            ch, wth + WOFF_WQ, wtl + WOFF_WQ, bq, bk, bv, qbb, kbb, vbb, vsum);
    }

    // 5: attention (3-stage KV pipeline)
    cudaFuncSetAttribute(attn_mma, cudaFuncAttributeMaxDynamicSharedMemorySize,
                         SM_ATT_TOTAL);
    attn_mma<<<dim3(NN / 128, NHD), 256, SM_ATT_TOTAL>>>(qbb, kbb, vbb, vsum, obh);

    // 6: GCN1 GEMM (composed weights): h_bf16 = ob@WG + bG  -> reuse K buffer
    {
        static bool done = false;
        if (!done) {
            cudaFuncSetAttribute(gemm_tc<2>,
                                 cudaFuncAttributeMaxDynamicSharedMemorySize, GEMM_SMEM3);
            done = true;
        }
        gemm_tc<2><<<dim3(32, 4), 256, GEMM_SMEM3>>>(
            obh, wth + WOFF_G1, wtl + WOFF_G1, bg, kbb, HH);
    }

    // 7: GCN1 aggregation (bf16 gather, self-loop fused) + relu -> bf16
    k_agg1<<<NN * 32 / 256, 256>>>(kbb, gcn1_b, g1h);

    // 8: GCN2 GEMM in classifier space (red into y)
    {
        static bool done = false;
        if (!done) {
            cudaFuncSetAttribute(gemm_tc<7>,
                                 cudaFuncAttributeMaxDynamicSharedMemorySize, GEMM_SMEM3);
            done = true;
        }
        gemm_tc<7><<<dim3(32, 4), 256, GEMM_SMEM3>>>(
            g1h, wth + WOFF_G2, wtl + WOFF_G2, cls_w, yb, HH);
    }

    // 9: GCN2 aggregation on y + bias
    k_agg2y<<<NN * 32 / 256, 256>>>(yb, cls_b, out);
}

// round 16
// speedup vs baseline: 1.2771x; 1.0633x over previous
#include <cuda_runtime.h>
#include <cuda_bf16.h>
#include <cstdint>
#include <cstddef>

#define NN 4096
#define TD 768
#define ID 512
#define HH 256
#define NHD 4
#define HD 64
#define EE 131072
#define NC 3

// ---------------- scratch (static device globals; no allocation) -------------
__device__ float g_y[NN * 4];       // GCN2 h @ cls_w (padded to 4)
__device__ float g_dinv[NN];
__device__ float g_vsum[HH];
__device__ float g_bconst[3];
__device__ float g_bg[HH];          // bo @ G1
__device__ int   g_cnt[NN];         // zero at module load; re-zeroed by k_scan
__device__ int   g_start[NN + 1];
__device__ int   g_cursor[NN];
__device__ int   g_sorted[EE];
// bf16 activations (hi only)
__device__ __nv_bfloat16 g_tb16[NN * TD];
__device__ __nv_bfloat16 g_ib16[NN * ID];
__device__ __nv_bfloat16 g_ch[NN * HH];
__device__ __nv_bfloat16 g_qb[NN * HH];
__device__ __nv_bfloat16 g_kb[NN * HH];   // K for attention; then reused as GCN1 h
__device__ __nv_bfloat16 g_vb[NN * HH];
__device__ __nv_bfloat16 g_obh[NN * HH];
__device__ __nv_bfloat16 g_g1h[NN * HH];
// transposed+split weights [n][K] (hi + lo)
#define WOFF_TEXT  0
#define WOFF_IMAGE 196608
#define WOFF_WQ    327680
#define WOFF_WK    393216
#define WOFF_WV    458752
#define WOFF_G1    524288   /* holds WG = Wo@G1, composed */
#define WOFF_G2    589824
#define WTOT       655360
__device__ __nv_bfloat16 g_wth[WTOT], g_wtl[WTOT];

// =================== helpers =================================================
__device__ __forceinline__ uint32_t smem_u32(const void* p) {
    uint32_t a;
    asm("{ .reg .u64 t; cvta.to.shared.u64 t, %1; cvt.u32.u64 %0, t; }"
        : "=r"(a) : "l"(p));
    return a;
}
__device__ __forceinline__ uint32_t swz128(uint32_t o) { return o ^ ((o >> 3) & 0x70); }
__device__ __forceinline__ uint32_t packbf2(float x0, float x1) {
    uint32_t r;  // lo = x0, hi = x1
    asm("cvt.rn.satfinite.bf16x2.f32 %0, %1, %2;" : "=r"(r) : "f"(x1), "f"(x0));
    return r;
}
__device__ __forceinline__ void unpack2(uint32_t u, float& lo, float& hi) {
    lo = __uint_as_float(u << 16);
    hi = __uint_as_float(u & 0xFFFF0000u);
}
__device__ __forceinline__ void mma16816(float* c,
    uint32_t a0, uint32_t a1, uint32_t a2, uint32_t a3, uint32_t b0, uint32_t b1) {
    asm volatile("mma.sync.aligned.m16n8k16.row.col.f32.bf16.bf16.f32 "
        "{%0,%1,%2,%3}, {%4,%5,%6,%7}, {%8,%9}, {%0,%1,%2,%3};"
        : "+f"(c[0]), "+f"(c[1]), "+f"(c[2]), "+f"(c[3])
        : "r"(a0), "r"(a1), "r"(a2), "r"(a3), "r"(b0), "r"(b1));
}
__device__ __forceinline__ void ldsm4(uint32_t* r, uint32_t a) {
    asm volatile("ldmatrix.sync.aligned.m8n8.x4.shared.b16 {%0,%1,%2,%3}, [%4];"
        : "=r"(r[0]), "=r"(r[1]), "=r"(r[2]), "=r"(r[3]) : "r"(a));
}
__device__ __forceinline__ void ldsm4t(uint32_t* r, uint32_t a) {
    asm volatile("ldmatrix.sync.aligned.m8n8.x4.trans.shared.b16 {%0,%1,%2,%3}, [%4];"
        : "=r"(r[0]), "=r"(r[1]), "=r"(r[2]), "=r"(r[3]) : "r"(a));
}
__device__ __forceinline__ void cp16(uint32_t dst, const void* src) {
    asm volatile("cp.async.cg.shared.global [%0], [%1], 16;" :: "r"(dst), "l"(src) : "memory");
}
__device__ __forceinline__ void cp_commit() {
    asm volatile("cp.async.commit_group;" ::: "memory");
}
__device__ __forceinline__ void cp_wait0() {
    asm volatile("cp.async.wait_group 0;" ::: "memory");
}
__device__ __forceinline__ void cp_wait1() {
    asm volatile("cp.async.wait_group 1;" ::: "memory");
}
__device__ __forceinline__ void redf(float* p, float v) {
    asm volatile("red.global.add.f32 [%0], %1;" :: "l"(p), "f"(v) : "memory");
}

// ====== single-launch prep: weights + hist + compose + bf16 inputs ===========
// grid (24, 8, 9): z 0-4,7 weight planes; z5 hist; z6 compose/bg/zero;
// z8: convert text/image fp32 -> bf16 (grid-stride).
__global__ void k_wprep_all(
    const float* w0, const float* w1, const float* w2, const float* w3,
    const float* w4, const float* wo, const float* g1w, const float* w7,
    const float* bo, const int* __restrict__ edst,
    const float* __restrict__ text, const float* __restrict__ image)
{
    const int z = blockIdx.z;
    const int tx = threadIdx.x, ty = threadIdx.y;
    if (z == 5) {
        int flat = (blockIdx.y * 24 + blockIdx.x) * 1024 + ty * 32 + tx;
        if (flat < EE) atomicAdd(&g_cnt[edst[flat]], 1);
        return;
    }
    if (z == 8) {
        // convert text (NN*TD) + image (NN*ID) to bf16, 2 floats per elem idx
        const int NT2 = NN * TD / 2, NI2 = NN * ID / 2;
        int tid = (blockIdx.y * 24 + blockIdx.x) * 1024 + ty * 32 + tx;
        for (int i = tid; i < NT2 + NI2; i += 196608) {
            if (i < NT2) {
                float2 v = ((const float2*)text)[i];
                ((uint32_t*)g_tb16)[i] = packbf2(v.x, v.y);
            } else {
                float2 v = ((const float2*)image)[i - NT2];
                ((uint32_t*)g_ib16)[i - NT2] = packbf2(v.x, v.y);
            }
        }
        return;
    }
    if (z == 6) {
        if (blockIdx.x < 8) {
            int k0 = blockIdx.x * 32, n0 = blockIdx.y * 32;
            __shared__ float sW[32][33], sG[32][33];
            float acc = 0.f;
            for (int j0 = 0; j0 < HH; j0 += 32) {
                sW[ty][tx] = wo[(size_t)(k0 + ty) * HH + j0 + tx];
                sG[ty][tx] = g1w[(size_t)(j0 + ty) * HH + n0 + tx];
                __syncthreads();
#pragma unroll
                for (int jj = 0; jj < 32; jj++)
                    acc = fmaf(sW[tx][jj], sG[jj][ty], acc);
                __syncthreads();
            }
            __nv_bfloat16 h = __float2bfloat16(acc);
            __nv_bfloat16 l = __float2bfloat16(acc - __bfloat162float(h));
            size_t idx = (size_t)WOFF_G1 + (size_t)(n0 + ty) * HH + k0 + tx;
            g_wth[idx] = h;
            g_wtl[idx] = l;
        } else if (blockIdx.x == 8) {
            if (blockIdx.y == 0) {
                int t = ty * 32 + tx;
                if (t < HH) {
                    float s = 0.f;
                    for (int j = 0; j < HH; j++)
                        s = fmaf(bo[j], g1w[(size_t)j * HH + t], s);
                    g_bg[t] = s;
                }
            }
        } else if (blockIdx.x == 9) {
            int flat = blockIdx.y * 1024 + ty * 32 + tx;
            for (int i = flat; i < NN * 4 + HH; i += 8192) {
                if (i < NN * 4) g_y[i] = 0.f;
                else g_vsum[i - NN * 4] = 0.f;
            }
        }
        return;
    }
    const float* W; int K, off;
    switch (z) {
        case 0: W = w0; K = TD; off = WOFF_TEXT; break;
        case 1: W = w1; K = ID; off = WOFF_IMAGE; break;
        case 2: W = w2; K = HH; off = WOFF_WQ; break;
        case 3: W = w3; K = HH; off = WOFF_WK; break;
        case 4: W = w4; K = HH; off = WOFF_WV; break;
        default: W = w7; K = HH; off = WOFF_G2; break;
    }
    int k0 = blockIdx.x * 32;
    if (k0 >= K) return;
    int n0 = blockIdx.y * 32;
    __shared__ float t[32][33];
    t[ty][tx] = W[(size_t)(k0 + ty) * HH + n0 + tx];
    __syncthreads();
    float v = t[tx][ty];
    __nv_bfloat16 h = __float2bfloat16(v);
    __nv_bfloat16 l = __float2bfloat16(v - __bfloat162float(h));
    size_t idx = (size_t)off + (size_t)(n0 + ty) * K + k0 + tx;
    g_wth[idx] = h;
    g_wtl[idx] = l;
}

// 1 CTA, 1024 threads: prefix-scan cnt -> start/cursor, dinv; re-zero cnt;
// bconst = gcn2_b @ cls_w (warp-parallel on first 3 warps).
__global__ void k_scan(const float* __restrict__ b2, const float* __restrict__ cw)
{
    __shared__ int wsum[32];
    const int t = threadIdx.x, lane = t & 31, wid = t >> 5;
    if (wid < 3) {
        float s = 0.f;
        for (int j = lane; j < HH; j += 32)
            s = fmaf(b2[j], __ldg(cw + j * 3 + wid), s);
#pragma unroll
        for (int off = 16; off > 0; off >>= 1)
            s += __shfl_xor_sync(0xffffffffu, s, off);
        if (lane == 0) g_bconst[wid] = s;
    }
    const int base = t * 4;
    int c0 = g_cnt[base], c1 = g_cnt[base + 1], c2 = g_cnt[base + 2], c3 = g_cnt[base + 3];
    int s = c0 + c1 + c2 + c3;
    int v = s;
#pragma unroll
    for (int off = 1; off < 32; off <<= 1) {
        int u = __shfl_up_sync(0xffffffffu, v, off);
        if (lane >= off) v += u;
    }
    if (lane == 31) wsum[wid] = v;
    __syncthreads();
    if (wid == 0) {
        int x = wsum[lane];
#pragma unroll
        for (int off = 1; off < 32; off <<= 1) {
            int u = __shfl_up_sync(0xffffffffu, x, off);
            if (lane >= off) x += u;
        }
        wsum[lane] = x;
    }
    __syncthreads();
    int excl = v - s + (wid > 0 ? wsum[wid - 1] : 0);
    int e0 = excl, e1 = e0 + c0, e2 = e1 + c1, e3 = e2 + c2;
    g_start[base] = e0;  g_cursor[base] = e0;
    g_start[base + 1] = e1; g_cursor[base + 1] = e1;
    g_start[base + 2] = e2; g_cursor[base + 2] = e2;
    g_start[base + 3] = e3; g_cursor[base + 3] = e3;
    g_dinv[base]     = rsqrtf((float)(c0 + 1));
    g_dinv[base + 1] = rsqrtf((float)(c1 + 1));
    g_dinv[base + 2] = rsqrtf((float)(c2 + 1));
    g_dinv[base + 3] = rsqrtf((float)(c3 + 1));
    g_cnt[base] = 0; g_cnt[base + 1] = 0; g_cnt[base + 2] = 0; g_cnt[base + 3] = 0;
    if (t == 1023) g_start[NN] = e3 + c3;
}

// ====== GCN layer-1 aggregation: warp per dst, bf16 gather ==================
__global__ void __launch_bounds__(256) k_agg1(
    const __nv_bfloat16* __restrict__ h, const float* __restrict__ b1,
    __nv_bfloat16* __restrict__ oh)
{
    const int dstn = (blockIdx.x * 256 + threadIdx.x) >> 5;
    const int lane = threadIdx.x & 31;
    if (dstn >= NN) return;
    const int beg = g_start[dstn], end = g_start[dstn + 1];
    const float dd = g_dinv[dstn];

    float acc[8];
    {
        uint4 u = __ldg((const uint4*)(h + (size_t)dstn * HH) + lane);
        const float c2 = dd * dd;
        const float* bb = b1 + lane * 8;
        float f0, f1;
        unpack2(u.x, f0, f1); acc[0] = fmaf(c2, f0, bb[0]); acc[1] = fmaf(c2, f1, bb[1]);
        unpack2(u.y, f0, f1); acc[2] = fmaf(c2, f0, bb[2]); acc[3] = fmaf(c2, f1, bb[3]);
        unpack2(u.z, f0, f1); acc[4] = fmaf(c2, f0, bb[4]); acc[5] = fmaf(c2, f1, bb[5]);
        unpack2(u.w, f0, f1); acc[6] = fmaf(c2, f0, bb[6]); acc[7] = fmaf(c2, f1, bb[7]);
    }
    for (int e = beg; e < end; e += 32) {
        int n = end - e; if (n > 32) n = 32;
        int sidx = 0; float dv = 0.f;
        if (lane < n) {
            sidx = __ldg(&g_sorted[e + lane]);
            dv = __ldg(&g_dinv[sidx]);
        }
#pragma unroll 4
        for (int j = 0; j < n; j++) {
            int s = __shfl_sync(0xffffffffu, sidx, j);
            float cf = __shfl_sync(0xffffffffu, dv, j) * dd;
            uint4 u = __ldg((const uint4*)(h + ((size_t)s << 8)) + lane);
            float f0, f1;
            unpack2(u.x, f0, f1); acc[0] = fmaf(cf, f0, acc[0]); acc[1] = fmaf(cf, f1, acc[1]);
            unpack2(u.y, f0, f1); acc[2] = fmaf(cf, f0, acc[2]); acc[3] = fmaf(cf, f1, acc[3]);
            unpack2(u.z, f0, f1); acc[4] = fmaf(cf, f0, acc[4]); acc[5] = fmaf(cf, f1, acc[5]);
            unpack2(u.w, f0, f1); acc[6] = fmaf(cf, f0, acc[6]); acc[7] = fmaf(cf, f1, acc[7]);
        }
    }
#pragma unroll
    for (int p = 0; p < 4; p++) {
        float x = fmaxf(acc[2 * p], 0.f), y = fmaxf(acc[2 * p + 1], 0.f);
        ((uint32_t*)oh)[((size_t)dstn * HH + lane * 8 + 2 * p) >> 1] = packbf2(x, y);
    }
}

// ====== GCN layer-2 aggregation on y[4] (classifier space) ===================
__global__ void __launch_bounds__(256) k_agg2y(
    const float* __restrict__ y, const float* __restrict__ cls_b,
    float* __restrict__ out)
{
    const int d = (blockIdx.x * 256 + threadIdx.x) >> 5;
    const int lane = threadIdx.x & 31;
    if (d >= NN) return;
    const int beg = g_start[d], end = g_start[d + 1];
    float a0 = 0.f, a1 = 0.f, a2 = 0.f;
    for (int e = beg + lane; e < end; e += 32) {
        int s = __ldg(&g_sorted[e]);
        float dv = __ldg(&g_dinv[s]);
        float4 yv = *(const float4*)(y + s * 4);
        a0 = fmaf(dv, yv.x, a0);
        a1 = fmaf(dv, yv.y, a1);
        a2 = fmaf(dv, yv.z, a2);
    }
#pragma unroll
    for (int off = 16; off > 0; off >>= 1) {
        a0 += __shfl_xor_sync(0xffffffffu, a0, off);
        a1 += __shfl_xor_sync(0xffffffffu, a1, off);
        a2 += __shfl_xor_sync(0xffffffffu, a2, off);
    }
    if (lane == 0) {
        float dd = g_dinv[d];
        float4 yd = *(const float4*)(y + d * 4);
        out[d * 3 + 0] = fmaf(dd, fmaf(dd, yd.x, a0), g_bconst[0] + cls_b[0]);
        out[d * 3 + 1] = fmaf(dd, fmaf(dd, yd.y, a1), g_bconst[1] + cls_b[1]);
        out[d * 3 + 2] = fmaf(dd, fmaf(dd, yd.z, a2), g_bconst[2] + cls_b[2]);
    }
}

// =============== HMMA GEMM core: 64-wide K chunks, 3-stage ===================
#define GST64 32768
#define G64W  16384
#define GEMM_SMEM3 98304

// NPASS: 2 = AhWh + AhWl, 1 = AhWh only.
template<int NPASS>
__device__ __forceinline__ void gemm_core_bf16(
    uint32_t sb, int tid, int m0, int n0,
    const __nv_bfloat16* A0,
    const __nv_bfloat16* WTh, const __nv_bfloat16* WTl,
    int K, float acc[8][4])
{
    const int w = tid >> 5, lane = tid & 31;
    const int rowa = w * 16 + (lane & 7) + ((lane >> 3) & 1) * 8;
    const int acb  = ((lane >> 4) & 1) * 16;
    const int nrow = lane & 7;
    const int bcb  = ((lane >> 3) & 3) * 16;
    const int nch = K >> 6;

    auto load_st = [&](int kc, int st) {
        int k0 = kc << 6;
        uint32_t base = sb + st * GST64;
#pragma unroll
        for (int j = 0; j < 4; j++) {      // A: 128 rows x 128B
            int flat = tid + j * 256;
            int r = flat >> 3, c = flat & 7;
            const char* src = (const char*)A0 +
                              (((size_t)(m0 + r) * K + k0) << 1) + c * 16;
            cp16(base + swz128((uint32_t)(r * 128 + c * 16)), src);
        }
#pragma unroll
        for (int p = 0; p < NPASS; p++) {  // W: 64 rows x 128B per part
#pragma unroll
            for (int j = 0; j < 2; j++) {
                int flat = tid + j * 256;
                int r = flat >> 3, c = flat & 7;
                const char* src = (const char*)(p ? WTl : WTh) +
                                  (((size_t)(n0 + r) * K + k0) << 1) + c * 16;
                cp16(base + G64W + p * 8192 + swz128((uint32_t)(r * 128 + c * 16)), src);
            }
        }
        cp_commit();
    };
    auto compute = [&](int st) {
        uint32_t base = sb + st * GST64;
#pragma unroll
        for (int s = 0; s < 2; s++) {
            uint32_t ah[2][4];
#pragma unroll
            for (int kk2 = 0; kk2 < 2; kk2++)
                ldsm4(ah[kk2], base + swz128((uint32_t)(rowa * 128 + s * 64 +
                                                        kk2 * 32 + acb)));
#pragma unroll
            for (int nb = 0; nb < 8; nb++) {
                uint32_t bo = (uint32_t)((nb * 8 + nrow) * 128 + s * 64 + bcb);
                uint32_t bh[4];
                ldsm4(bh, base + G64W + swz128(bo));
                mma16816(acc[nb], ah[0][0], ah[0][1], ah[0][2], ah[0][3], bh[0], bh[1]);
                mma16816(acc[nb], ah[1][0], ah[1][1], ah[1][2], ah[1][3], bh[2], bh[3]);
                if (NPASS == 2) {
                    uint32_t bl[4];
                    ldsm4(bl, base + G64W + 8192 + swz128(bo));
                    mma16816(acc[nb], ah[0][0], ah[0][1], ah[0][2], ah[0][3], bl[0], bl[1]);
                    mma16816(acc[nb], ah[1][0], ah[1][1], ah[1][2], ah[1][3], bl[2], bl[3]);
                }
            }
        }
    };

    load_st(0, 0);
    load_st(1, 1);
    cp_wait1();
    __syncthreads();
    int st = 0;
    for (int kc = 0; kc < nch; kc++) {
        if (kc + 2 < nch) {
            int s2 = st + 2; if (s2 >= 3) s2 -= 3;
            load_st(kc + 2, s2);
        }
        compute(st);
        if (kc + 1 < nch) {
            if (kc + 2 < nch) cp_wait1(); else cp_wait0();
            __syncthreads();
        }
        if (++st == 3) st = 0;
    }
}

// fused text+image projection (bf16 inputs) + edge-scatter plane (y == 4)
__global__ void __launch_bounds__(256, 2) gemm_fuse2(
    const __nv_bfloat16* __restrict__ tb16, const __nv_bfloat16* __restrict__ ib16,
    const __nv_bfloat16* __restrict__ Wth, const __nv_bfloat16* __restrict__ Wtl,
    const __nv_bfloat16* __restrict__ Wih, const __nv_bfloat16* __restrict__ Wil,
    const float* __restrict__ tb, const float* __restrict__ ib,
    __nv_bfloat16* __restrict__ ch,
    const int* __restrict__ esrc, const int* __restrict__ edst)
{
    if (blockIdx.y == 4) {
        int base = (blockIdx.x * 256 + threadIdx.x) * 16;
        int4 d4[4], s4[4];
#pragma unroll
        for (int i = 0; i < 4; i++) {
            d4[i] = *(const int4*)(edst + base + i * 4);
            s4[i] = *(const int4*)(esrc + base + i * 4);
        }
#pragma unroll
        for (int i = 0; i < 4; i++) {
            const int dd[4] = {d4[i].x, d4[i].y, d4[i].z, d4[i].w};
            const int ss[4] = {s4[i].x, s4[i].y, s4[i].z, s4[i].w};
#pragma unroll
            for (int j = 0; j < 4; j++) {
                int pos = atomicAdd(&g_cursor[dd[j]], 1);
                g_sorted[pos] = ss[j];
            }
        }
        return;
    }
    extern __shared__ char sm[];
    const uint32_t sb = smem_u32(sm);
    const int tid = threadIdx.x, w = tid >> 5, lane = tid & 31;
    const int m0 = blockIdx.x * 128, n0 = blockIdx.y * 64;

    float acc[8][4] = {};
    gemm_core_bf16<2>(sb, tid, m0, n0, tb16, Wth, Wtl, TD, acc);
    float rf[8][4];
#pragma unroll
    for (int nb = 0; nb < 8; nb++) {
        const int cg = n0 + (lane & 3) * 2 + nb * 8;
        float b0 = tb[cg], b1 = tb[cg + 1];
        rf[nb][0] = fmaxf(acc[nb][0] + b0, 0.f);
        rf[nb][1] = fmaxf(acc[nb][1] + b1, 0.f);
        rf[nb][2] = fmaxf(acc[nb][2] + b0, 0.f);
        rf[nb][3] = fmaxf(acc[nb][3] + b1, 0.f);
        acc[nb][0] = acc[nb][1] = acc[nb][2] = acc[nb][3] = 0.f;
    }
    __syncthreads();   // smem reuse between the two core passes
    gemm_core_bf16<2>(sb, tid, m0, n0, ib16, Wih, Wil, ID, acc);

    const int r0 = m0 + w * 16 + (lane >> 2);
#pragma unroll
    for (int nb = 0; nb < 8; nb++) {
        const int cg = n0 + (lane & 3) * 2 + nb * 8;
        float b0 = ib[cg], b1 = ib[cg + 1];
        const size_t i0 = (size_t)r0 * HH + cg;
        const size_t i1 = (size_t)(r0 + 8) * HH + cg;
        ((uint32_t*)ch)[i0 >> 1] = packbf2(rf[nb][0] + fmaxf(acc[nb][0] + b0, 0.f),
                                           rf[nb][1] + fmaxf(acc[nb][1] + b1, 0.f));
        ((uint32_t*)ch)[i1 >> 1] = packbf2(rf[nb][2] + fmaxf(acc[nb][2] + b0, 0.f),
                                           rf[nb][3] + fmaxf(acc[nb][3] + b1, 0.f));
    }
}

// general GEMM kernel (bf16-A hi, 2-pass), epilogues:
// EPI 2: bias -> bf16 out0 (GCN1 h)
// EPI 7: y-partials: red out0 += acc@cls_w (bias = cls_w)
template<int EPI>
__global__ void __launch_bounds__(256, 2) gemm_tc(
    const __nv_bfloat16* __restrict__ A0,
    const __nv_bfloat16* __restrict__ WTh, const __nv_bfloat16* __restrict__ WTl,
    const float* __restrict__ bias,
    void* out0v, int K)
{
    extern __shared__ char sm[];
    const uint32_t sb = smem_u32(sm);
    const int tid = threadIdx.x, w = tid >> 5, lane = tid & 31;
    const int m0 = blockIdx.x * 128, n0 = blockIdx.y * 64;
    float acc[8][4] = {};
    gemm_core_bf16<2>(sb, tid, m0, n0, A0, WTh, WTl, K, acc);

    const int r0 = m0 + w * 16 + (lane >> 2);
    if (EPI == 7) {
        const float* cw = bias;
        float p0[3] = {0.f, 0.f, 0.f}, p1[3] = {0.f, 0.f, 0.f};
#pragma unroll
        for (int nb = 0; nb < 8; nb++) {
            const int cg = n0 + (lane & 3) * 2 + nb * 8;
#pragma unroll
            for (int c = 0; c < 3; c++) {
                float w0 = __ldg(cw + cg * 3 + c), w1 = __ldg(cw + (cg + 1) * 3 + c);
                p0[c] = fmaf(acc[nb][0], w0, fmaf(acc[nb][1], w1, p0[c]));
                p1[c] = fmaf(acc[nb][2], w0, fmaf(acc[nb][3], w1, p1[c]));
            }
        }
#pragma unroll
        for (int c = 0; c < 3; c++) {
            p0[c] += __shfl_xor_sync(0xffffffffu, p0[c], 1);
            p0[c] += __shfl_xor_sync(0xffffffffu, p0[c], 2);
            p1[c] += __shfl_xor_sync(0xffffffffu, p1[c], 1);
            p1[c] += __shfl_xor_sync(0xffffffffu, p1[c], 2);
        }
        if ((lane & 3) == 0) {
            float* y = (float*)out0v;
#pragma unroll
            for (int c = 0; c < 3; c++) {
                redf(y + r0 * 4 + c, p0[c]);
                redf(y + (r0 + 8) * 4 + c, p1[c]);
            }
        }
        return;
    }
#pragma unroll
    for (int nb = 0; nb < 8; nb++) {
        const int cg = n0 + (lane & 3) * 2 + nb * 8;
        float b0 = bias[cg], b1 = bias[cg + 1];
        const size_t i0 = (size_t)r0 * HH + cg;
        const size_t i1 = (size_t)(r0 + 8) * HH + cg;
        ((uint32_t*)out0v)[i0 >> 1] = packbf2(acc[nb][0] + b0, acc[nb][1] + b1);
        ((uint32_t*)out0v)[i1 >> 1] = packbf2(acc[nb][2] + b0, acc[nb][3] + b1);
    }
}

// fused QKV GEMM: grid (32, 12). V first (slow 2-pass in wave 1), then K, Q.
__global__ void __launch_bounds__(256, 2) gemm_qkv(
    const __nv_bfloat16* __restrict__ A0,
    const __nv_bfloat16* __restrict__ WTbase, const __nv_bfloat16* __restrict__ WLbase,
    const float* __restrict__ bq, const float* __restrict__ bk,
    const float* __restrict__ bv,
    __nv_bfloat16* __restrict__ oq, __nv_bfloat16* __restrict__ ok,
    __nv_bfloat16* __restrict__ ov, float* __restrict__ vsum)
{
    extern __shared__ char sm[];
    const uint32_t sb = smem_u32(sm);
    const int tid = threadIdx.x, w = tid >> 5, lane = tid & 31;
    const int sel = 2 - (blockIdx.y >> 2);       // y 0-3: V, 4-7: K, 8-11: Q
    const int m0 = blockIdx.x * 128, n0 = (blockIdx.y & 3) * 64;
    const __nv_bfloat16* WTh = WTbase + (size_t)sel * HH * HH;
    const __nv_bfloat16* WTl = WLbase + (size_t)sel * HH * HH;
    const float* bias = sel == 0 ? bq : (sel == 1 ? bk : bv);
    __nv_bfloat16* out = sel == 0 ? oq : (sel == 1 ? ok : ov);

    float acc[8][4] = {};
    if (sel == 2) gemm_core_bf16<2>(sb, tid, m0, n0, A0, WTh, WTl, HH, acc);
    else          gemm_core_bf16<1>(sb, tid, m0, n0, A0, WTh, WTl, HH, acc);

    const int r0 = m0 + w * 16 + (lane >> 2);
#pragma unroll
    for (int nb = 0; nb < 8; nb++) {
        const int cg = n0 + (lane & 3) * 2 + nb * 8;
        float b0 = bias[cg], b1 = bias[cg + 1];
        float v00 = acc[nb][0] + b0, v01 = acc[nb][1] + b1;
        float v10 = acc[nb][2] + b0, v11 = acc[nb][3] + b1;
        const size_t i0 = (size_t)r0 * HH + cg;
        const size_t i1 = (size_t)(r0 + 8) * HH + cg;
        ((uint32_t*)out)[i0 >> 1] = packbf2(v00, v01);
        ((uint32_t*)out)[i1 >> 1] = packbf2(v10, v11);
        if (sel == 2) {
            float s0 = v00 + v10, s1 = v01 + v11;
#pragma unroll
            for (int off = 4; off < 32; off <<= 1) {
                s0 += __shfl_xor_sync(0xffffffffu, s0, off);
                s1 += __shfl_xor_sync(0xffffffffu, s1, off);
            }
            if (lane < 4) {
                redf(vsum + cg, s0);
                redf(vsum + cg + 1, s1);
            }
        }
    }
}

// ============== HMMA flash attention: 128 q-rows x 1 head per CTA ============
#define SM_BUFSTRIDE 32768
#define SM_VOFF 16384
#define SM_Q 98304
#define SM_ATT_TOTAL 114688

__device__ __forceinline__ void load_kv_tile(
    uint32_t sb, int buf, int kt, int head,
    const __nv_bfloat16* kb, const __nv_bfloat16* vb, int tid)
{
    const char* kc = (const char*)kb;
    const char* vc = (const char*)vb;
#pragma unroll
    for (int j = 0; j < 8; j++) {
        int flat = tid + j * 256;
        int arr = flat >> 10;
        int row = (flat >> 3) & 127;
        int c = flat & 7;
        const char* src = (arr ? vc : kc) +
            (((size_t)(kt + row) * HH + head * HD) << 1) + c * 16;
        uint32_t dst = sb + buf * SM_BUFSTRIDE + arr * SM_VOFF +
                       swz128((uint32_t)(row * 128 + c * 16));
        cp16(dst, src);
    }
}

__global__ void __launch_bounds__(256, 1) attn_mma(
    const __nv_bfloat16* __restrict__ qb, const __nv_bfloat16* __restrict__ kb,
    const __nv_bfloat16* __restrict__ vb, const float* __restrict__ vsum,
    __nv_bfloat16* __restrict__ oh)
{
    extern __shared__ char sm[];
    const uint32_t sb = smem_u32(sm);
    const int tid = threadIdx.x, w = tid >> 5, lane = tid & 31;
    const int q0 = blockIdx.x * 128, head = blockIdx.y;

    {
        const char* qc = (const char*)qb;
#pragma unroll
        for (int j = 0; j < 4; j++) {
            int flat = tid + j * 256;
            int row = flat >> 3, c = flat & 7;
            const char* src = qc + (((size_t)(q0 + row) * HH + head * HD) << 1) + c * 16;
            cp16(sb + SM_Q + swz128((uint32_t)(row * 128 + c * 16)), src);
        }
        load_kv_tile(sb, 0, 0, head, kb, vb, tid);
        cp_commit();
        load_kv_tile(sb, 1, 128, head, kb, vb, tid);
        cp_commit();
        cp_wait1();
        __syncthreads();
    }

    uint32_t qa[4][4];
    {
        const int rowa = w * 16 + (lane & 7) + ((lane >> 3) & 1) * 8;
        const int cb = ((lane >> 4) & 1) * 16;
#pragma unroll
        for (int kk = 0; kk < 4; kk++)
            ldsm4(qa[kk], sb + SM_Q + swz128((uint32_t)(rowa * 128 + kk * 32 + cb)));
    }

    float oacc[8][4] = {};
    float sumd0 = 0.f, sumd1 = 0.f;

    int buf = 0;
    for (int t = 0; t < 32; t++) {
        const uint32_t kbase = sb + buf * SM_BUFSTRIDE;
        const uint32_t vbase = kbase + SM_VOFF;
        if (t + 2 < 32) {
            int b2 = buf + 2; if (b2 >= 3) b2 -= 3;
            load_kv_tile(sb, b2, (t + 2) * 128, head, kb, vb, tid);
            cp_commit();
        }
#pragma unroll 2
        for (int kk = 0; kk < 8; kk++) {
            // 4 independent QK accumulation chains: [half][kk2]
            float s2a[2][4] = {{0.f,0.f,0.f,0.f},{0.f,0.f,0.f,0.f}};
            float s2b[2][4] = {{0.f,0.f,0.f,0.f},{0.f,0.f,0.f,0.f}};
#pragma unroll
            for (int half = 0; half < 2; half++) {
                const int keyl = kk * 16 + half * 8 + (lane & 7);
                uint32_t b0[4], b1[4];
                ldsm4(b0, kbase + swz128((uint32_t)(keyl * 128 +
                                                    ((lane >> 3) & 3) * 16)));
                ldsm4(b1, kbase + swz128((uint32_t)(keyl * 128 + 64 +
                                                    ((lane >> 3) & 3) * 16)));
                mma16816(s2a[half], qa[0][0], qa[0][1], qa[0][2], qa[0][3], b0[0], b0[1]);
                mma16816(s2b[half], qa[2][0], qa[2][1], qa[2][2], qa[2][3], b1[0], b1[1]);
                mma16816(s2a[half], qa[1][0], qa[1][1], qa[1][2], qa[1][3], b0[2], b0[3]);
                mma16816(s2b[half], qa[3][0], qa[3][1], qa[3][2], qa[3][3], b1[2], b1[3]);
            }
            float s[2][4];
#pragma unroll
            for (int half = 0; half < 2; half++) {
#pragma unroll
                for (int j = 0; j < 4; j++) {
                    float x = (s2a[half][j] + s2b[half][j]) * 0.125f;
                    float h = fmaf(x, 4.166666667e-2f, 0.166666667f);
                    h = fmaf(h, x, 0.5f);
                    h = fmaf(h, x, 1.0f);
                    float dlt = x * h;
                    s[half][j] = dlt;
                    if (j < 2) sumd0 += dlt; else sumd1 += dlt;
                }
            }
            uint32_t A0 = packbf2(s[0][0], s[0][1]);
            uint32_t A1 = packbf2(s[0][2], s[0][3]);
            uint32_t A2 = packbf2(s[1][0], s[1][1]);
            uint32_t A3 = packbf2(s[1][2], s[1][3]);
            const int keyl2 = kk * 16 + (lane & 7) + ((lane >> 3) & 1) * 8;
            const int cb2 = ((lane >> 4) & 1) * 16;
#pragma unroll
            for (int nb2 = 0; nb2 < 4; nb2++) {
                uint32_t b[4];
                ldsm4t(b, vbase + swz128((uint32_t)(keyl2 * 128 + nb2 * 32 + cb2)));
                mma16816(oacc[2*nb2],     A0, A1, A2, A3, b[0], b[1]);
                mma16816(oacc[2*nb2 + 1], A0, A1, A2, A3, b[2], b[3]);
            }
        }
        if (t + 1 < 32) {
            if (t + 2 < 32) cp_wait1(); else cp_wait0();
            __syncthreads();
        }
        if (++buf == 3) buf = 0;
    }

    sumd0 += __shfl_xor_sync(0xffffffffu, sumd0, 1);
    sumd0 += __shfl_xor_sync(0xffffffffu, sumd0, 2);
    sumd1 += __shfl_xor_sync(0xffffffffu, sumd1, 1);
    sumd1 += __shfl_xor_sync(0xffffffffu, sumd1, 2);
    const float inv0 = 1.0f / (4096.0f + sumd0);
    const float inv1 = 1.0f / (4096.0f + sumd1);
    const int r0 = q0 + w * 16 + (lane >> 2);
    const int cbase = head * HD + (lane & 3) * 2;
#pragma unroll
    for (int nb = 0; nb < 8; nb++) {
        int d = cbase + nb * 8;
        float sv0 = vsum[d], sv1 = vsum[d + 1];
        ((uint32_t*)oh)[((size_t)r0 * HH + d) >> 1] =
            packbf2((sv0 + oacc[nb][0]) * inv0, (sv1 + oacc[nb][1]) * inv0);
        ((uint32_t*)oh)[((size_t)(r0 + 8) * HH + d) >> 1] =
            packbf2((sv0 + oacc[nb][2]) * inv1, (sv1 + oacc[nb][3]) * inv1);
    }
}

// ---------------- launch -----------------------------------------------------
extern "C" void kernel_launch(void* const* d_in, const int* in_sizes, int n_in,
                              void* d_out, int out_size)
{
    const float* text    = (const float*)d_in[0];
    const float* image   = (const float*)d_in[1];
    const int*   ei      = (const int*)d_in[2];
    const float* text_w  = (const float*)d_in[3];
    const float* text_b  = (const float*)d_in[4];
    const float* image_w = (const float*)d_in[5];
    const float* image_b = (const float*)d_in[6];
    const float* wq = (const float*)d_in[7];  const float* bq = (const float*)d_in[8];
    const float* wk = (const float*)d_in[9];  const float* bk = (const float*)d_in[10];
    const float* wv = (const float*)d_in[11]; const float* bv = (const float*)d_in[12];
    const float* wo = (const float*)d_in[13]; const float* bo = (const float*)d_in[14];
    const float* gcn1_w = (const float*)d_in[15]; const float* gcn1_b = (const float*)d_in[16];
    const float* gcn2_w = (const float*)d_in[17]; const float* gcn2_b = (const float*)d_in[18];
    const float* cls_w  = (const float*)d_in[19]; const float* cls_b  = (const float*)d_in[20];
    float* out = (float*)d_out;

    float *yb, *dinv, *vsum, *bg;
    __nv_bfloat16 *tb16, *ib16, *ch, *qbb, *kbb, *vbb, *obh, *g1h, *wth, *wtl;
    cudaGetSymbolAddress((void**)&yb, g_y);
    cudaGetSymbolAddress((void**)&dinv, g_dinv);
    cudaGetSymbolAddress((void**)&vsum, g_vsum);
    cudaGetSymbolAddress((void**)&bg, g_bg);
    cudaGetSymbolAddress((void**)&tb16, g_tb16);
    cudaGetSymbolAddress((void**)&ib16, g_ib16);
    cudaGetSymbolAddress((void**)&ch, g_ch);
    cudaGetSymbolAddress((void**)&qbb, g_qb);
    cudaGetSymbolAddress((void**)&kbb, g_kb);
    cudaGetSymbolAddress((void**)&vbb, g_vb);
    cudaGetSymbolAddress((void**)&obh, g_obh);
    cudaGetSymbolAddress((void**)&g1h, g_g1h);
    cudaGetSymbolAddress((void**)&wth, g_wth);
    cudaGetSymbolAddress((void**)&wtl, g_wtl);

    // 1: weight prep + hist + WG compose + bG + zero + bf16 input conversion
    k_wprep_all<<<dim3(24, 8, 9), dim3(32, 32)>>>(
        text_w, image_w, wq, wk, wv, wo, gcn1_w, gcn2_w, bo, ei + EE,
        text, image);

    // 2: scan (start/cursor/dinv, re-zero cnt, bconst)
    k_scan<<<1, 1024>>>(gcn2_b, cls_w);

    // 3: fused text+image projection (bf16 core) + scatter plane
    {
        static bool done = false;
        if (!done) {
            cudaFuncSetAttribute(gemm_fuse2,
                                 cudaFuncAttributeMaxDynamicSharedMemorySize, GEMM_SMEM3);
            done = true;
        }
        gemm_fuse2<<<dim3(32, 5), 256, GEMM_SMEM3>>>(
            tb16, ib16, wth + WOFF_TEXT, wtl + WOFF_TEXT,
            wth + WOFF_IMAGE, wtl + WOFF_IMAGE, text_b, image_b, ch,
            ei, ei + EE);
    }

    // 4: fused QKV (V first; Q,K 1-pass; V 2-pass + vsum reds)
    {
        static bool done = false;
        if (!done) {
            cudaFuncSetAttribute(gemm_qkv,
                                 cudaFuncAttributeMaxDynamicSharedMemorySize, GEMM_SMEM3);
            done = true;
        }
        gemm_qkv<<<dim3(32, 12), 256, GEMM_SMEM3>>>(
            ch, wth + WOFF_WQ, wtl + WOFF_WQ, bq, bk, bv, qbb, kbb, vbb, vsum);
    }

    // 5: attention (3-stage KV pipeline, 4 QK chains)
    cudaFuncSetAttribute(attn_mma, cudaFuncAttributeMaxDynamicSharedMemorySize,
                         SM_ATT_TOTAL);
    attn_mma<<<dim3(NN / 128, NHD), 256, SM_ATT_TOTAL>>>(qbb, kbb, vbb, vsum, obh);

    // 6: GCN1 GEMM (composed weights): h_bf16 = ob@WG + bG -> reuse K buffer
    {
        static bool done = false;
        if (!done) {
            cudaFuncSetAttribute(gemm_tc<2>,
                                 cudaFuncAttributeMaxDynamicSharedMemorySize, GEMM_SMEM3);
            done = true;
        }
        gemm_tc<2><<<dim3(32, 4), 256, GEMM_SMEM3>>>(
            obh, wth + WOFF_G1, wtl + WOFF_G1, bg, kbb, HH);
    }

    // 7: GCN1 aggregation (bf16 gather, self-loop fused) + relu -> bf16
    k_agg1<<<NN * 32 / 256, 256>>>(kbb, gcn1_b, g1h);

    // 8: GCN2 GEMM in classifier space (red into y)
    {
        static bool done = false;
        if (!done) {
            cudaFuncSetAttribute(gemm_tc<7>,
                                 cudaFuncAttributeMaxDynamicSharedMemorySize, GEMM_SMEM3);
            done = true;
        }
        gemm_tc<7><<<dim3(32, 4), 256, GEMM_SMEM3>>>(
            g1h, wth + WOFF_G2, wtl + WOFF_G2, cls_w, yb, HH);
    }

    // 9: GCN2 aggregation on y + bias
    k_agg2y<<<NN * 32 / 256, 256>>>(yb, cls_b, out);
}

// round 17
// speedup vs baseline: 1.3267x; 1.0388x over previous
#include <cuda_runtime.h>
#include <cuda_bf16.h>
#include <cstdint>
#include <cstddef>

#define NN 4096
#define TD 768
#define ID 512
#define HH 256
#define NHD 4
#define HD 64
#define EE 131072
#define NC 3

// ---------------- scratch (static device globals; no allocation) -------------
__device__ float g_y[NN * 4];
__device__ float g_dinv[NN];
__device__ float g_vsum[HH];
__device__ float g_bconst[3];
__device__ float g_bg[HH];
__device__ int   g_cnt[NN];
__device__ int   g_start[NN + 1];
__device__ int   g_cursor[NN];
__device__ int   g_sorted[EE];
__device__ __nv_bfloat16 g_tb16[NN * TD];
__device__ __nv_bfloat16 g_ib16[NN * ID];
__device__ __nv_bfloat16 g_ch[NN * HH];
__device__ __nv_bfloat16 g_qb[NN * HH];
__device__ __nv_bfloat16 g_kb[NN * HH];   // K for attention; then GCN1 h
__device__ __nv_bfloat16 g_vb[NN * HH];
__device__ __nv_bfloat16 g_obh[NN * HH];
__device__ __nv_bfloat16 g_g1h[NN * HH];
#define WOFF_TEXT  0
#define WOFF_IMAGE 196608
#define WOFF_WQ    327680
#define WOFF_WK    393216
#define WOFF_WV    458752
#define WOFF_G1    524288
#define WOFF_G2    589824
#define WTOT       655360
__device__ __nv_bfloat16 g_wth[WTOT], g_wtl[WTOT];

// =================== helpers =================================================
__device__ __forceinline__ uint32_t smem_u32(const void* p) {
    uint32_t a;
    asm("{ .reg .u64 t; cvta.to.shared.u64 t, %1; cvt.u32.u64 %0, t; }"
        : "=r"(a) : "l"(p));
    return a;
}
__device__ __forceinline__ uint32_t swz128(uint32_t o) { return o ^ ((o >> 3) & 0x70); }
__device__ __forceinline__ uint32_t packbf2(float x0, float x1) {
    uint32_t r;
    asm("cvt.rn.satfinite.bf16x2.f32 %0, %1, %2;" : "=r"(r) : "f"(x1), "f"(x0));
    return r;
}
__device__ __forceinline__ void unpack2(uint32_t u, float& lo, float& hi) {
    lo = __uint_as_float(u << 16);
    hi = __uint_as_float(u & 0xFFFF0000u);
}
__device__ __forceinline__ void mma16816(float* c,
    uint32_t a0, uint32_t a1, uint32_t a2, uint32_t a3, uint32_t b0, uint32_t b1) {
    asm volatile("mma.sync.aligned.m16n8k16.row.col.f32.bf16.bf16.f32 "
        "{%0,%1,%2,%3}, {%4,%5,%6,%7}, {%8,%9}, {%0,%1,%2,%3};"
        : "+f"(c[0]), "+f"(c[1]), "+f"(c[2]), "+f"(c[3])
        : "r"(a0), "r"(a1), "r"(a2), "r"(a3), "r"(b0), "r"(b1));
}
__device__ __forceinline__ void ldsm4(uint32_t* r, uint32_t a) {
    asm volatile("ldmatrix.sync.aligned.m8n8.x4.shared.b16 {%0,%1,%2,%3}, [%4];"
        : "=r"(r[0]), "=r"(r[1]), "=r"(r[2]), "=r"(r[3]) : "r"(a));
}
__device__ __forceinline__ void ldsm4t(uint32_t* r, uint32_t a) {
    asm volatile("ldmatrix.sync.aligned.m8n8.x4.trans.shared.b16 {%0,%1,%2,%3}, [%4];"
        : "=r"(r[0]), "=r"(r[1]), "=r"(r[2]), "=r"(r[3]) : "r"(a));
}
__device__ __forceinline__ void cp16(uint32_t dst, const void* src) {
    asm volatile("cp.async.cg.shared.global [%0], [%1], 16;" :: "r"(dst), "l"(src) : "memory");
}
__device__ __forceinline__ void cp_commit() {
    asm volatile("cp.async.commit_group;" ::: "memory");
}
__device__ __forceinline__ void cp_wait0() {
    asm volatile("cp.async.wait_group 0;" ::: "memory");
}
__device__ __forceinline__ void cp_wait1() {
    asm volatile("cp.async.wait_group 1;" ::: "memory");
}
__device__ __forceinline__ void redf(float* p, float v) {
    asm volatile("red.global.add.f32 [%0], %1;" :: "l"(p), "f"(v) : "memory");
}

// ====== single-launch prep: weights + hist + compose + bf16 inputs ===========
__global__ void k_wprep_all(
    const float* w0, const float* w1, const float* w2, const float* w3,
    const float* w4, const float* wo, const float* g1w, const float* w7,
    const float* bo, const int* __restrict__ edst,
    const float* __restrict__ text, const float* __restrict__ image)
{
    const int z = blockIdx.z;
    const int tx = threadIdx.x, ty = threadIdx.y;
    if (z == 5) {
        int flat = (blockIdx.y * 24 + blockIdx.x) * 1024 + ty * 32 + tx;
        if (flat < EE) atomicAdd(&g_cnt[edst[flat]], 1);
        return;
    }
    if (z == 8) {
        const int NT2 = NN * TD / 2, NI2 = NN * ID / 2;
        int tid = (blockIdx.y * 24 + blockIdx.x) * 1024 + ty * 32 + tx;
        for (int i = tid; i < NT2 + NI2; i += 196608) {
            if (i < NT2) {
                float2 v = ((const float2*)text)[i];
                ((uint32_t*)g_tb16)[i] = packbf2(v.x, v.y);
            } else {
                float2 v = ((const float2*)image)[i - NT2];
                ((uint32_t*)g_ib16)[i - NT2] = packbf2(v.x, v.y);
            }
        }
        return;
    }
    if (z == 6) {
        if (blockIdx.x < 8) {
            int k0 = blockIdx.x * 32, n0 = blockIdx.y * 32;
            __shared__ float sW[32][33], sG[32][33];
            float acc = 0.f;
            for (int j0 = 0; j0 < HH; j0 += 32) {
                sW[ty][tx] = wo[(size_t)(k0 + ty) * HH + j0 + tx];
                sG[ty][tx] = g1w[(size_t)(j0 + ty) * HH + n0 + tx];
                __syncthreads();
#pragma unroll
                for (int jj = 0; jj < 32; jj++)
                    acc = fmaf(sW[tx][jj], sG[jj][ty], acc);
                __syncthreads();
            }
            __nv_bfloat16 h = __float2bfloat16(acc);
            __nv_bfloat16 l = __float2bfloat16(acc - __bfloat162float(h));
            size_t idx = (size_t)WOFF_G1 + (size_t)(n0 + ty) * HH + k0 + tx;
            g_wth[idx] = h;
            g_wtl[idx] = l;
        } else if (blockIdx.x == 8) {
            if (blockIdx.y == 0) {
                int t = ty * 32 + tx;
                if (t < HH) {
                    float s = 0.f;
                    for (int j = 0; j < HH; j++)
                        s = fmaf(bo[j], g1w[(size_t)j * HH + t], s);
                    g_bg[t] = s;
                }
            }
        } else if (blockIdx.x == 9) {
            int flat = blockIdx.y * 1024 + ty * 32 + tx;
            for (int i = flat; i < NN * 4 + HH; i += 8192) {
                if (i < NN * 4) g_y[i] = 0.f;
                else g_vsum[i - NN * 4] = 0.f;
            }
        }
        return;
    }
    const float* W; int K, off;
    switch (z) {
        case 0: W = w0; K = TD; off = WOFF_TEXT; break;
        case 1: W = w1; K = ID; off = WOFF_IMAGE; break;
        case 2: W = w2; K = HH; off = WOFF_WQ; break;
        case 3: W = w3; K = HH; off = WOFF_WK; break;
        case 4: W = w4; K = HH; off = WOFF_WV; break;
        default: W = w7; K = HH; off = WOFF_G2; break;
    }
    int k0 = blockIdx.x * 32;
    if (k0 >= K) return;
    int n0 = blockIdx.y * 32;
    __shared__ float t[32][33];
    t[ty][tx] = W[(size_t)(k0 + ty) * HH + n0 + tx];
    __syncthreads();
    float v = t[tx][ty];
    __nv_bfloat16 h = __float2bfloat16(v);
    __nv_bfloat16 l = __float2bfloat16(v - __bfloat162float(h));
    size_t idx = (size_t)off + (size_t)(n0 + ty) * K + k0 + tx;
    g_wth[idx] = h;
    g_wtl[idx] = l;
}

// 1 CTA, 1024 threads: prefix-scan; dinv; re-zero cnt; bconst.
__global__ void k_scan(const float* __restrict__ b2, const float* __restrict__ cw)
{
    __shared__ int wsum[32];
    const int t = threadIdx.x, lane = t & 31, wid = t >> 5;
    if (wid < 3) {
        float s = 0.f;
        for (int j = lane; j < HH; j += 32)
            s = fmaf(b2[j], __ldg(cw + j * 3 + wid), s);
#pragma unroll
        for (int off = 16; off > 0; off >>= 1)
            s += __shfl_xor_sync(0xffffffffu, s, off);
        if (lane == 0) g_bconst[wid] = s;
    }
    const int base = t * 4;
    int c0 = g_cnt[base], c1 = g_cnt[base + 1], c2 = g_cnt[base + 2], c3 = g_cnt[base + 3];
    int s = c0 + c1 + c2 + c3;
    int v = s;
#pragma unroll
    for (int off = 1; off < 32; off <<= 1) {
        int u = __shfl_up_sync(0xffffffffu, v, off);
        if (lane >= off) v += u;
    }
    if (lane == 31) wsum[wid] = v;
    __syncthreads();
    if (wid == 0) {
        int x = wsum[lane];
#pragma unroll
        for (int off = 1; off < 32; off <<= 1) {
            int u = __shfl_up_sync(0xffffffffu, x, off);
            if (lane >= off) x += u;
        }
        wsum[lane] = x;
    }
    __syncthreads();
    int excl = v - s + (wid > 0 ? wsum[wid - 1] : 0);
    int e0 = excl, e1 = e0 + c0, e2 = e1 + c1, e3 = e2 + c2;
    g_start[base] = e0;  g_cursor[base] = e0;
    g_start[base + 1] = e1; g_cursor[base + 1] = e1;
    g_start[base + 2] = e2; g_cursor[base + 2] = e2;
    g_start[base + 3] = e3; g_cursor[base + 3] = e3;
    g_dinv[base]     = rsqrtf((float)(c0 + 1));
    g_dinv[base + 1] = rsqrtf((float)(c1 + 1));
    g_dinv[base + 2] = rsqrtf((float)(c2 + 1));
    g_dinv[base + 3] = rsqrtf((float)(c3 + 1));
    g_cnt[base] = 0; g_cnt[base + 1] = 0; g_cnt[base + 2] = 0; g_cnt[base + 3] = 0;
    if (t == 1023) g_start[NN] = e3 + c3;
}

// ====== GCN layer-1 aggregation: warp per dst, bf16 gather ==================
__global__ void __launch_bounds__(256) k_agg1(
    const __nv_bfloat16* __restrict__ h, const float* __restrict__ b1,
    __nv_bfloat16* __restrict__ oh)
{
    const int dstn = (blockIdx.x * 256 + threadIdx.x) >> 5;
    const int lane = threadIdx.x & 31;
    if (dstn >= NN) return;
    const int beg = g_start[dstn], end = g_start[dstn + 1];
    const float dd = g_dinv[dstn];

    float acc[8];
    {
        uint4 u = __ldg((const uint4*)(h + (size_t)dstn * HH) + lane);
        const float c2 = dd * dd;
        const float* bb = b1 + lane * 8;
        float f0, f1;
        unpack2(u.x, f0, f1); acc[0] = fmaf(c2, f0, bb[0]); acc[1] = fmaf(c2, f1, bb[1]);
        unpack2(u.y, f0, f1); acc[2] = fmaf(c2, f0, bb[2]); acc[3] = fmaf(c2, f1, bb[3]);
        unpack2(u.z, f0, f1); acc[4] = fmaf(c2, f0, bb[4]); acc[5] = fmaf(c2, f1, bb[5]);
        unpack2(u.w, f0, f1); acc[6] = fmaf(c2, f0, bb[6]); acc[7] = fmaf(c2, f1, bb[7]);
    }
    for (int e = beg; e < end; e += 32) {
        int n = end - e; if (n > 32) n = 32;
        int sidx = 0; float dv = 0.f;
        if (lane < n) {
            sidx = __ldg(&g_sorted[e + lane]);
            dv = __ldg(&g_dinv[sidx]);
        }
#pragma unroll 4
        for (int j = 0; j < n; j++) {
            int s = __shfl_sync(0xffffffffu, sidx, j);
            float cf = __shfl_sync(0xffffffffu, dv, j) * dd;
            uint4 u = __ldg((const uint4*)(h + ((size_t)s << 8)) + lane);
            float f0, f1;
            unpack2(u.x, f0, f1); acc[0] = fmaf(cf, f0, acc[0]); acc[1] = fmaf(cf, f1, acc[1]);
            unpack2(u.y, f0, f1); acc[2] = fmaf(cf, f0, acc[2]); acc[3] = fmaf(cf, f1, acc[3]);
            unpack2(u.z, f0, f1); acc[4] = fmaf(cf, f0, acc[4]); acc[5] = fmaf(cf, f1, acc[5]);
            unpack2(u.w, f0, f1); acc[6] = fmaf(cf, f0, acc[6]); acc[7] = fmaf(cf, f1, acc[7]);
        }
    }
#pragma unroll
    for (int p = 0; p < 4; p++) {
        float x = fmaxf(acc[2 * p], 0.f), y = fmaxf(acc[2 * p + 1], 0.f);
        ((uint32_t*)oh)[((size_t)dstn * HH + lane * 8 + 2 * p) >> 1] = packbf2(x, y);
    }
}

// ====== GCN layer-2 aggregation on y[4] ======================================
__global__ void __launch_bounds__(256) k_agg2y(
    const float* __restrict__ y, const float* __restrict__ cls_b,
    float* __restrict__ out)
{
    const int d = (blockIdx.x * 256 + threadIdx.x) >> 5;
    const int lane = threadIdx.x & 31;
    if (d >= NN) return;
    const int beg = g_start[d], end = g_start[d + 1];
    float a0 = 0.f, a1 = 0.f, a2 = 0.f;
    for (int e = beg + lane; e < end; e += 32) {
        int s = __ldg(&g_sorted[e]);
        float dv = __ldg(&g_dinv[s]);
        float4 yv = *(const float4*)(y + s * 4);
        a0 = fmaf(dv, yv.x, a0);
        a1 = fmaf(dv, yv.y, a1);
        a2 = fmaf(dv, yv.z, a2);
    }
#pragma unroll
    for (int off = 16; off > 0; off >>= 1) {
        a0 += __shfl_xor_sync(0xffffffffu, a0, off);
        a1 += __shfl_xor_sync(0xffffffffu, a1, off);
        a2 += __shfl_xor_sync(0xffffffffu, a2, off);
    }
    if (lane == 0) {
        float dd = g_dinv[d];
        float4 yd = *(const float4*)(y + d * 4);
        out[d * 3 + 0] = fmaf(dd, fmaf(dd, yd.x, a0), g_bconst[0] + cls_b[0]);
        out[d * 3 + 1] = fmaf(dd, fmaf(dd, yd.y, a1), g_bconst[1] + cls_b[1]);
        out[d * 3 + 2] = fmaf(dd, fmaf(dd, yd.z, a2), g_bconst[2] + cls_b[2]);
    }
}

// =============== HMMA GEMM core: 64-wide K chunks, 3-stage, static NCH =======
#define GST64 32768
#define G64W  16384
#define GEMM_SMEM3 98304

// Stage loader + compute, parameterized. NPASS: 2 = AhWh + AhWl, 1 = AhWh.
template<int NPASS>
__device__ __forceinline__ void g_load_st(
    uint32_t sb, int tid, int st,
    const __nv_bfloat16* A0, int KA, int mrow0, int ka0,
    const __nv_bfloat16* WTh, const __nv_bfloat16* WTl, int KW, int n0, int kw0)
{
    uint32_t base = sb + st * GST64;
#pragma unroll
    for (int j = 0; j < 4; j++) {
        int flat = tid + j * 256;
        int r = flat >> 3, c = flat & 7;
        const char* src = (const char*)A0 +
                          (((size_t)(mrow0 + r) * KA + ka0) << 1) + c * 16;
        cp16(base + swz128((uint32_t)(r * 128 + c * 16)), src);
    }
#pragma unroll
    for (int p = 0; p < NPASS; p++) {
#pragma unroll
        for (int j = 0; j < 2; j++) {
            int flat = tid + j * 256;
            int r = flat >> 3, c = flat & 7;
            const char* src = (const char*)(p ? WTl : WTh) +
                              (((size_t)(n0 + r) * KW + kw0) << 1) + c * 16;
            cp16(base + G64W + p * 8192 + swz128((uint32_t)(r * 128 + c * 16)), src);
        }
    }
    cp_commit();
}

template<int NPASS>
__device__ __forceinline__ void g_compute(
    uint32_t sb, int st, int rowa, int acb, int nrow, int bcb, float acc[8][4])
{
    uint32_t base = sb + st * GST64;
#pragma unroll
    for (int s = 0; s < 2; s++) {
        uint32_t ah[2][4];
#pragma unroll
        for (int kk2 = 0; kk2 < 2; kk2++)
            ldsm4(ah[kk2], base + swz128((uint32_t)(rowa * 128 + s * 64 +
                                                    kk2 * 32 + acb)));
#pragma unroll
        for (int nb = 0; nb < 8; nb++) {
            uint32_t bo = (uint32_t)((nb * 8 + nrow) * 128 + s * 64 + bcb);
            uint32_t bh[4];
            ldsm4(bh, base + G64W + swz128(bo));
            mma16816(acc[nb], ah[0][0], ah[0][1], ah[0][2], ah[0][3], bh[0], bh[1]);
            mma16816(acc[nb], ah[1][0], ah[1][1], ah[1][2], ah[1][3], bh[2], bh[3]);
            if (NPASS == 2) {
                uint32_t bl[4];
                ldsm4(bl, base + G64W + 8192 + swz128(bo));
                mma16816(acc[nb], ah[0][0], ah[0][1], ah[0][2], ah[0][3], bl[0], bl[1]);
                mma16816(acc[nb], ah[1][0], ah[1][1], ah[1][2], ah[1][3], bl[2], bl[3]);
            }
        }
    }
}

// single-source GEMM core, static chunk count (fully unrolled pipeline)
template<int NPASS, int NCH>
__device__ __forceinline__ void gemm_core_bf16(
    uint32_t sb, int tid, int m0, int n0,
    const __nv_bfloat16* A0,
    const __nv_bfloat16* WTh, const __nv_bfloat16* WTl,
    float acc[8][4])
{
    const int w = tid >> 5, lane = tid & 31;
    const int rowa = w * 16 + (lane & 7) + ((lane >> 3) & 1) * 8;
    const int acb  = ((lane >> 4) & 1) * 16;
    const int nrow = lane & 7;
    const int bcb  = ((lane >> 3) & 3) * 16;
    const int K = NCH * 64;

    g_load_st<NPASS>(sb, tid, 0, A0, K, m0, 0, WTh, WTl, K, n0, 0);
    if (NCH > 1)
        g_load_st<NPASS>(sb, tid, 1, A0, K, m0, 64, WTh, WTl, K, n0, 64);
    cp_wait1();
    __syncthreads();
#pragma unroll
    for (int kc = 0; kc < NCH; kc++) {
        const int st = kc % 3;
        if (kc + 2 < NCH)
            g_load_st<NPASS>(sb, tid, (kc + 2) % 3, A0, K, m0, (kc + 2) * 64,
                             WTh, WTl, K, n0, (kc + 2) * 64);
        g_compute<NPASS>(sb, st, rowa, acb, nrow, bcb, acc);
        if (kc + 1 < NCH) {
            if (kc + 2 < NCH) cp_wait1(); else cp_wait0();
            __syncthreads();
        }
    }
}

// fused text+image projection: ONE 20-chunk pipeline (text 12 + image 8),
// mid-loop relu epilogue at the seam. + edge-scatter plane (blockIdx.y == 4).
__global__ void __launch_bounds__(256, 2) gemm_fuse2(
    const __nv_bfloat16* __restrict__ tb16, const __nv_bfloat16* __restrict__ ib16,
    const __nv_bfloat16* __restrict__ Wth, const __nv_bfloat16* __restrict__ Wtl,
    const __nv_bfloat16* __restrict__ Wih, const __nv_bfloat16* __restrict__ Wil,
    const float* __restrict__ tb, const float* __restrict__ ib,
    __nv_bfloat16* __restrict__ ch,
    const int* __restrict__ esrc, const int* __restrict__ edst)
{
    if (blockIdx.y == 4) {
        int base = (blockIdx.x * 256 + threadIdx.x) * 16;
        int4 d4[4], s4[4];
#pragma unroll
        for (int i = 0; i < 4; i++) {
            d4[i] = *(const int4*)(edst + base + i * 4);
            s4[i] = *(const int4*)(esrc + base + i * 4);
        }
#pragma unroll
        for (int i = 0; i < 4; i++) {
            const int dd[4] = {d4[i].x, d4[i].y, d4[i].z, d4[i].w};
            const int ss[4] = {s4[i].x, s4[i].y, s4[i].z, s4[i].w};
#pragma unroll
            for (int j = 0; j < 4; j++) {
                int pos = atomicAdd(&g_cursor[dd[j]], 1);
                g_sorted[pos] = ss[j];
            }
        }
        return;
    }
    extern __shared__ char sm[];
    const uint32_t sb = smem_u32(sm);
    const int tid = threadIdx.x, w = tid >> 5, lane = tid & 31;
    const int m0 = blockIdx.x * 128, n0 = blockIdx.y * 64;
    const int rowa = w * 16 + (lane & 7) + ((lane >> 3) & 1) * 8;
    const int acb  = ((lane >> 4) & 1) * 16;
    const int nrow = lane & 7;
    const int bcb  = ((lane >> 3) & 3) * 16;
    const int NCHT = TD / 64;          // 12
    const int NCHA = (TD + ID) / 64;   // 20

    // unified chunk loader: text part for kc<12, image part after
    auto load_any = [&](int kc, int st) {
        if (kc < NCHT)
            g_load_st<2>(sb, tid, st, tb16, TD, m0, kc * 64,
                         Wth, Wtl, TD, n0, kc * 64);
        else
            g_load_st<2>(sb, tid, st, ib16, ID, m0, (kc - NCHT) * 64,
                         Wih, Wil, ID, n0, (kc - NCHT) * 64);
    };

    float acc[8][4] = {};
    float rf[8][4];

    load_any(0, 0);
    load_any(1, 1);
    cp_wait1();
    __syncthreads();
#pragma unroll
    for (int kc = 0; kc < NCHA; kc++) {
        const int st = kc % 3;
        if (kc + 2 < NCHA) load_any(kc + 2, (kc + 2) % 3);
        g_compute<2>(sb, st, rowa, acb, nrow, bcb, acc);
        if (kc == NCHT - 1) {
            // text half done: relu epilogue into rf, reset acc (loads keep going)
#pragma unroll
            for (int nb = 0; nb < 8; nb++) {
                const int cg = n0 + (lane & 3) * 2 + nb * 8;
                float b0 = tb[cg], b1 = tb[cg + 1];
                rf[nb][0] = fmaxf(acc[nb][0] + b0, 0.f);
                rf[nb][1] = fmaxf(acc[nb][1] + b1, 0.f);
                rf[nb][2] = fmaxf(acc[nb][2] + b0, 0.f);
                rf[nb][3] = fmaxf(acc[nb][3] + b1, 0.f);
                acc[nb][0] = acc[nb][1] = acc[nb][2] = acc[nb][3] = 0.f;
            }
        }
        if (kc + 1 < NCHA) {
            if (kc + 2 < NCHA) cp_wait1(); else cp_wait0();
            __syncthreads();
        }
    }

    const int r0 = m0 + w * 16 + (lane >> 2);
#pragma unroll
    for (int nb = 0; nb < 8; nb++) {
        const int cg = n0 + (lane & 3) * 2 + nb * 8;
        float b0 = ib[cg], b1 = ib[cg + 1];
        const size_t i0 = (size_t)r0 * HH + cg;
        const size_t i1 = (size_t)(r0 + 8) * HH + cg;
        ((uint32_t*)ch)[i0 >> 1] = packbf2(rf[nb][0] + fmaxf(acc[nb][0] + b0, 0.f),
                                           rf[nb][1] + fmaxf(acc[nb][1] + b1, 0.f));
        ((uint32_t*)ch)[i1 >> 1] = packbf2(rf[nb][2] + fmaxf(acc[nb][2] + b0, 0.f),
                                           rf[nb][3] + fmaxf(acc[nb][3] + b1, 0.f));
    }
}

// general K=256 GEMM (bf16-A hi, 2-pass): EPI 2 bias->bf16; EPI 7 y-red.
template<int EPI>
__global__ void __launch_bounds__(256, 2) gemm_tc(
    const __nv_bfloat16* __restrict__ A0,
    const __nv_bfloat16* __restrict__ WTh, const __nv_bfloat16* __restrict__ WTl,
    const float* __restrict__ bias,
    void* out0v)
{
    extern __shared__ char sm[];
    const uint32_t sb = smem_u32(sm);
    const int tid = threadIdx.x, w = tid >> 5, lane = tid & 31;
    const int m0 = blockIdx.x * 128, n0 = blockIdx.y * 64;
    float acc[8][4] = {};
    gemm_core_bf16<2, 4>(sb, tid, m0, n0, A0, WTh, WTl, acc);

    const int r0 = m0 + w * 16 + (lane >> 2);
    if (EPI == 7) {
        const float* cw = bias;
        float p0[3] = {0.f, 0.f, 0.f}, p1[3] = {0.f, 0.f, 0.f};
#pragma unroll
        for (int nb = 0; nb < 8; nb++) {
            const int cg = n0 + (lane & 3) * 2 + nb * 8;
#pragma unroll
            for (int c = 0; c < 3; c++) {
                float w0 = __ldg(cw + cg * 3 + c), w1 = __ldg(cw + (cg + 1) * 3 + c);
                p0[c] = fmaf(acc[nb][0], w0, fmaf(acc[nb][1], w1, p0[c]));
                p1[c] = fmaf(acc[nb][2], w0, fmaf(acc[nb][3], w1, p1[c]));
            }
        }
#pragma unroll
        for (int c = 0; c < 3; c++) {
            p0[c] += __shfl_xor_sync(0xffffffffu, p0[c], 1);
            p0[c] += __shfl_xor_sync(0xffffffffu, p0[c], 2);
            p1[c] += __shfl_xor_sync(0xffffffffu, p1[c], 1);
            p1[c] += __shfl_xor_sync(0xffffffffu, p1[c], 2);
        }
        if ((lane & 3) == 0) {
            float* y = (float*)out0v;
#pragma unroll
            for (int c = 0; c < 3; c++) {
                redf(y + r0 * 4 + c, p0[c]);
                redf(y + (r0 + 8) * 4 + c, p1[c]);
            }
        }
        return;
    }
#pragma unroll
    for (int nb = 0; nb < 8; nb++) {
        const int cg = n0 + (lane & 3) * 2 + nb * 8;
        float b0 = bias[cg], b1 = bias[cg + 1];
        const size_t i0 = (size_t)r0 * HH + cg;
        const size_t i1 = (size_t)(r0 + 8) * HH + cg;
        ((uint32_t*)out0v)[i0 >> 1] = packbf2(acc[nb][0] + b0, acc[nb][1] + b1);
        ((uint32_t*)out0v)[i1 >> 1] = packbf2(acc[nb][2] + b0, acc[nb][3] + b1);
    }
}

// fused QKV GEMM: grid (32, 12). V first, then K, Q.
__global__ void __launch_bounds__(256, 2) gemm_qkv(
    const __nv_bfloat16* __restrict__ A0,
    const __nv_bfloat16* __restrict__ WTbase, const __nv_bfloat16* __restrict__ WLbase,
    const float* __restrict__ bq, const float* __restrict__ bk,
    const float* __restrict__ bv,
    __nv_bfloat16* __restrict__ oq, __nv_bfloat16* __restrict__ ok,
    __nv_bfloat16* __restrict__ ov, float* __restrict__ vsum)
{
    extern __shared__ char sm[];
    const uint32_t sb = smem_u32(sm);
    const int tid = threadIdx.x, w = tid >> 5, lane = tid & 31;
    const int sel = 2 - (blockIdx.y >> 2);       // y 0-3: V, 4-7: K, 8-11: Q
    const int m0 = blockIdx.x * 128, n0 = (blockIdx.y & 3) * 64;
    const __nv_bfloat16* WTh = WTbase + (size_t)sel * HH * HH;
    const __nv_bfloat16* WTl = WLbase + (size_t)sel * HH * HH;
    const float* bias = sel == 0 ? bq : (sel == 1 ? bk : bv);
    __nv_bfloat16* out = sel == 0 ? oq : (sel == 1 ? ok : ov);

    float acc[8][4] = {};
    if (sel == 2) gemm_core_bf16<2, 4>(sb, tid, m0, n0, A0, WTh, WTl, acc);
    else          gemm_core_bf16<1, 4>(sb, tid, m0, n0, A0, WTh, WTl, acc);

    const int r0 = m0 + w * 16 + (lane >> 2);
#pragma unroll
    for (int nb = 0; nb < 8; nb++) {
        const int cg = n0 + (lane & 3) * 2 + nb * 8;
        float b0 = bias[cg], b1 = bias[cg + 1];
        float v00 = acc[nb][0] + b0, v01 = acc[nb][1] + b1;
        float v10 = acc[nb][2] + b0, v11 = acc[nb][3] + b1;
        const size_t i0 = (size_t)r0 * HH + cg;
        const size_t i1 = (size_t)(r0 + 8) * HH + cg;
        ((uint32_t*)out)[i0 >> 1] = packbf2(v00, v01);
        ((uint32_t*)out)[i1 >> 1] = packbf2(v10, v11);
        if (sel == 2) {
            float s0 = v00 + v10, s1 = v01 + v11;
#pragma unroll
            for (int off = 4; off < 32; off <<= 1) {
                s0 += __shfl_xor_sync(0xffffffffu, s0, off);
                s1 += __shfl_xor_sync(0xffffffffu, s1, off);
            }
            if (lane < 4) {
                redf(vsum + cg, s0);
                redf(vsum + cg + 1, s1);
            }
        }
    }
}

// ============== HMMA flash attention: 128 q-rows x 1 head per CTA ============
#define SM_BUFSTRIDE 32768
#define SM_VOFF 16384
#define SM_Q 98304
#define SM_ATT_TOTAL 114688

__device__ __forceinline__ void load_kv_tile(
    uint32_t sb, int buf, int kt, int head,
    const __nv_bfloat16* kb, const __nv_bfloat16* vb, int tid)
{
    const char* kc = (const char*)kb;
    const char* vc = (const char*)vb;
#pragma unroll
    for (int j = 0; j < 8; j++) {
        int flat = tid + j * 256;
        int arr = flat >> 10;
        int row = (flat >> 3) & 127;
        int c = flat & 7;
        const char* src = (arr ? vc : kc) +
            (((size_t)(kt + row) * HH + head * HD) << 1) + c * 16;
        uint32_t dst = sb + buf * SM_BUFSTRIDE + arr * SM_VOFF +
                       swz128((uint32_t)(row * 128 + c * 16));
        cp16(dst, src);
    }
}

__global__ void __launch_bounds__(256, 1) attn_mma(
    const __nv_bfloat16* __restrict__ qb, const __nv_bfloat16* __restrict__ kb,
    const __nv_bfloat16* __restrict__ vb, const float* __restrict__ vsum,
    __nv_bfloat16* __restrict__ oh)
{
    extern __shared__ char sm[];
    const uint32_t sb = smem_u32(sm);
    const int tid = threadIdx.x, w = tid >> 5, lane = tid & 31;
    const int q0 = blockIdx.x * 128, head = blockIdx.y;

    {
        const char* qc = (const char*)qb;
#pragma unroll
        for (int j = 0; j < 4; j++) {
            int flat = tid + j * 256;
            int row = flat >> 3, c = flat & 7;
            const char* src = qc + (((size_t)(q0 + row) * HH + head * HD) << 1) + c * 16;
            cp16(sb + SM_Q + swz128((uint32_t)(row * 128 + c * 16)), src);
        }
        load_kv_tile(sb, 0, 0, head, kb, vb, tid);
        cp_commit();
        load_kv_tile(sb, 1, 128, head, kb, vb, tid);
        cp_commit();
        cp_wait1();
        __syncthreads();
    }

    uint32_t qa[4][4];
    {
        const int rowa = w * 16 + (lane & 7) + ((lane >> 3) & 1) * 8;
        const int cb = ((lane >> 4) & 1) * 16;
#pragma unroll
        for (int kk = 0; kk < 4; kk++)
            ldsm4(qa[kk], sb + SM_Q + swz128((uint32_t)(rowa * 128 + kk * 32 + cb)));
    }

    float oacc[8][4] = {};
    float sumd0 = 0.f, sumd1 = 0.f;

    int buf = 0;
    for (int t = 0; t < 32; t++) {
        const uint32_t kbase = sb + buf * SM_BUFSTRIDE;
        const uint32_t vbase = kbase + SM_VOFF;
        if (t + 2 < 32) {
            int b2 = buf + 2; if (b2 >= 3) b2 -= 3;
            load_kv_tile(sb, b2, (t + 2) * 128, head, kb, vb, tid);
            cp_commit();
        }
#pragma unroll 2
        for (int kk = 0; kk < 8; kk++) {
            float s2a[2][4] = {{0.f,0.f,0.f,0.f},{0.f,0.f,0.f,0.f}};
            float s2b[2][4] = {{0.f,0.f,0.f,0.f},{0.f,0.f,0.f,0.f}};
#pragma unroll
            for (int half = 0; half < 2; half++) {
                const int keyl = kk * 16 + half * 8 + (lane & 7);
                uint32_t b0[4], b1[4];
                ldsm4(b0, kbase + swz128((uint32_t)(keyl * 128 +
                                                    ((lane >> 3) & 3) * 16)));
                ldsm4(b1, kbase + swz128((uint32_t)(keyl * 128 + 64 +
                                                    ((lane >> 3) & 3) * 16)));
                mma16816(s2a[half], qa[0][0], qa[0][1], qa[0][2], qa[0][3], b0[0], b0[1]);
                mma16816(s2b[half], qa[2][0], qa[2][1], qa[2][2], qa[2][3], b1[0], b1[1]);
                mma16816(s2a[half], qa[1][0], qa[1][1], qa[1][2], qa[1][3], b0[2], b0[3]);
                mma16816(s2b[half], qa[3][0], qa[3][1], qa[3][2], qa[3][3], b1[2], b1[3]);
            }
            float s[2][4];
#pragma unroll
            for (int half = 0; half < 2; half++) {
#pragma unroll
                for (int j = 0; j < 4; j++) {
                    float x = (s2a[half][j] + s2b[half][j]) * 0.125f;
                    float h = fmaf(x, 4.166666667e-2f, 0.166666667f);
                    h = fmaf(h, x, 0.5f);
                    h = fmaf(h, x, 1.0f);
                    float dlt = x * h;
                    s[half][j] = dlt;
                    if (j < 2) sumd0 += dlt; else sumd1 += dlt;
                }
            }
            uint32_t A0 = packbf2(s[0][0], s[0][1]);
            uint32_t A1 = packbf2(s[0][2], s[0][3]);
            uint32_t A2 = packbf2(s[1][0], s[1][1]);
            uint32_t A3 = packbf2(s[1][2], s[1][3]);
            const int keyl2 = kk * 16 + (lane & 7) + ((lane >> 3) & 1) * 8;
            const int cb2 = ((lane >> 4) & 1) * 16;
#pragma unroll
            for (int nb2 = 0; nb2 < 4; nb2++) {
                uint32_t b[4];
                ldsm4t(b, vbase + swz128((uint32_t)(keyl2 * 128 + nb2 * 32 + cb2)));
                mma16816(oacc[2*nb2],     A0, A1, A2, A3, b[0], b[1]);
                mma16816(oacc[2*nb2 + 1], A0, A1, A2, A3, b[2], b[3]);
            }
        }
        if (t + 1 < 32) {
            if (t + 2 < 32) cp_wait1(); else cp_wait0();
            __syncthreads();
        }
        if (++buf == 3) buf = 0;
    }

    sumd0 += __shfl_xor_sync(0xffffffffu, sumd0, 1);
    sumd0 += __shfl_xor_sync(0xffffffffu, sumd0, 2);
    sumd1 += __shfl_xor_sync(0xffffffffu, sumd1, 1);
    sumd1 += __shfl_xor_sync(0xffffffffu, sumd1, 2);
    const float inv0 = 1.0f / (4096.0f + sumd0);
    const float inv1 = 1.0f / (4096.0f + sumd1);
    const int r0 = q0 + w * 16 + (lane >> 2);
    const int cbase = head * HD + (lane & 3) * 2;
#pragma unroll
    for (int nb = 0; nb < 8; nb++) {
        int d = cbase + nb * 8;
        float sv0 = vsum[d], sv1 = vsum[d + 1];
        ((uint32_t*)oh)[((size_t)r0 * HH + d) >> 1] =
            packbf2((sv0 + oacc[nb][0]) * inv0, (sv1 + oacc[nb][1]) * inv0);
        ((uint32_t*)oh)[((size_t)(r0 + 8) * HH + d) >> 1] =
            packbf2((sv0 + oacc[nb][2]) * inv1, (sv1 + oacc[nb][3]) * inv1);
    }
}

// ---------------- launch -----------------------------------------------------
extern "C" void kernel_launch(void* const* d_in, const int* in_sizes, int n_in,
                              void* d_out, int out_size)
{
    const float* text    = (const float*)d_in[0];
    const float* image   = (const float*)d_in[1];
    const int*   ei      = (const int*)d_in[2];
    const float* text_w  = (const float*)d_in[3];
    const float* text_b  = (const float*)d_in[4];
    const float* image_w = (const float*)d_in[5];
    const float* image_b = (const float*)d_in[6];
    const float* wq = (const float*)d_in[7];  const float* bq = (const float*)d_in[8];
    const float* wk = (const float*)d_in[9];  const float* bk = (const float*)d_in[10];
    const float* wv = (const float*)d_in[11]; const float* bv = (const float*)d_in[12];
    const float* wo = (const float*)d_in[13]; const float* bo = (const float*)d_in[14];
    const float* gcn1_w = (const float*)d_in[15]; const float* gcn1_b = (const float*)d_in[16];
    const float* gcn2_w = (const float*)d_in[17]; const float* gcn2_b = (const float*)d_in[18];
    const float* cls_w  = (const float*)d_in[19]; const float* cls_b  = (const float*)d_in[20];
    float* out = (float*)d_out;

    float *yb, *dinv, *vsum, *bg;
    __nv_bfloat16 *tb16, *ib16, *ch, *qbb, *kbb, *vbb, *obh, *g1h, *wth, *wtl;
    cudaGetSymbolAddress((void**)&yb, g_y);
    cudaGetSymbolAddress((void**)&dinv, g_dinv);
    cudaGetSymbolAddress((void**)&vsum, g_vsum);
    cudaGetSymbolAddress((void**)&bg, g_bg);
    cudaGetSymbolAddress((void**)&tb16, g_tb16);
    cudaGetSymbolAddress((void**)&ib16, g_ib16);
    cudaGetSymbolAddress((void**)&ch, g_ch);
    cudaGetSymbolAddress((void**)&qbb, g_qb);
    cudaGetSymbolAddress((void**)&kbb, g_kb);
    cudaGetSymbolAddress((void**)&vbb, g_vb);
    cudaGetSymbolAddress((void**)&obh, g_obh);
    cudaGetSymbolAddress((void**)&g1h, g_g1h);
    cudaGetSymbolAddress((void**)&wth, g_wth);
    cudaGetSymbolAddress((void**)&wtl, g_wtl);

    // 1: weight prep + hist + WG compose + bG + zero + bf16 input conversion
    k_wprep_all<<<dim3(24, 8, 9), dim3(32, 32)>>>(
        text_w, image_w, wq, wk, wv, wo, gcn1_w, gcn2_w, bo, ei + EE,
        text, image);

    // 2: scan
    k_scan<<<1, 1024>>>(gcn2_b, cls_w);

    // 3: fused text+image projection (single 20-chunk pipeline) + scatter
    {
        static bool done = false;
        if (!done) {
            cudaFuncSetAttribute(gemm_fuse2,
                                 cudaFuncAttributeMaxDynamicSharedMemorySize, GEMM_SMEM3);
            done = true;
        }
        gemm_fuse2<<<dim3(32, 5), 256, GEMM_SMEM3>>>(
            tb16, ib16, wth + WOFF_TEXT, wtl + WOFF_TEXT,
            wth + WOFF_IMAGE, wtl + WOFF_IMAGE, text_b, image_b, ch,
            ei, ei + EE);
    }

    // 4: fused QKV
    {
        static bool done = false;
        if (!done) {
            cudaFuncSetAttribute(gemm_qkv,
                                 cudaFuncAttributeMaxDynamicSharedMemorySize, GEMM_SMEM3);
            done = true;
        }
        gemm_qkv<<<dim3(32, 12), 256, GEMM_SMEM3>>>(
            ch, wth + WOFF_WQ, wtl + WOFF_WQ, bq, bk, bv, qbb, kbb, vbb, vsum);
    }

    // 5: attention
    cudaFuncSetAttribute(attn_mma, cudaFuncAttributeMaxDynamicSharedMemorySize,
                         SM_ATT_TOTAL);
    attn_mma<<<dim3(NN / 128, NHD), 256, SM_ATT_TOTAL>>>(qbb, kbb, vbb, vsum, obh);

    // 6: GCN1 GEMM (composed weights): h_bf16 = ob@WG + bG -> reuse K buffer
    {
        static bool done = false;
        if (!done) {
            cudaFuncSetAttribute(gemm_tc<2>,
                                 cudaFuncAttributeMaxDynamicSharedMemorySize, GEMM_SMEM3);
            done = true;
        }
        gemm_tc<2><<<dim3(32, 4), 256, GEMM_SMEM3>>>(
            obh, wth + WOFF_G1, wtl + WOFF_G1, bg, kbb);
    }

    // 7: GCN1 aggregation
    k_agg1<<<NN * 32 / 256, 256>>>(kbb, gcn1_b, g1h);

    // 8: GCN2 GEMM in classifier space
    {
        static bool done = false;
        if (!done) {
            cudaFuncSetAttribute(gemm_tc<7>,
                                 cudaFuncAttributeMaxDynamicSharedMemorySize, GEMM_SMEM3);
            done = true;
        }
        gemm_tc<7><<<dim3(32, 4), 256, GEMM_SMEM3>>>(
            g1h, wth + WOFF_G2, wtl + WOFF_G2, cls_w, yb);
    }

    // 9: GCN2 aggregation
    k_agg2y<<<NN * 32 / 256, 256>>>(yb, cls_b, out);
}